// round 6
// baseline (speedup 1.0000x reference)
#include <cuda_runtime.h>
#include <cuda_bf16.h>
#include <cstdint>
#include <math.h>

// ---------------------------------------------------------------------------
// Problem constants
// ---------------------------------------------------------------------------
#define BB 4
#define SS 1024
#define DD 1024
#define HH 16
#define HDIM 64
#define FF 2048
#define HID 4096
#define TOK (BB*SS)          // 4096 tokens
#define QKVN 3072

// ---------------------------------------------------------------------------
// Scratch (__device__ globals; no allocation allowed)
// ---------------------------------------------------------------------------
__device__ float g_qkv [TOK*QKVN];
__device__ float g_att [TOK*DD];
__device__ float g_o   [TOK*DD];
__device__ float g_h   [TOK*DD];
__device__ float g_feat[TOK*DD];
__device__ float g_feat2[TOK*DD];
__device__ float g_ff  [TOK*FF];
__device__ float g_s   [TOK];
__device__ float g_sv  [TOK];
__device__ int   g_seg [TOK];
__device__ float g_maxseg[BB];
__device__ float g_bqkv[QKVN];

// tf32-path transposed weights [N,K] (K contiguous)
__device__ float g_wt_qkv[QKVN*DD];   // [Wq^T ; Wk^T ; Wv^T]
__device__ float g_wt_o [DD*DD];
__device__ float g_wt_1 [FF*DD];
__device__ float g_wt_2 [DD*FF];

// bf16-split projector operands
__device__ __nv_bfloat16 g_p1h[HID*DD],  g_p1l[HID*DD];    // P1^T split
__device__ __nv_bfloat16 g_p2h[HID*HID], g_p2l[HID*HID];   // P2^T split
__device__ __nv_bfloat16 g_poolh[TOK*DD],  g_pooll[TOK*DD];
__device__ __nv_bfloat16 g_phh[TOK*HID],   g_phl[TOK*HID];

// ---------------------------------------------------------------------------
// Helpers
// ---------------------------------------------------------------------------
__device__ __forceinline__ float gelu_f(float x) {
    return 0.5f * x * (1.0f + erff(x * 0.70710678118654752440f));
}

__device__ __forceinline__ void cp16(uint32_t dst, const void* src) {
    asm volatile("cp.async.cg.shared.global [%0], [%1], 16;\n"
                 :: "r"(dst), "l"(src));
}

__device__ __forceinline__ uint32_t smem_u32(const void* p) {
    uint32_t a;
    asm("{ .reg .u64 t; cvta.to.shared.u64 t, %1; cvt.u32.u64 %0, t; }"
        : "=r"(a) : "l"(p));
    return a;
}

// mma.sync m16n8k8 tf32: D += A*B
__device__ __forceinline__ void mma_tf32(float* c,
                                         uint32_t a0, uint32_t a1,
                                         uint32_t a2, uint32_t a3,
                                         uint32_t b0, uint32_t b1) {
    asm volatile(
        "mma.sync.aligned.m16n8k8.row.col.f32.tf32.tf32.f32 "
        "{%0,%1,%2,%3}, {%4,%5,%6,%7}, {%8,%9}, {%0,%1,%2,%3};\n"
        : "+f"(c[0]), "+f"(c[1]), "+f"(c[2]), "+f"(c[3])
        : "r"(a0), "r"(a1), "r"(a2), "r"(a3), "r"(b0), "r"(b1));
}

// mma.sync m16n8k16 bf16: D += A*B
__device__ __forceinline__ void mma_bf16(float* c,
                                         uint32_t a0, uint32_t a1,
                                         uint32_t a2, uint32_t a3,
                                         uint32_t b0, uint32_t b1) {
    asm volatile(
        "mma.sync.aligned.m16n8k16.row.col.f32.bf16.bf16.f32 "
        "{%0,%1,%2,%3}, {%4,%5,%6,%7}, {%8,%9}, {%0,%1,%2,%3};\n"
        : "+f"(c[0]), "+f"(c[1]), "+f"(c[2]), "+f"(c[3])
        : "r"(a0), "r"(a1), "r"(a2), "r"(a3), "r"(b0), "r"(b1));
}

__device__ __forceinline__ void split1(float v, uint32_t& h, uint32_t& l) {
    uint32_t hb = __float_as_uint(v) & 0xFFFFE000u;
    h = hb;
    l = __float_as_uint(v - __uint_as_float(hb));
}

__device__ __forceinline__ void bsplit(float v, __nv_bfloat16& h, __nv_bfloat16& l) {
    h = __float2bfloat16(v);
    l = __float2bfloat16(v - __bfloat162float(h));
}

// ---------------------------------------------------------------------------
// tf32 tensor-core GEMM with exact 2-way split (fp32-equivalent accuracy)
// C[M,N] = act(A[M,K] @ Bt[N,K]^T + bias[N])
// ---------------------------------------------------------------------------
#define PAD 20

__global__ __launch_bounds__(256)
void mma_gemm_kernel(const float* __restrict__ A, const float* __restrict__ Bt,
                     const float* __restrict__ bias, float* __restrict__ C,
                     int M, int N, int K, int act)
{
    __shared__ float As[2][128 * PAD];
    __shared__ float Bs[2][128 * PAD];

    const int tid  = threadIdx.x;
    const int wid  = tid >> 5;
    const int lane = tid & 31;
    const int gr   = lane >> 2;
    const int gc   = lane & 3;
    const int row0 = blockIdx.y * 128;
    const int col0 = blockIdx.x * 128;
    const int warp_m = (wid & 3) * 32;
    const int warp_n = (wid >> 2) * 64;

    const uint32_t sA = smem_u32(&As[0][0]);
    const uint32_t sB = smem_u32(&Bs[0][0]);

    float acc[2][8][4];
#pragma unroll
    for (int i = 0; i < 2; i++)
#pragma unroll
        for (int j = 0; j < 8; j++)
#pragma unroll
            for (int r = 0; r < 4; r++) acc[i][j][r] = 0.0f;

    const int nk = K >> 4;
    const int m_a  = tid >> 2;
    const int kc_a = (tid & 3) << 2;

    {
#pragma unroll
        for (int j = 0; j < 2; j++) {
            int m = m_a + j * 64;
            cp16(sA + (uint32_t)(m * PAD + kc_a) * 4u,
                 A + (size_t)(row0 + m) * K + kc_a);
            cp16(sB + (uint32_t)(m * PAD + kc_a) * 4u,
                 Bt + (size_t)(col0 + m) * K + kc_a);
        }
        asm volatile("cp.async.commit_group;\n");
    }

    for (int t = 0; t < nk; t++) {
        const int st = t & 1;
        if (t + 1 < nk) {
            const int st2 = (t + 1) & 1;
            const int k0 = (t + 1) << 4;
#pragma unroll
            for (int j = 0; j < 2; j++) {
                int m = m_a + j * 64;
                cp16(sA + (uint32_t)(st2 * 128 * PAD + m * PAD + kc_a) * 4u,
                     A + (size_t)(row0 + m) * K + k0 + kc_a);
                cp16(sB + (uint32_t)(st2 * 128 * PAD + m * PAD + kc_a) * 4u,
                     Bt + (size_t)(col0 + m) * K + k0 + kc_a);
            }
            asm volatile("cp.async.commit_group;\n");
            asm volatile("cp.async.wait_group 1;\n");
        } else {
            asm volatile("cp.async.wait_group 0;\n");
        }
        __syncthreads();

        const float* as = &As[st][0];
        const float* bs = &Bs[st][0];

#pragma unroll
        for (int k8 = 0; k8 < 16; k8 += 8) {
            uint32_t ah[2][4], al[2][4];
#pragma unroll
            for (int mt = 0; mt < 2; mt++) {
                int base = (warp_m + mt * 16 + gr) * PAD + k8 + gc;
                split1(as[base],               ah[mt][0], al[mt][0]);
                split1(as[base + 8 * PAD],     ah[mt][1], al[mt][1]);
                split1(as[base + 4],           ah[mt][2], al[mt][2]);
                split1(as[base + 8 * PAD + 4], ah[mt][3], al[mt][3]);
            }
            uint32_t bh[8][2], bl[8][2];
#pragma unroll
            for (int nt = 0; nt < 8; nt++) {
                int base = (warp_n + nt * 8 + gr) * PAD + k8 + gc;
                split1(bs[base],     bh[nt][0], bl[nt][0]);
                split1(bs[base + 4], bh[nt][1], bl[nt][1]);
            }
#pragma unroll
            for (int mt = 0; mt < 2; mt++)
#pragma unroll
                for (int nt = 0; nt < 8; nt++) {
                    float* c = acc[mt][nt];
                    mma_tf32(c, ah[mt][0], ah[mt][1], ah[mt][2], ah[mt][3],
                             bh[nt][0], bh[nt][1]);
                    mma_tf32(c, ah[mt][0], ah[mt][1], ah[mt][2], ah[mt][3],
                             bl[nt][0], bl[nt][1]);
                    mma_tf32(c, al[mt][0], al[mt][1], al[mt][2], al[mt][3],
                             bh[nt][0], bh[nt][1]);
                }
        }
        __syncthreads();
    }

#pragma unroll
    for (int mt = 0; mt < 2; mt++) {
        const int r0 = row0 + warp_m + mt * 16 + gr;
#pragma unroll
        for (int nt = 0; nt < 8; nt++) {
            const int cc = col0 + warp_n + nt * 8 + 2 * gc;
            float b0v = bias[cc], b1v = bias[cc + 1];
            float v0 = acc[mt][nt][0] + b0v;
            float v1 = acc[mt][nt][1] + b1v;
            float v2 = acc[mt][nt][2] + b0v;
            float v3 = acc[mt][nt][3] + b1v;
            if (act == 1) {
                v0 = gelu_f(v0); v1 = gelu_f(v1);
                v2 = gelu_f(v2); v3 = gelu_f(v3);
            }
            *(float2*)(C + (size_t)r0 * N + cc)       = make_float2(v0, v1);
            *(float2*)(C + (size_t)(r0 + 8) * N + cc) = make_float2(v2, v3);
        }
    }
}

// ---------------------------------------------------------------------------
// bf16 split GEMM (projector): 3 combos on m16n8k16.
// ---------------------------------------------------------------------------
#define HS 40
#define BF_STAGE_HALVES 20480
#define BF_SMEM_BYTES  (2 * BF_STAGE_HALVES * 2)

__global__ __launch_bounds__(256)
void bf16_gemm_kernel(const __nv_bfloat16* __restrict__ Ah,
                      const __nv_bfloat16* __restrict__ Al,
                      const __nv_bfloat16* __restrict__ Bh,
                      const __nv_bfloat16* __restrict__ Bl,
                      const float* __restrict__ bias, float* __restrict__ C,
                      __nv_bfloat16* __restrict__ Ch, __nv_bfloat16* __restrict__ Cl,
                      int M, int N, int K, int act, int out_split)
{
    extern __shared__ __nv_bfloat16 hsm[];
    const int tid  = threadIdx.x;
    const int wid  = tid >> 5;
    const int lane = tid & 31;
    const int gr   = lane >> 2;
    const int gc   = lane & 3;
    const int row0 = blockIdx.y * 128;
    const int col0 = blockIdx.x * 128;
    const int warp_m = (wid & 3) * 32;
    const int warp_n = (wid >> 2) * 64;
    const uint32_t sbase = smem_u32(hsm);

    float acc[2][8][4];
#pragma unroll
    for (int i = 0; i < 2; i++)
#pragma unroll
        for (int j = 0; j < 8; j++)
#pragma unroll
            for (int r = 0; r < 4; r++) acc[i][j][r] = 0.0f;

    const int nk = K >> 5;
    const int c0i = tid * 2, c1i = tid * 2 + 1;
    const int m0 = c0i >> 2, kc0 = (c0i & 3) * 8;
    const int m1 = c1i >> 2, kc1 = (c1i & 3) * 8;

#define BF_LOAD_STAGE(st, k0)                                                    \
    do {                                                                         \
        uint32_t b = sbase + (uint32_t)(st) * BF_STAGE_HALVES * 2u;              \
        cp16(b + (uint32_t)(m0 * HS + kc0) * 2u,                                 \
             Ah + (size_t)(row0 + m0) * K + (k0) + kc0);                         \
        cp16(b + (uint32_t)(m1 * HS + kc1) * 2u,                                 \
             Ah + (size_t)(row0 + m1) * K + (k0) + kc1);                         \
        cp16(b + (uint32_t)(5120 + m0 * HS + kc0) * 2u,                          \
             Al + (size_t)(row0 + m0) * K + (k0) + kc0);                         \
        cp16(b + (uint32_t)(5120 + m1 * HS + kc1) * 2u,                          \
             Al + (size_t)(row0 + m1) * K + (k0) + kc1);                         \
        cp16(b + (uint32_t)(10240 + m0 * HS + kc0) * 2u,                         \
             Bh + (size_t)(col0 + m0) * K + (k0) + kc0);                         \
        cp16(b + (uint32_t)(10240 + m1 * HS + kc1) * 2u,                         \
             Bh + (size_t)(col0 + m1) * K + (k0) + kc1);                         \
        cp16(b + (uint32_t)(15360 + m0 * HS + kc0) * 2u,                         \
             Bl + (size_t)(col0 + m0) * K + (k0) + kc0);                         \
        cp16(b + (uint32_t)(15360 + m1 * HS + kc1) * 2u,                         \
             Bl + (size_t)(col0 + m1) * K + (k0) + kc1);                         \
        asm volatile("cp.async.commit_group;\n");                                \
    } while (0)

    BF_LOAD_STAGE(0, 0);

    for (int t = 0; t < nk; t++) {
        const int st = t & 1;
        if (t + 1 < nk) {
            BF_LOAD_STAGE((t + 1) & 1, (t + 1) << 5);
            asm volatile("cp.async.wait_group 1;\n");
        } else {
            asm volatile("cp.async.wait_group 0;\n");
        }
        __syncthreads();

        const __nv_bfloat16* s = hsm + st * BF_STAGE_HALVES;

#pragma unroll
        for (int ks = 0; ks < 2; ks++) {
            const int kh = ks * 16;
            uint32_t ahf[2][4], alf[2][4];
#pragma unroll
            for (int mt = 0; mt < 2; mt++) {
                int r = warp_m + mt * 16 + gr;
                ahf[mt][0] = *(const uint32_t*)(s + r * HS + kh + 2 * gc);
                ahf[mt][1] = *(const uint32_t*)(s + (r + 8) * HS + kh + 2 * gc);
                ahf[mt][2] = *(const uint32_t*)(s + r * HS + kh + 8 + 2 * gc);
                ahf[mt][3] = *(const uint32_t*)(s + (r + 8) * HS + kh + 8 + 2 * gc);
                alf[mt][0] = *(const uint32_t*)(s + 5120 + r * HS + kh + 2 * gc);
                alf[mt][1] = *(const uint32_t*)(s + 5120 + (r + 8) * HS + kh + 2 * gc);
                alf[mt][2] = *(const uint32_t*)(s + 5120 + r * HS + kh + 8 + 2 * gc);
                alf[mt][3] = *(const uint32_t*)(s + 5120 + (r + 8) * HS + kh + 8 + 2 * gc);
            }
#pragma unroll
            for (int nt = 0; nt < 8; nt++) {
                int r = warp_n + nt * 8 + gr;
                uint32_t bh0 = *(const uint32_t*)(s + 10240 + r * HS + kh + 2 * gc);
                uint32_t bh1 = *(const uint32_t*)(s + 10240 + r * HS + kh + 8 + 2 * gc);
                uint32_t bl0 = *(const uint32_t*)(s + 15360 + r * HS + kh + 2 * gc);
                uint32_t bl1 = *(const uint32_t*)(s + 15360 + r * HS + kh + 8 + 2 * gc);
#pragma unroll
                for (int mt = 0; mt < 2; mt++) {
                    float* c = acc[mt][nt];
                    mma_bf16(c, ahf[mt][0], ahf[mt][1], ahf[mt][2], ahf[mt][3], bh0, bh1);
                    mma_bf16(c, ahf[mt][0], ahf[mt][1], ahf[mt][2], ahf[mt][3], bl0, bl1);
                    mma_bf16(c, alf[mt][0], alf[mt][1], alf[mt][2], alf[mt][3], bh0, bh1);
                }
            }
        }
        __syncthreads();
    }

#pragma unroll
    for (int mt = 0; mt < 2; mt++) {
        const int r0 = row0 + warp_m + mt * 16 + gr;
#pragma unroll
        for (int nt = 0; nt < 8; nt++) {
            const int cc = col0 + warp_n + nt * 8 + 2 * gc;
            float b0v = bias[cc], b1v = bias[cc + 1];
            float v0 = acc[mt][nt][0] + b0v;
            float v1 = acc[mt][nt][1] + b1v;
            float v2 = acc[mt][nt][2] + b0v;
            float v3 = acc[mt][nt][3] + b1v;
            if (act == 1) {
                v0 = gelu_f(v0); v1 = gelu_f(v1);
                v2 = gelu_f(v2); v3 = gelu_f(v3);
            }
            if (!out_split) {
                *(float2*)(C + (size_t)r0 * N + cc)       = make_float2(v0, v1);
                *(float2*)(C + (size_t)(r0 + 8) * N + cc) = make_float2(v2, v3);
            } else {
                __nv_bfloat16 h0, l0, h1, l1;
                bsplit(v0, h0, l0); bsplit(v1, h1, l1);
                *(__nv_bfloat162*)(Ch + (size_t)r0 * N + cc) =
                    __nv_bfloat162(h0, h1);
                *(__nv_bfloat162*)(Cl + (size_t)r0 * N + cc) =
                    __nv_bfloat162(l0, l1);
                bsplit(v2, h0, l0); bsplit(v3, h1, l1);
                *(__nv_bfloat162*)(Ch + (size_t)(r0 + 8) * N + cc) =
                    __nv_bfloat162(h0, h1);
                *(__nv_bfloat162*)(Cl + (size_t)(r0 + 8) * N + cc) =
                    __nv_bfloat162(l0, l1);
            }
        }
    }
}

// ---------------------------------------------------------------------------
// Tensor-core flash attention, Q-tile 128, 256 threads (8 warps x 16 queries).
// tf32 2-way split, 3 combos on both GEMMs. K-tile 64.
// ---------------------------------------------------------------------------
#define AST 72
// Qs 128 rows, Ks 64, Vs 64, Ps 128 rows + mask 64 floats
#define ATT_SMEM_BYTES ((128 + 64 + 64 + 128) * AST * 4 + 64 * 4)

__global__ __launch_bounds__(256)
void attn_mma_kernel(const float* __restrict__ qkv, const float* __restrict__ masks,
                     int mode, float* __restrict__ o)
{
    extern __shared__ float smem[];
    float* Qs = smem;                   // [128][AST]
    float* Ks = Qs + 128 * AST;         // [64][AST]
    float* Vs = Ks + 64 * AST;          // [64][AST]
    float* Ps = Vs + 64 * AST;          // [128][AST]
    float* mb = Ps + 128 * AST;         // [64]

    const int tid  = threadIdx.x;
    const int wid  = tid >> 5;
    const int lane = tid & 31;
    const int gr   = lane >> 2;
    const int gc   = lane & 3;
    const int q0   = blockIdx.x * 128;
    const int b    = blockIdx.y >> 4;
    const int h    = blockIdx.y & 15;
    const size_t qbase = (size_t)b * SS * QKVN + (size_t)h * HDIM;
    const size_t obase = (size_t)b * SS * DD + (size_t)h * HDIM;
    const int q0w = wid * 16;

    // load Q tile (pre-scaled by 1/sqrt(HD) = 0.125): 128 rows x 64 cols
    for (int idx = tid; idx < 128 * 16; idx += 256) {
        int r = idx >> 4, c4 = (idx & 15) << 2;
        float4 v = *(const float4*)(qkv + qbase + (size_t)(q0 + r) * QKVN + c4);
        v.x *= 0.125f; v.y *= 0.125f; v.z *= 0.125f; v.w *= 0.125f;
        *(float4*)(Qs + r * AST + c4) = v;
    }

    float mrow[2] = {-1e30f, -1e30f};
    float lrow[2] = {0.0f, 0.0f};
    float Oacc[8][4];
#pragma unroll
    for (int i = 0; i < 8; i++)
#pragma unroll
        for (int j = 0; j < 4; j++) Oacc[i][j] = 0.0f;
    __syncthreads();

    for (int t = 0; t < 16; t++) {
        const int k0 = t * 64;
        for (int idx = tid; idx < 64 * 16; idx += 256) {
            int r = idx >> 4, c4 = (idx & 15) << 2;
            *(float4*)(Ks + r * AST + c4) =
                *(const float4*)(qkv + qbase + 1024 + (size_t)(k0 + r) * QKVN + c4);
            *(float4*)(Vs + r * AST + c4) =
                *(const float4*)(qkv + qbase + 2048 + (size_t)(k0 + r) * QKVN + c4);
        }
        if (tid < 64) {
            float mv = masks[b * SS + k0 + tid];
            mb[tid] = (mode == 0) ? mv : (mv > 0.0f ? 0.0f : -1e9f);
        }
        __syncthreads();

        // ---- scores: S(16q x 64k) = Q @ K^T per warp
        float S[8][4];
#pragma unroll
        for (int i = 0; i < 8; i++)
#pragma unroll
            for (int j = 0; j < 4; j++) S[i][j] = 0.0f;

#pragma unroll
        for (int k8 = 0; k8 < 64; k8 += 8) {
            uint32_t ah[4], al[4];
            {
                int base = (q0w + gr) * AST + k8 + gc;
                split1(Qs[base],               ah[0], al[0]);
                split1(Qs[base + 8 * AST],     ah[1], al[1]);
                split1(Qs[base + 4],           ah[2], al[2]);
                split1(Qs[base + 8 * AST + 4], ah[3], al[3]);
            }
#pragma unroll
            for (int nt = 0; nt < 8; nt++) {
                int base = (nt * 8 + gr) * AST + k8 + gc;
                uint32_t bh0, bl0, bh1, bl1;
                split1(Ks[base],     bh0, bl0);
                split1(Ks[base + 4], bh1, bl1);
                mma_tf32(S[nt], ah[0], ah[1], ah[2], ah[3], bh0, bh1);
                mma_tf32(S[nt], ah[0], ah[1], ah[2], ah[3], bl0, bl1);
                mma_tf32(S[nt], al[0], al[1], al[2], al[3], bh0, bh1);
            }
        }

        // ---- bias + online softmax
        float rmax[2] = {-1e30f, -1e30f};
#pragma unroll
        for (int nt = 0; nt < 8; nt++) {
            float m0 = mb[nt * 8 + 2 * gc];
            float m1 = mb[nt * 8 + 2 * gc + 1];
            S[nt][0] += m0; S[nt][1] += m1;
            S[nt][2] += m0; S[nt][3] += m1;
            rmax[0] = fmaxf(rmax[0], fmaxf(S[nt][0], S[nt][1]));
            rmax[1] = fmaxf(rmax[1], fmaxf(S[nt][2], S[nt][3]));
        }
#pragma unroll
        for (int sh = 1; sh < 4; sh <<= 1) {
            rmax[0] = fmaxf(rmax[0], __shfl_xor_sync(0xffffffffu, rmax[0], sh));
            rmax[1] = fmaxf(rmax[1], __shfl_xor_sync(0xffffffffu, rmax[1], sh));
        }
        float mnew0 = fmaxf(mrow[0], rmax[0]);
        float mnew1 = fmaxf(mrow[1], rmax[1]);
        float scl0 = __expf(mrow[0] - mnew0);
        float scl1 = __expf(mrow[1] - mnew1);
        float rsum[2] = {0.0f, 0.0f};
#pragma unroll
        for (int nt = 0; nt < 8; nt++) {
            S[nt][0] = __expf(S[nt][0] - mnew0);
            S[nt][1] = __expf(S[nt][1] - mnew0);
            S[nt][2] = __expf(S[nt][2] - mnew1);
            S[nt][3] = __expf(S[nt][3] - mnew1);
            rsum[0] += S[nt][0] + S[nt][1];
            rsum[1] += S[nt][2] + S[nt][3];
        }
#pragma unroll
        for (int sh = 1; sh < 4; sh <<= 1) {
            rsum[0] += __shfl_xor_sync(0xffffffffu, rsum[0], sh);
            rsum[1] += __shfl_xor_sync(0xffffffffu, rsum[1], sh);
        }
        lrow[0] = lrow[0] * scl0 + rsum[0];
        lrow[1] = lrow[1] * scl1 + rsum[1];
        mrow[0] = mnew0; mrow[1] = mnew1;
#pragma unroll
        for (int dt = 0; dt < 8; dt++) {
            Oacc[dt][0] *= scl0; Oacc[dt][1] *= scl0;
            Oacc[dt][2] *= scl1; Oacc[dt][3] *= scl1;
        }

        // ---- stage P to smem (per-warp private rows)
        __syncwarp();
#pragma unroll
        for (int nt = 0; nt < 8; nt++) {
            int c0 = nt * 8 + 2 * gc;
            Ps[(q0w + gr) * AST + c0]         = S[nt][0];
            Ps[(q0w + gr) * AST + c0 + 1]     = S[nt][1];
            Ps[(q0w + gr + 8) * AST + c0]     = S[nt][2];
            Ps[(q0w + gr + 8) * AST + c0 + 1] = S[nt][3];
        }
        __syncwarp();

        // ---- O += P @ V
#pragma unroll
        for (int k8 = 0; k8 < 64; k8 += 8) {
            uint32_t ah[4], al[4];
            {
                int base = (q0w + gr) * AST + k8 + gc;
                split1(Ps[base],               ah[0], al[0]);
                split1(Ps[base + 8 * AST],     ah[1], al[1]);
                split1(Ps[base + 4],           ah[2], al[2]);
                split1(Ps[base + 8 * AST + 4], ah[3], al[3]);
            }
#pragma unroll
            for (int dt = 0; dt < 8; dt++) {
                uint32_t bh0, bl0, bh1, bl1;
                split1(Vs[(k8 + gc) * AST + dt * 8 + gr],     bh0, bl0);
                split1(Vs[(k8 + gc + 4) * AST + dt * 8 + gr], bh1, bl1);
                mma_tf32(Oacc[dt], ah[0], ah[1], ah[2], ah[3], bh0, bh1);
                mma_tf32(Oacc[dt], ah[0], ah[1], ah[2], ah[3], bl0, bl1);
                mma_tf32(Oacc[dt], al[0], al[1], al[2], al[3], bh0, bh1);
            }
        }
        __syncthreads();
    }

    float inv0 = 1.0f / lrow[0];
    float inv1 = 1.0f / lrow[1];
    const int r0 = q0 + q0w + gr;
#pragma unroll
    for (int dt = 0; dt < 8; dt++) {
        int col = dt * 8 + 2 * gc;
        *(float2*)(o + obase + (size_t)r0 * DD + col) =
            make_float2(Oacc[dt][0] * inv0, Oacc[dt][1] * inv0);
        *(float2*)(o + obase + (size_t)(r0 + 8) * DD + col) =
            make_float2(Oacc[dt][2] * inv1, Oacc[dt][3] * inv1);
    }
}

// ---------------------------------------------------------------------------
// Weight transpose: Wt[n,k] = W[k,n] (fp32)
// ---------------------------------------------------------------------------
__global__ __launch_bounds__(256)
void transpose_kernel(const float* __restrict__ W, float* __restrict__ Wt,
                      int Kd, int Nd)
{
    __shared__ float t[32][33];
    const int n0 = blockIdx.x * 32, k0 = blockIdx.y * 32;
    const int tx = threadIdx.x & 31, ty = threadIdx.x >> 5;
#pragma unroll
    for (int r = ty; r < 32; r += 8)
        t[r][tx] = W[(size_t)(k0 + r) * Nd + n0 + tx];
    __syncthreads();
#pragma unroll
    for (int r = ty; r < 32; r += 8)
        Wt[(size_t)(n0 + r) * Kd + k0 + tx] = t[tx][r];
}

// ---------------------------------------------------------------------------
// Transpose + bf16 split: Wh/Wl[n,k] = split(W[k,n])
// ---------------------------------------------------------------------------
__global__ __launch_bounds__(256)
void trans_split_kernel(const float* __restrict__ W,
                        __nv_bfloat16* __restrict__ Wh,
                        __nv_bfloat16* __restrict__ Wl, int Kd, int Nd)
{
    __shared__ float t[32][33];
    const int n0 = blockIdx.x * 32, k0 = blockIdx.y * 32;
    const int tx = threadIdx.x & 31, ty = threadIdx.x >> 5;
#pragma unroll
    for (int r = ty; r < 32; r += 8)
        t[r][tx] = W[(size_t)(k0 + r) * Nd + n0 + tx];
    __syncthreads();
#pragma unroll
    for (int r = ty; r < 32; r += 8) {
        float v = t[tx][r];
        __nv_bfloat16 h, l;
        bsplit(v, h, l);
        Wh[(size_t)(n0 + r) * Kd + k0 + tx] = h;
        Wl[(size_t)(n0 + r) * Kd + k0 + tx] = l;
    }
}

// ---------------------------------------------------------------------------
// concat bias [bq|bk|bv] -> bqkv
// ---------------------------------------------------------------------------
__global__ __launch_bounds__(256)
void concat_bias_kernel(const float* __restrict__ bq, const float* __restrict__ bk,
                        const float* __restrict__ bv, float* __restrict__ bqkv)
{
    int i = blockIdx.x * 256 + threadIdx.x;
    if (i < QKVN) {
        float v = (i < 1024) ? bq[i] : ((i < 2048) ? bk[i - 1024] : bv[i - 2048]);
        bqkv[i] = v;
    }
}

// ---------------------------------------------------------------------------
// out = LayerNorm(a + b) * g + beta
// ---------------------------------------------------------------------------
__global__ __launch_bounds__(256)
void add_ln_kernel(const float* __restrict__ a, const float* __restrict__ b2,
                   const float* __restrict__ g, const float* __restrict__ beta,
                   float* __restrict__ out)
{
    const int row = blockIdx.x;
    const size_t off = (size_t)row * DD;
    const int t = threadIdx.x;
    __shared__ float r1[256], r2[256];

    float vloc[4];
    float s = 0.0f, s2 = 0.0f;
#pragma unroll
    for (int i = 0; i < 4; i++) {
        int d = t + i * 256;
        float vv = a[off + d] + b2[off + d];
        vloc[i] = vv;
        s += vv; s2 += vv * vv;
    }
    r1[t] = s; r2[t] = s2;
    __syncthreads();
    for (int o2 = 128; o2 > 0; o2 >>= 1) {
        if (t < o2) { r1[t] += r1[t + o2]; r2[t] += r2[t + o2]; }
        __syncthreads();
    }
    float mean = r1[0] * (1.0f / DD);
    float var  = r2[0] * (1.0f / DD) - mean * mean;
    float inv  = rsqrtf(var + 1e-5f);
#pragma unroll
    for (int i = 0; i < 4; i++) {
        int d = t + i * 256;
        out[off + d] = (vloc[i] - mean) * inv * g[d] + beta[d];
    }
}

// ---------------------------------------------------------------------------
// s = sigmoid(feat @ Ws + bs); one warp per token
// ---------------------------------------------------------------------------
__global__ __launch_bounds__(256)
void score_kernel(const float* __restrict__ feat, const float* __restrict__ Ws,
                  const float* __restrict__ bs, float* __restrict__ sbuf)
{
    int token = blockIdx.x * 8 + (threadIdx.x >> 5);
    int lane  = threadIdx.x & 31;
    const float* f = feat + (size_t)token * DD;
    float acc = 0.0f;
    for (int i = lane; i < DD; i += 32) acc += f[i] * Ws[i];
#pragma unroll
    for (int m = 16; m; m >>= 1) acc += __shfl_xor_sync(0xffffffffu, acc, m);
    if (lane == 0) sbuf[token] = 1.0f / (1.0f + expf(-(acc + bs[0])));
}

// ---------------------------------------------------------------------------
// Per-batch inclusive scan of sv, floor -> segment ids, max over valid
// ---------------------------------------------------------------------------
__global__ __launch_bounds__(1024)
void scan_kernel(const float* __restrict__ sbuf, const float* __restrict__ masks,
                 float* __restrict__ svbuf, int* __restrict__ segbuf,
                 float* __restrict__ maxseg)
{
    const int b = blockIdx.x;
    const int t = threadIdx.x;
    __shared__ float sc[SS];
    __shared__ float mr[SS];

    float valid = masks[b * SS + t];
    float sv = (valid > 0.0f) ? sbuf[b * SS + t] : 0.0f;
    svbuf[b * SS + t] = sv;
    sc[t] = sv;
    __syncthreads();
    for (int off = 1; off < SS; off <<= 1) {
        float vprev = (t >= off) ? sc[t - off] : 0.0f;
        __syncthreads();
        sc[t] += vprev;
        __syncthreads();
    }
    float c = floorf(sc[t]);
    int seg = (int)c;
    seg = seg < 0 ? 0 : (seg > SS - 1 ? SS - 1 : seg);
    segbuf[b * SS + t] = seg;

    mr[t] = (valid > 0.0f) ? c : -1.0f;
    __syncthreads();
    for (int off = 512; off > 0; off >>= 1) {
        if (t < off) mr[t] = fmaxf(mr[t], mr[t + off]);
        __syncthreads();
    }
    if (t == 0) maxseg[b] = mr[0];
}

// ---------------------------------------------------------------------------
// pooled[b,g,:] = sum_{s: seg[b,s]==g} x[b,s,:]*sv[b,s] -> split bf16 output
// ---------------------------------------------------------------------------
__global__ __launch_bounds__(256)
void pool_kernel(const float* __restrict__ x, const float* __restrict__ svbuf,
                 const int* __restrict__ segbuf,
                 __nv_bfloat16* __restrict__ ph, __nv_bfloat16* __restrict__ pl)
{
    const int g = blockIdx.x;
    const int b = blockIdx.y;
    const int* seg = segbuf + b * SS;

    int lo = 0, hi = SS;
    while (lo < hi) { int mid = (lo + hi) >> 1; if (seg[mid] < g) lo = mid + 1; else hi = mid; }
    int beg = lo;
    lo = beg; hi = SS;
    while (lo < hi) { int mid = (lo + hi) >> 1; if (seg[mid] < g + 1) lo = mid + 1; else hi = mid; }
    int end = lo;

    const int t = threadIdx.x;
    float acc[4] = {0.0f, 0.0f, 0.0f, 0.0f};
    for (int s = beg; s < end; s++) {
        float w = svbuf[b * SS + s];
        const float* xr = x + ((size_t)b * SS + s) * DD;
#pragma unroll
        for (int i = 0; i < 4; i++) acc[i] += xr[t + i * 256] * w;
    }
    size_t rbase = ((size_t)b * SS + g) * DD;
#pragma unroll
    for (int i = 0; i < 4; i++) {
        __nv_bfloat16 h, l;
        bsplit(acc[i], h, l);
        ph[rbase + t + i * 256] = h;
        pl[rbase + t + i * 256] = l;
    }
}

// ---------------------------------------------------------------------------
// new_mask[b,s] = (s <= max_seg[b]) ? 1 : 0
// ---------------------------------------------------------------------------
__global__ __launch_bounds__(1024)
void mask_kernel(const float* __restrict__ maxseg, float* __restrict__ outmask)
{
    const int b = blockIdx.x;
    const int t = threadIdx.x;
    outmask[b * SS + t] = ((float)t <= maxseg[b]) ? 1.0f : 0.0f;
}

// ---------------------------------------------------------------------------
// Host side
// ---------------------------------------------------------------------------
static void* sym_addr(const void* sym) {
    void* p = nullptr;
    cudaGetSymbolAddress(&p, sym);
    return p;
}

static void launch_tgemm(const float* A, const float* Bt, const float* bias,
                         float* C, int M, int N, int K, int act) {
    dim3 grid(N / 128, M / 128);
    mma_gemm_kernel<<<grid, 256>>>(A, Bt, bias, C, M, N, K, act);
}

static void launch_bgemm(const __nv_bfloat16* Ah, const __nv_bfloat16* Al,
                         const __nv_bfloat16* Bh, const __nv_bfloat16* Bl,
                         const float* bias, float* C,
                         __nv_bfloat16* Ch, __nv_bfloat16* Cl,
                         int M, int N, int K, int act, int out_split) {
    dim3 grid(N / 128, M / 128);
    bf16_gemm_kernel<<<grid, 256, BF_SMEM_BYTES>>>(Ah, Al, Bh, Bl, bias, C,
                                                   Ch, Cl, M, N, K, act, out_split);
}

static void launch_transpose(const float* W, float* Wt, int Kd, int Nd) {
    transpose_kernel<<<dim3(Nd / 32, Kd / 32), 256>>>(W, Wt, Kd, Nd);
}

extern "C" void kernel_launch(void* const* d_in, const int* in_sizes, int n_in,
                              void* d_out, int out_size)
{
    (void)in_sizes; (void)n_in;
    const float* x     = (const float*)d_in[0];
    const float* masks = (const float*)d_in[1];
    const float* Wq  = (const float*)d_in[2];
    const float* bq  = (const float*)d_in[3];
    const float* Wk  = (const float*)d_in[4];
    const float* bk  = (const float*)d_in[5];
    const float* Wv  = (const float*)d_in[6];
    const float* bv  = (const float*)d_in[7];
    const float* Wo  = (const float*)d_in[8];
    const float* bo  = (const float*)d_in[9];
    const float* g1  = (const float*)d_in[10];
    const float* be1 = (const float*)d_in[11];
    const float* g2  = (const float*)d_in[12];
    const float* be2 = (const float*)d_in[13];
    const float* W1  = (const float*)d_in[14];
    const float* bf1 = (const float*)d_in[15];
    const float* W2  = (const float*)d_in[16];
    const float* bf2 = (const float*)d_in[17];
    const float* Ws  = (const float*)d_in[18];
    const float* bs  = (const float*)d_in[19];
    const float* P1  = (const float*)d_in[20];
    const float* bp1 = (const float*)d_in[21];
    const float* P2  = (const float*)d_in[22];
    const float* bp2 = (const float*)d_in[23];

    float* out = (float*)d_out;
    (void)out_size;

    cudaFuncSetAttribute(attn_mma_kernel,
                         cudaFuncAttributeMaxDynamicSharedMemorySize,
                         ATT_SMEM_BYTES);
    cudaFuncSetAttribute(bf16_gemm_kernel,
                         cudaFuncAttributeMaxDynamicSharedMemorySize,
                         BF_SMEM_BYTES);

    float* qkvb  = (float*)sym_addr(g_qkv);
    float* attb  = (float*)sym_addr(g_att);
    float* ob    = (float*)sym_addr(g_o);
    float* hb    = (float*)sym_addr(g_h);
    float* featb = (float*)sym_addr(g_feat);
    float* feat2b= (float*)sym_addr(g_feat2);
    float* ffb   = (float*)sym_addr(g_ff);
    float* sb    = (float*)sym_addr(g_s);
    float* svb   = (float*)sym_addr(g_sv);
    int*   segb  = (int*)sym_addr(g_seg);
    float* msb   = (float*)sym_addr(g_maxseg);
    float* bqkvb = (float*)sym_addr(g_bqkv);

    float* Wqkvt = (float*)sym_addr(g_wt_qkv);
    float* Wot = (float*)sym_addr(g_wt_o);
    float* W1t = (float*)sym_addr(g_wt_1);
    float* W2t = (float*)sym_addr(g_wt_2);

    __nv_bfloat16* p1h = (__nv_bfloat16*)sym_addr(g_p1h);
    __nv_bfloat16* p1l = (__nv_bfloat16*)sym_addr(g_p1l);
    __nv_bfloat16* p2h = (__nv_bfloat16*)sym_addr(g_p2h);
    __nv_bfloat16* p2l = (__nv_bfloat16*)sym_addr(g_p2l);
    __nv_bfloat16* poolh = (__nv_bfloat16*)sym_addr(g_poolh);
    __nv_bfloat16* pooll = (__nv_bfloat16*)sym_addr(g_pooll);
    __nv_bfloat16* phh = (__nv_bfloat16*)sym_addr(g_phh);
    __nv_bfloat16* phl = (__nv_bfloat16*)sym_addr(g_phl);

    // ---- weight prep ----
    launch_transpose(Wq, Wqkvt,               DD, DD);
    launch_transpose(Wk, Wqkvt + DD * DD,     DD, DD);
    launch_transpose(Wv, Wqkvt + 2 * DD * DD, DD, DD);
    launch_transpose(Wo, Wot, DD, DD);
    launch_transpose(W1, W1t, DD, FF);
    launch_transpose(W2, W2t, FF, DD);
    trans_split_kernel<<<dim3(HID / 32, DD / 32), 256>>>(P1, p1h, p1l, DD, HID);
    trans_split_kernel<<<dim3(HID / 32, HID / 32), 256>>>(P2, p2h, p2l, HID, HID);
    concat_bias_kernel<<<(QKVN + 255) / 256, 256>>>(bq, bk, bv, bqkvb);

    // ---- encoder layer, applied twice (tf32 exact path) ----
    const float* enc_in = x;
    float* enc_out = featb;
    for (int pass = 0; pass < 2; pass++) {
        int mode = pass;
        launch_tgemm(enc_in, Wqkvt, bqkvb, qkvb, TOK, QKVN, DD, 0);
        attn_mma_kernel<<<dim3(SS / 128, BB * HH), 256, ATT_SMEM_BYTES>>>(
            qkvb, masks, mode, attb);
        launch_tgemm(attb, Wot, bo, ob, TOK, DD, DD, 0);
        add_ln_kernel<<<TOK, 256>>>(enc_in, ob, g1, be1, hb);
        launch_tgemm(hb, W1t, bf1, ffb, TOK, FF, DD, 1);   // GELU
        launch_tgemm(ffb, W2t, bf2, ob, TOK, DD, FF, 0);
        add_ln_kernel<<<TOK, 256>>>(hb, ob, g2, be2, enc_out);
        enc_in = featb;
        enc_out = feat2b;
    }

    // ---- importance scores, cumsum segmentation ----
    score_kernel<<<TOK / 8, 256>>>(feat2b, Ws, bs, sb);
    scan_kernel<<<BB, 1024>>>(sb, masks, svb, segb, msb);

    // ---- weighted segment-sum pooling of original x (split bf16 output) ----
    pool_kernel<<<dim3(SS, BB), 256>>>(x, svb, segb, poolh, pooll);

    // ---- projector on bf16-split tensor cores ----
    launch_bgemm(poolh, pooll, p1h, p1l, bp1, nullptr, phh, phl,
                 TOK, HID, DD, 1, 1);                    // GELU, split out
    launch_bgemm(phh, phl, p2h, p2l, bp2, out, nullptr, nullptr,
                 TOK, HID, HID, 0, 0);                   // fp32 out

    // ---- new_mask appended after the [B,S,HID] output ----
    mask_kernel<<<BB, 1024>>>(msb, out + (size_t)TOK * HID);
}

// round 7
// speedup vs baseline: 1.1630x; 1.1630x over previous
#include <cuda_runtime.h>
#include <cuda_fp16.h>
#include <cstdint>
#include <math.h>

// ---------------------------------------------------------------------------
// Problem constants
// ---------------------------------------------------------------------------
#define BB 4
#define SS 1024
#define DD 1024
#define HH 16
#define HDIM 64
#define FF 2048
#define HID 4096
#define TOK (BB*SS)          // 4096 tokens
#define QKVN 3072
#define WSCALE (1.0f/64.0f)  // weights pre-scaled by 64 (fp16 subnormal guard)

// ---------------------------------------------------------------------------
// Scratch (__device__ globals; no allocation allowed)
// ---------------------------------------------------------------------------
__device__ float g_qkv [TOK*QKVN];
__device__ float g_o   [TOK*DD];
__device__ float g_h   [TOK*DD];
__device__ float g_feat[TOK*DD];
__device__ float g_feat2[TOK*DD];
__device__ float g_s   [TOK];
__device__ float g_sv  [TOK];
__device__ int   g_seg [TOK];
__device__ float g_maxseg[BB];
__device__ float g_bqkv[QKVN];

// fp16 split activations
__device__ __half g_xh[TOK*DD],    g_xl[TOK*DD];
__device__ __half g_fh[TOK*DD],    g_fl[TOK*DD];     // feat / feat2 split
__device__ __half g_ath[TOK*DD],   g_atl[TOK*DD];    // attention out split
__device__ __half g_hh[TOK*DD],    g_hl[TOK*DD];     // h split
__device__ __half g_ffh[TOK*FF],   g_ffl[TOK*FF];    // ffn mid split
__device__ __half g_plh[TOK*DD],   g_pll[TOK*DD];    // pooled split
__device__ __half g_phh[TOK*HID],  g_phl[TOK*HID];   // projector mid split

// fp16 split weights [N,K] K-contiguous, pre-scaled x64
__device__ __half g_wqkvh[QKVN*DD], g_wqkvl[QKVN*DD];
__device__ __half g_woh[DD*DD],     g_wol[DD*DD];
__device__ __half g_w1h[FF*DD],     g_w1l[FF*DD];
__device__ __half g_w2h[DD*FF],     g_w2l[DD*FF];
__device__ __half g_p1h[HID*DD],    g_p1l[HID*DD];
__device__ __half g_p2h[HID*HID],   g_p2l[HID*HID];

// ---------------------------------------------------------------------------
// Helpers
// ---------------------------------------------------------------------------
__device__ __forceinline__ float gelu_f(float x) {
    return 0.5f * x * (1.0f + erff(x * 0.70710678118654752440f));
}

__device__ __forceinline__ void cp16(uint32_t dst, const void* src) {
    asm volatile("cp.async.cg.shared.global [%0], [%1], 16;\n"
                 :: "r"(dst), "l"(src));
}

__device__ __forceinline__ uint32_t smem_u32(const void* p) {
    uint32_t a;
    asm("{ .reg .u64 t; cvta.to.shared.u64 t, %1; cvt.u32.u64 %0, t; }"
        : "=r"(a) : "l"(p));
    return a;
}

// mma.sync m16n8k8 tf32: D += A*B (attention path)
__device__ __forceinline__ void mma_tf32(float* c,
                                         uint32_t a0, uint32_t a1,
                                         uint32_t a2, uint32_t a3,
                                         uint32_t b0, uint32_t b1) {
    asm volatile(
        "mma.sync.aligned.m16n8k8.row.col.f32.tf32.tf32.f32 "
        "{%0,%1,%2,%3}, {%4,%5,%6,%7}, {%8,%9}, {%0,%1,%2,%3};\n"
        : "+f"(c[0]), "+f"(c[1]), "+f"(c[2]), "+f"(c[3])
        : "r"(a0), "r"(a1), "r"(a2), "r"(a3), "r"(b0), "r"(b1));
}

// mma.sync m16n8k16 f16 with f32 accumulate
__device__ __forceinline__ void mma_f16(float* c,
                                        uint32_t a0, uint32_t a1,
                                        uint32_t a2, uint32_t a3,
                                        uint32_t b0, uint32_t b1) {
    asm volatile(
        "mma.sync.aligned.m16n8k16.row.col.f32.f16.f16.f32 "
        "{%0,%1,%2,%3}, {%4,%5,%6,%7}, {%8,%9}, {%0,%1,%2,%3};\n"
        : "+f"(c[0]), "+f"(c[1]), "+f"(c[2]), "+f"(c[3])
        : "r"(a0), "r"(a1), "r"(a2), "r"(a3), "r"(b0), "r"(b1));
}

__device__ __forceinline__ void split1(float v, uint32_t& h, uint32_t& l) {
    uint32_t hb = __float_as_uint(v) & 0xFFFFE000u;
    h = hb;
    l = __float_as_uint(v - __uint_as_float(hb));
}

__device__ __forceinline__ void hsplit(float v, __half& h, __half& l) {
    h = __float2half(v);
    l = __float2half(v - __half2float(h));
}

// ---------------------------------------------------------------------------
// fp16 2-split 3-combo GEMM (fp32-grade accuracy, half the tf32 instr count)
// C[M,N] = act((A @ Bt^T) * WSCALE + bias[N]),  A = Ah+Al, Bt = Bh+Bl
// BM=BN=128, BK=32 halves/stage; smem row stride 40 halves (conflict-free).
// out_split=1: write split fp16 (Ch, Cl) instead of fp32 C.
// ---------------------------------------------------------------------------
#define HS 40
#define H_STAGE_HALVES 20480          // 4 arrays * 128*40
#define H_SMEM_BYTES  (2 * H_STAGE_HALVES * 2)

__global__ __launch_bounds__(256)
void hgemm_kernel(const __half* __restrict__ Ah, const __half* __restrict__ Al,
                  const __half* __restrict__ Bh, const __half* __restrict__ Bl,
                  const float* __restrict__ bias, float* __restrict__ C,
                  __half* __restrict__ Ch, __half* __restrict__ Cl,
                  int M, int N, int K, int act, int out_split)
{
    extern __shared__ __half hsm[];
    const int tid  = threadIdx.x;
    const int wid  = tid >> 5;
    const int lane = tid & 31;
    const int gr   = lane >> 2;
    const int gc   = lane & 3;
    const int row0 = blockIdx.y * 128;
    const int col0 = blockIdx.x * 128;
    const int warp_m = (wid & 3) * 32;
    const int warp_n = (wid >> 2) * 64;
    const uint32_t sbase = smem_u32(hsm);

    float acc[2][8][4];
#pragma unroll
    for (int i = 0; i < 2; i++)
#pragma unroll
        for (int j = 0; j < 8; j++)
#pragma unroll
            for (int r = 0; r < 4; r++) acc[i][j][r] = 0.0f;

    const int nk = K >> 5;
    const int c0i = tid * 2, c1i = tid * 2 + 1;
    const int m0 = c0i >> 2, kc0 = (c0i & 3) * 8;
    const int m1 = c1i >> 2, kc1 = (c1i & 3) * 8;

#define H_LOAD_STAGE(st, k0)                                                     \
    do {                                                                         \
        uint32_t b = sbase + (uint32_t)(st) * H_STAGE_HALVES * 2u;               \
        cp16(b + (uint32_t)(m0 * HS + kc0) * 2u,                                 \
             Ah + (size_t)(row0 + m0) * K + (k0) + kc0);                         \
        cp16(b + (uint32_t)(m1 * HS + kc1) * 2u,                                 \
             Ah + (size_t)(row0 + m1) * K + (k0) + kc1);                         \
        cp16(b + (uint32_t)(5120 + m0 * HS + kc0) * 2u,                          \
             Al + (size_t)(row0 + m0) * K + (k0) + kc0);                         \
        cp16(b + (uint32_t)(5120 + m1 * HS + kc1) * 2u,                          \
             Al + (size_t)(row0 + m1) * K + (k0) + kc1);                         \
        cp16(b + (uint32_t)(10240 + m0 * HS + kc0) * 2u,                         \
             Bh + (size_t)(col0 + m0) * K + (k0) + kc0);                         \
        cp16(b + (uint32_t)(10240 + m1 * HS + kc1) * 2u,                         \
             Bh + (size_t)(col0 + m1) * K + (k0) + kc1);                         \
        cp16(b + (uint32_t)(15360 + m0 * HS + kc0) * 2u,                         \
             Bl + (size_t)(col0 + m0) * K + (k0) + kc0);                         \
        cp16(b + (uint32_t)(15360 + m1 * HS + kc1) * 2u,                         \
             Bl + (size_t)(col0 + m1) * K + (k0) + kc1);                         \
        asm volatile("cp.async.commit_group;\n");                                \
    } while (0)

    H_LOAD_STAGE(0, 0);

    for (int t = 0; t < nk; t++) {
        const int st = t & 1;
        if (t + 1 < nk) {
            H_LOAD_STAGE((t + 1) & 1, (t + 1) << 5);
            asm volatile("cp.async.wait_group 1;\n");
        } else {
            asm volatile("cp.async.wait_group 0;\n");
        }
        __syncthreads();

        const __half* s = hsm + st * H_STAGE_HALVES;

#pragma unroll
        for (int ks = 0; ks < 2; ks++) {
            const int kh = ks * 16;
            uint32_t ahf[2][4], alf[2][4];
#pragma unroll
            for (int mt = 0; mt < 2; mt++) {
                int r = warp_m + mt * 16 + gr;
                ahf[mt][0] = *(const uint32_t*)(s + r * HS + kh + 2 * gc);
                ahf[mt][1] = *(const uint32_t*)(s + (r + 8) * HS + kh + 2 * gc);
                ahf[mt][2] = *(const uint32_t*)(s + r * HS + kh + 8 + 2 * gc);
                ahf[mt][3] = *(const uint32_t*)(s + (r + 8) * HS + kh + 8 + 2 * gc);
                alf[mt][0] = *(const uint32_t*)(s + 5120 + r * HS + kh + 2 * gc);
                alf[mt][1] = *(const uint32_t*)(s + 5120 + (r + 8) * HS + kh + 2 * gc);
                alf[mt][2] = *(const uint32_t*)(s + 5120 + r * HS + kh + 8 + 2 * gc);
                alf[mt][3] = *(const uint32_t*)(s + 5120 + (r + 8) * HS + kh + 8 + 2 * gc);
            }
#pragma unroll
            for (int nt = 0; nt < 8; nt++) {
                int r = warp_n + nt * 8 + gr;
                uint32_t bh0 = *(const uint32_t*)(s + 10240 + r * HS + kh + 2 * gc);
                uint32_t bh1 = *(const uint32_t*)(s + 10240 + r * HS + kh + 8 + 2 * gc);
                uint32_t bl0 = *(const uint32_t*)(s + 15360 + r * HS + kh + 2 * gc);
                uint32_t bl1 = *(const uint32_t*)(s + 15360 + r * HS + kh + 8 + 2 * gc);
#pragma unroll
                for (int mt = 0; mt < 2; mt++) {
                    float* c = acc[mt][nt];
                    mma_f16(c, ahf[mt][0], ahf[mt][1], ahf[mt][2], ahf[mt][3], bh0, bh1);
                    mma_f16(c, ahf[mt][0], ahf[mt][1], ahf[mt][2], ahf[mt][3], bl0, bl1);
                    mma_f16(c, alf[mt][0], alf[mt][1], alf[mt][2], alf[mt][3], bh0, bh1);
                }
            }
        }
        __syncthreads();
    }

#pragma unroll
    for (int mt = 0; mt < 2; mt++) {
        const int r0 = row0 + warp_m + mt * 16 + gr;
#pragma unroll
        for (int nt = 0; nt < 8; nt++) {
            const int cc = col0 + warp_n + nt * 8 + 2 * gc;
            float b0v = bias[cc], b1v = bias[cc + 1];
            float v0 = acc[mt][nt][0] * WSCALE + b0v;
            float v1 = acc[mt][nt][1] * WSCALE + b1v;
            float v2 = acc[mt][nt][2] * WSCALE + b0v;
            float v3 = acc[mt][nt][3] * WSCALE + b1v;
            if (act == 1) {
                v0 = gelu_f(v0); v1 = gelu_f(v1);
                v2 = gelu_f(v2); v3 = gelu_f(v3);
            }
            if (!out_split) {
                *(float2*)(C + (size_t)r0 * N + cc)       = make_float2(v0, v1);
                *(float2*)(C + (size_t)(r0 + 8) * N + cc) = make_float2(v2, v3);
            } else {
                __half h0, l0, h1, l1;
                hsplit(v0, h0, l0); hsplit(v1, h1, l1);
                *(__half2*)(Ch + (size_t)r0 * N + cc) = __halves2half2(h0, h1);
                *(__half2*)(Cl + (size_t)r0 * N + cc) = __halves2half2(l0, l1);
                hsplit(v2, h0, l0); hsplit(v3, h1, l1);
                *(__half2*)(Ch + (size_t)(r0 + 8) * N + cc) = __halves2half2(h0, h1);
                *(__half2*)(Cl + (size_t)(r0 + 8) * N + cc) = __halves2half2(l0, l1);
            }
        }
    }
}

// ---------------------------------------------------------------------------
// Tensor-core flash attention (R5 config: 64-q tile, 128 threads, tf32 split).
// Epilogue writes fp16-split output (consumed only by Wo GEMM).
// ---------------------------------------------------------------------------
#define AST 72
#define ATT_SMEM_BYTES (4 * 64 * AST * 4 + 64 * 4)

__global__ __launch_bounds__(128)
void attn_mma_kernel(const float* __restrict__ qkv, const float* __restrict__ masks,
                     int mode, __half* __restrict__ oh, __half* __restrict__ ol)
{
    extern __shared__ float smem[];
    float* Qs = smem;
    float* Ks = Qs + 64 * AST;
    float* Vs = Ks + 64 * AST;
    float* Ps = Vs + 64 * AST;
    float* mb = Ps + 64 * AST;

    const int tid  = threadIdx.x;
    const int wid  = tid >> 5;
    const int lane = tid & 31;
    const int gr   = lane >> 2;
    const int gc   = lane & 3;
    const int q0   = blockIdx.x * 64;
    const int b    = blockIdx.y >> 4;
    const int h    = blockIdx.y & 15;
    const size_t qbase = (size_t)b * SS * QKVN + (size_t)h * HDIM;
    const size_t obase = (size_t)b * SS * DD + (size_t)h * HDIM;
    const int q0w = wid * 16;

    for (int idx = tid; idx < 64 * 16; idx += 128) {
        int r = idx >> 4, c4 = (idx & 15) << 2;
        float4 v = *(const float4*)(qkv + qbase + (size_t)(q0 + r) * QKVN + c4);
        v.x *= 0.125f; v.y *= 0.125f; v.z *= 0.125f; v.w *= 0.125f;
        *(float4*)(Qs + r * AST + c4) = v;
    }

    float mrow[2] = {-1e30f, -1e30f};
    float lrow[2] = {0.0f, 0.0f};
    float Oacc[8][4];
#pragma unroll
    for (int i = 0; i < 8; i++)
#pragma unroll
        for (int j = 0; j < 4; j++) Oacc[i][j] = 0.0f;
    __syncthreads();

    for (int t = 0; t < 16; t++) {
        const int k0 = t * 64;
        for (int idx = tid; idx < 64 * 16; idx += 128) {
            int r = idx >> 4, c4 = (idx & 15) << 2;
            *(float4*)(Ks + r * AST + c4) =
                *(const float4*)(qkv + qbase + 1024 + (size_t)(k0 + r) * QKVN + c4);
            *(float4*)(Vs + r * AST + c4) =
                *(const float4*)(qkv + qbase + 2048 + (size_t)(k0 + r) * QKVN + c4);
        }
        if (tid < 64) {
            float mv = masks[b * SS + k0 + tid];
            mb[tid] = (mode == 0) ? mv : (mv > 0.0f ? 0.0f : -1e9f);
        }
        __syncthreads();

        float S[8][4];
#pragma unroll
        for (int i = 0; i < 8; i++)
#pragma unroll
            for (int j = 0; j < 4; j++) S[i][j] = 0.0f;

#pragma unroll
        for (int k8 = 0; k8 < 64; k8 += 8) {
            uint32_t ah[4], al[4];
            {
                int base = (q0w + gr) * AST + k8 + gc;
                split1(Qs[base],               ah[0], al[0]);
                split1(Qs[base + 8 * AST],     ah[1], al[1]);
                split1(Qs[base + 4],           ah[2], al[2]);
                split1(Qs[base + 8 * AST + 4], ah[3], al[3]);
            }
#pragma unroll
            for (int nt = 0; nt < 8; nt++) {
                int base = (nt * 8 + gr) * AST + k8 + gc;
                uint32_t bh0, bl0, bh1, bl1;
                split1(Ks[base],     bh0, bl0);
                split1(Ks[base + 4], bh1, bl1);
                mma_tf32(S[nt], ah[0], ah[1], ah[2], ah[3], bh0, bh1);
                mma_tf32(S[nt], ah[0], ah[1], ah[2], ah[3], bl0, bl1);
                mma_tf32(S[nt], al[0], al[1], al[2], al[3], bh0, bh1);
            }
        }

        float rmax[2] = {-1e30f, -1e30f};
#pragma unroll
        for (int nt = 0; nt < 8; nt++) {
            float m0 = mb[nt * 8 + 2 * gc];
            float m1 = mb[nt * 8 + 2 * gc + 1];
            S[nt][0] += m0; S[nt][1] += m1;
            S[nt][2] += m0; S[nt][3] += m1;
            rmax[0] = fmaxf(rmax[0], fmaxf(S[nt][0], S[nt][1]));
            rmax[1] = fmaxf(rmax[1], fmaxf(S[nt][2], S[nt][3]));
        }
#pragma unroll
        for (int sh = 1; sh < 4; sh <<= 1) {
            rmax[0] = fmaxf(rmax[0], __shfl_xor_sync(0xffffffffu, rmax[0], sh));
            rmax[1] = fmaxf(rmax[1], __shfl_xor_sync(0xffffffffu, rmax[1], sh));
        }
        float mnew0 = fmaxf(mrow[0], rmax[0]);
        float mnew1 = fmaxf(mrow[1], rmax[1]);
        float scl0 = __expf(mrow[0] - mnew0);
        float scl1 = __expf(mrow[1] - mnew1);
        float rsum[2] = {0.0f, 0.0f};
#pragma unroll
        for (int nt = 0; nt < 8; nt++) {
            S[nt][0] = __expf(S[nt][0] - mnew0);
            S[nt][1] = __expf(S[nt][1] - mnew0);
            S[nt][2] = __expf(S[nt][2] - mnew1);
            S[nt][3] = __expf(S[nt][3] - mnew1);
            rsum[0] += S[nt][0] + S[nt][1];
            rsum[1] += S[nt][2] + S[nt][3];
        }
#pragma unroll
        for (int sh = 1; sh < 4; sh <<= 1) {
            rsum[0] += __shfl_xor_sync(0xffffffffu, rsum[0], sh);
            rsum[1] += __shfl_xor_sync(0xffffffffu, rsum[1], sh);
        }
        lrow[0] = lrow[0] * scl0 + rsum[0];
        lrow[1] = lrow[1] * scl1 + rsum[1];
        mrow[0] = mnew0; mrow[1] = mnew1;
#pragma unroll
        for (int dt = 0; dt < 8; dt++) {
            Oacc[dt][0] *= scl0; Oacc[dt][1] *= scl0;
            Oacc[dt][2] *= scl1; Oacc[dt][3] *= scl1;
        }

        __syncwarp();
#pragma unroll
        for (int nt = 0; nt < 8; nt++) {
            int c0 = nt * 8 + 2 * gc;
            Ps[(q0w + gr) * AST + c0]         = S[nt][0];
            Ps[(q0w + gr) * AST + c0 + 1]     = S[nt][1];
            Ps[(q0w + gr + 8) * AST + c0]     = S[nt][2];
            Ps[(q0w + gr + 8) * AST + c0 + 1] = S[nt][3];
        }
        __syncwarp();

#pragma unroll
        for (int k8 = 0; k8 < 64; k8 += 8) {
            uint32_t ah[4], al[4];
            {
                int base = (q0w + gr) * AST + k8 + gc;
                split1(Ps[base],               ah[0], al[0]);
                split1(Ps[base + 8 * AST],     ah[1], al[1]);
                split1(Ps[base + 4],           ah[2], al[2]);
                split1(Ps[base + 8 * AST + 4], ah[3], al[3]);
            }
#pragma unroll
            for (int dt = 0; dt < 8; dt++) {
                uint32_t bh0, bl0, bh1, bl1;
                split1(Vs[(k8 + gc) * AST + dt * 8 + gr],     bh0, bl0);
                split1(Vs[(k8 + gc + 4) * AST + dt * 8 + gr], bh1, bl1);
                mma_tf32(Oacc[dt], ah[0], ah[1], ah[2], ah[3], bh0, bh1);
                mma_tf32(Oacc[dt], ah[0], ah[1], ah[2], ah[3], bl0, bl1);
                mma_tf32(Oacc[dt], al[0], al[1], al[2], al[3], bh0, bh1);
            }
        }
        __syncthreads();
    }

    float inv0 = 1.0f / lrow[0];
    float inv1 = 1.0f / lrow[1];
    const int r0 = q0 + q0w + gr;
#pragma unroll
    for (int dt = 0; dt < 8; dt++) {
        int col = dt * 8 + 2 * gc;
        __half h0, l0, h1, l1;
        hsplit(Oacc[dt][0] * inv0, h0, l0);
        hsplit(Oacc[dt][1] * inv0, h1, l1);
        *(__half2*)(oh + obase + (size_t)r0 * DD + col) = __halves2half2(h0, h1);
        *(__half2*)(ol + obase + (size_t)r0 * DD + col) = __halves2half2(l0, l1);
        hsplit(Oacc[dt][2] * inv1, h0, l0);
        hsplit(Oacc[dt][3] * inv1, h1, l1);
        *(__half2*)(oh + obase + (size_t)(r0 + 8) * DD + col) = __halves2half2(h0, h1);
        *(__half2*)(ol + obase + (size_t)(r0 + 8) * DD + col) = __halves2half2(l0, l1);
    }
}

// ---------------------------------------------------------------------------
// Transpose + scale x64 + fp16 split: Wh/Wl[n,k] = split(64 * W[k,n])
// ---------------------------------------------------------------------------
__global__ __launch_bounds__(256)
void trans_split_h_kernel(const float* __restrict__ W,
                          __half* __restrict__ Wh, __half* __restrict__ Wl,
                          int Kd, int Nd)
{
    __shared__ float t[32][33];
    const int n0 = blockIdx.x * 32, k0 = blockIdx.y * 32;
    const int tx = threadIdx.x & 31, ty = threadIdx.x >> 5;
#pragma unroll
    for (int r = ty; r < 32; r += 8)
        t[r][tx] = W[(size_t)(k0 + r) * Nd + n0 + tx];
    __syncthreads();
#pragma unroll
    for (int r = ty; r < 32; r += 8) {
        float v = t[tx][r] * 64.0f;
        __half h, l;
        hsplit(v, h, l);
        Wh[(size_t)(n0 + r) * Kd + k0 + tx] = h;
        Wl[(size_t)(n0 + r) * Kd + k0 + tx] = l;
    }
}

// ---------------------------------------------------------------------------
// Elementwise fp16 split of an fp32 array
// ---------------------------------------------------------------------------
__global__ __launch_bounds__(256)
void split_h_kernel(const float* __restrict__ a, __half* __restrict__ ah,
                    __half* __restrict__ al, int n)
{
    int i = blockIdx.x * 256 + threadIdx.x;
    if (i < n) {
        __half h, l;
        hsplit(a[i], h, l);
        ah[i] = h; al[i] = l;
    }
}

// ---------------------------------------------------------------------------
// concat bias [bq|bk|bv] -> bqkv
// ---------------------------------------------------------------------------
__global__ __launch_bounds__(256)
void concat_bias_kernel(const float* __restrict__ bq, const float* __restrict__ bk,
                        const float* __restrict__ bv, float* __restrict__ bqkv)
{
    int i = blockIdx.x * 256 + threadIdx.x;
    if (i < QKVN) {
        float v = (i < 1024) ? bq[i] : ((i < 2048) ? bk[i - 1024] : bv[i - 2048]);
        bqkv[i] = v;
    }
}

// ---------------------------------------------------------------------------
// out = LayerNorm(a + b) * g + beta ; also writes fp16 split of out
// ---------------------------------------------------------------------------
__global__ __launch_bounds__(256)
void add_ln_kernel(const float* __restrict__ a, const float* __restrict__ b2,
                   const float* __restrict__ g, const float* __restrict__ beta,
                   float* __restrict__ out,
                   __half* __restrict__ outh, __half* __restrict__ outl)
{
    const int row = blockIdx.x;
    const size_t off = (size_t)row * DD;
    const int t = threadIdx.x;
    __shared__ float r1[256], r2[256];

    float vloc[4];
    float s = 0.0f, s2 = 0.0f;
#pragma unroll
    for (int i = 0; i < 4; i++) {
        int d = t + i * 256;
        float vv = a[off + d] + b2[off + d];
        vloc[i] = vv;
        s += vv; s2 += vv * vv;
    }
    r1[t] = s; r2[t] = s2;
    __syncthreads();
    for (int o2 = 128; o2 > 0; o2 >>= 1) {
        if (t < o2) { r1[t] += r1[t + o2]; r2[t] += r2[t + o2]; }
        __syncthreads();
    }
    float mean = r1[0] * (1.0f / DD);
    float var  = r2[0] * (1.0f / DD) - mean * mean;
    float inv  = rsqrtf(var + 1e-5f);
#pragma unroll
    for (int i = 0; i < 4; i++) {
        int d = t + i * 256;
        float vv = (vloc[i] - mean) * inv * g[d] + beta[d];
        out[off + d] = vv;
        __half h, l;
        hsplit(vv, h, l);
        outh[off + d] = h;
        outl[off + d] = l;
    }
}

// ---------------------------------------------------------------------------
// s = sigmoid(feat @ Ws + bs); one warp per token
// ---------------------------------------------------------------------------
__global__ __launch_bounds__(256)
void score_kernel(const float* __restrict__ feat, const float* __restrict__ Ws,
                  const float* __restrict__ bs, float* __restrict__ sbuf)
{
    int token = blockIdx.x * 8 + (threadIdx.x >> 5);
    int lane  = threadIdx.x & 31;
    const float* f = feat + (size_t)token * DD;
    float acc = 0.0f;
    for (int i = lane; i < DD; i += 32) acc += f[i] * Ws[i];
#pragma unroll
    for (int m = 16; m; m >>= 1) acc += __shfl_xor_sync(0xffffffffu, acc, m);
    if (lane == 0) sbuf[token] = 1.0f / (1.0f + expf(-(acc + bs[0])));
}

// ---------------------------------------------------------------------------
// Per-batch inclusive scan of sv, floor -> segment ids, max over valid
// ---------------------------------------------------------------------------
__global__ __launch_bounds__(1024)
void scan_kernel(const float* __restrict__ sbuf, const float* __restrict__ masks,
                 float* __restrict__ svbuf, int* __restrict__ segbuf,
                 float* __restrict__ maxseg)
{
    const int b = blockIdx.x;
    const int t = threadIdx.x;
    __shared__ float sc[SS];
    __shared__ float mr[SS];

    float valid = masks[b * SS + t];
    float sv = (valid > 0.0f) ? sbuf[b * SS + t] : 0.0f;
    svbuf[b * SS + t] = sv;
    sc[t] = sv;
    __syncthreads();
    for (int off = 1; off < SS; off <<= 1) {
        float vprev = (t >= off) ? sc[t - off] : 0.0f;
        __syncthreads();
        sc[t] += vprev;
        __syncthreads();
    }
    float c = floorf(sc[t]);
    int seg = (int)c;
    seg = seg < 0 ? 0 : (seg > SS - 1 ? SS - 1 : seg);
    segbuf[b * SS + t] = seg;

    mr[t] = (valid > 0.0f) ? c : -1.0f;
    __syncthreads();
    for (int off = 512; off > 0; off >>= 1) {
        if (t < off) mr[t] = fmaxf(mr[t], mr[t + off]);
        __syncthreads();
    }
    if (t == 0) maxseg[b] = mr[0];
}

// ---------------------------------------------------------------------------
// pooled[b,g,:] = sum_{s: seg[b,s]==g} x[b,s,:]*sv[b,s] -> split fp16 output
// ---------------------------------------------------------------------------
__global__ __launch_bounds__(256)
void pool_kernel(const float* __restrict__ x, const float* __restrict__ svbuf,
                 const int* __restrict__ segbuf,
                 __half* __restrict__ ph, __half* __restrict__ pl)
{
    const int g = blockIdx.x;
    const int b = blockIdx.y;
    const int* seg = segbuf + b * SS;

    int lo = 0, hi = SS;
    while (lo < hi) { int mid = (lo + hi) >> 1; if (seg[mid] < g) lo = mid + 1; else hi = mid; }
    int beg = lo;
    lo = beg; hi = SS;
    while (lo < hi) { int mid = (lo + hi) >> 1; if (seg[mid] < g + 1) lo = mid + 1; else hi = mid; }
    int end = lo;

    const int t = threadIdx.x;
    float acc[4] = {0.0f, 0.0f, 0.0f, 0.0f};
    for (int s = beg; s < end; s++) {
        float w = svbuf[b * SS + s];
        const float* xr = x + ((size_t)b * SS + s) * DD;
#pragma unroll
        for (int i = 0; i < 4; i++) acc[i] += xr[t + i * 256] * w;
    }
    size_t rbase = ((size_t)b * SS + g) * DD;
#pragma unroll
    for (int i = 0; i < 4; i++) {
        __half h, l;
        hsplit(acc[i], h, l);
        ph[rbase + t + i * 256] = h;
        pl[rbase + t + i * 256] = l;
    }
}

// ---------------------------------------------------------------------------
// new_mask[b,s] = (s <= max_seg[b]) ? 1 : 0
// ---------------------------------------------------------------------------
__global__ __launch_bounds__(1024)
void mask_kernel(const float* __restrict__ maxseg, float* __restrict__ outmask)
{
    const int b = blockIdx.x;
    const int t = threadIdx.x;
    outmask[b * SS + t] = ((float)t <= maxseg[b]) ? 1.0f : 0.0f;
}

// ---------------------------------------------------------------------------
// Host side
// ---------------------------------------------------------------------------
static void* sym_addr(const void* sym) {
    void* p = nullptr;
    cudaGetSymbolAddress(&p, sym);
    return p;
}

static void launch_hgemm(const __half* Ah, const __half* Al,
                         const __half* Bh, const __half* Bl,
                         const float* bias, float* C,
                         __half* Ch, __half* Cl,
                         int M, int N, int K, int act, int out_split) {
    dim3 grid(N / 128, M / 128);
    hgemm_kernel<<<grid, 256, H_SMEM_BYTES>>>(Ah, Al, Bh, Bl, bias, C,
                                              Ch, Cl, M, N, K, act, out_split);
}

extern "C" void kernel_launch(void* const* d_in, const int* in_sizes, int n_in,
                              void* d_out, int out_size)
{
    (void)in_sizes; (void)n_in;
    const float* x     = (const float*)d_in[0];
    const float* masks = (const float*)d_in[1];
    const float* Wq  = (const float*)d_in[2];
    const float* bq  = (const float*)d_in[3];
    const float* Wk  = (const float*)d_in[4];
    const float* bk  = (const float*)d_in[5];
    const float* Wv  = (const float*)d_in[6];
    const float* bv  = (const float*)d_in[7];
    const float* Wo  = (const float*)d_in[8];
    const float* bo  = (const float*)d_in[9];
    const float* g1  = (const float*)d_in[10];
    const float* be1 = (const float*)d_in[11];
    const float* g2  = (const float*)d_in[12];
    const float* be2 = (const float*)d_in[13];
    const float* W1  = (const float*)d_in[14];
    const float* bf1 = (const float*)d_in[15];
    const float* W2  = (const float*)d_in[16];
    const float* bf2 = (const float*)d_in[17];
    const float* Ws  = (const float*)d_in[18];
    const float* bs  = (const float*)d_in[19];
    const float* P1  = (const float*)d_in[20];
    const float* bp1 = (const float*)d_in[21];
    const float* P2  = (const float*)d_in[22];
    const float* bp2 = (const float*)d_in[23];

    float* out = (float*)d_out;
    (void)out_size;

    cudaFuncSetAttribute(attn_mma_kernel,
                         cudaFuncAttributeMaxDynamicSharedMemorySize,
                         ATT_SMEM_BYTES);
    cudaFuncSetAttribute(hgemm_kernel,
                         cudaFuncAttributeMaxDynamicSharedMemorySize,
                         H_SMEM_BYTES);

    float* qkvb  = (float*)sym_addr(g_qkv);
    float* ob    = (float*)sym_addr(g_o);
    float* hb    = (float*)sym_addr(g_h);
    float* featb = (float*)sym_addr(g_feat);
    float* feat2b= (float*)sym_addr(g_feat2);
    float* sb    = (float*)sym_addr(g_s);
    float* svb   = (float*)sym_addr(g_sv);
    int*   segb  = (int*)sym_addr(g_seg);
    float* msb   = (float*)sym_addr(g_maxseg);
    float* bqkvb = (float*)sym_addr(g_bqkv);

    __half* xh  = (__half*)sym_addr(g_xh);
    __half* xl  = (__half*)sym_addr(g_xl);
    __half* fh  = (__half*)sym_addr(g_fh);
    __half* fl  = (__half*)sym_addr(g_fl);
    __half* ath = (__half*)sym_addr(g_ath);
    __half* atl = (__half*)sym_addr(g_atl);
    __half* hh  = (__half*)sym_addr(g_hh);
    __half* hl  = (__half*)sym_addr(g_hl);
    __half* ffh = (__half*)sym_addr(g_ffh);
    __half* ffl = (__half*)sym_addr(g_ffl);
    __half* plh = (__half*)sym_addr(g_plh);
    __half* pll = (__half*)sym_addr(g_pll);
    __half* phh = (__half*)sym_addr(g_phh);
    __half* phl = (__half*)sym_addr(g_phl);

    __half* wqkvh = (__half*)sym_addr(g_wqkvh);
    __half* wqkvl = (__half*)sym_addr(g_wqkvl);
    __half* woh = (__half*)sym_addr(g_woh);
    __half* wol = (__half*)sym_addr(g_wol);
    __half* w1h = (__half*)sym_addr(g_w1h);
    __half* w1l = (__half*)sym_addr(g_w1l);
    __half* w2h = (__half*)sym_addr(g_w2h);
    __half* w2l = (__half*)sym_addr(g_w2l);
    __half* p1h = (__half*)sym_addr(g_p1h);
    __half* p1l = (__half*)sym_addr(g_p1l);
    __half* p2h = (__half*)sym_addr(g_p2h);
    __half* p2l = (__half*)sym_addr(g_p2l);

    // ---- weight prep: transpose + x64 + fp16 split ----
    trans_split_h_kernel<<<dim3(DD / 32, DD / 32), 256>>>(Wq, wqkvh, wqkvl, DD, DD);
    trans_split_h_kernel<<<dim3(DD / 32, DD / 32), 256>>>(Wk, wqkvh + DD * DD,
                                                          wqkvl + DD * DD, DD, DD);
    trans_split_h_kernel<<<dim3(DD / 32, DD / 32), 256>>>(Wv, wqkvh + 2 * DD * DD,
                                                          wqkvl + 2 * DD * DD, DD, DD);
    trans_split_h_kernel<<<dim3(DD / 32, DD / 32), 256>>>(Wo, woh, wol, DD, DD);
    trans_split_h_kernel<<<dim3(FF / 32, DD / 32), 256>>>(W1, w1h, w1l, DD, FF);
    trans_split_h_kernel<<<dim3(DD / 32, FF / 32), 256>>>(W2, w2h, w2l, FF, DD);
    trans_split_h_kernel<<<dim3(HID / 32, DD / 32), 256>>>(P1, p1h, p1l, DD, HID);
    trans_split_h_kernel<<<dim3(HID / 32, HID / 32), 256>>>(P2, p2h, p2l, HID, HID);
    concat_bias_kernel<<<(QKVN + 255) / 256, 256>>>(bq, bk, bv, bqkvb);
    split_h_kernel<<<(TOK * DD + 255) / 256, 256>>>(x, xh, xl, TOK * DD);

    // ---- encoder layer, applied twice (fp16 2-split exact path) ----
    const __half* inh = xh;
    const __half* inl = xl;
    const float* enc_in = x;
    float* enc_out = featb;
    for (int pass = 0; pass < 2; pass++) {
        int mode = pass;
        launch_hgemm(inh, inl, wqkvh, wqkvl, bqkvb, qkvb, nullptr, nullptr,
                     TOK, QKVN, DD, 0, 0);
        attn_mma_kernel<<<dim3(SS / 64, BB * HH), 128, ATT_SMEM_BYTES>>>(
            qkvb, masks, mode, ath, atl);
        launch_hgemm(ath, atl, woh, wol, bo, ob, nullptr, nullptr,
                     TOK, DD, DD, 0, 0);
        add_ln_kernel<<<TOK, 256>>>(enc_in, ob, g1, be1, hb, hh, hl);
        launch_hgemm(hh, hl, w1h, w1l, bf1, nullptr, ffh, ffl,
                     TOK, FF, DD, 1, 1);                    // GELU, split out
        launch_hgemm(ffh, ffl, w2h, w2l, bf2, ob, nullptr, nullptr,
                     TOK, DD, FF, 0, 0);
        add_ln_kernel<<<TOK, 256>>>(hb, ob, g2, be2, enc_out, fh, fl);
        enc_in = featb;
        enc_out = feat2b;
        inh = fh; inl = fl;
    }

    // ---- importance scores, cumsum segmentation ----
    score_kernel<<<TOK / 8, 256>>>(feat2b, Ws, bs, sb);
    scan_kernel<<<BB, 1024>>>(sb, masks, svb, segb, msb);

    // ---- weighted segment-sum pooling of original x (split fp16 output) ----
    pool_kernel<<<dim3(SS, BB), 256>>>(x, svb, segb, plh, pll);

    // ---- projector on fp16-split tensor cores ----
    launch_hgemm(plh, pll, p1h, p1l, bp1, nullptr, phh, phl,
                 TOK, HID, DD, 1, 1);                       // GELU, split out
    launch_hgemm(phh, phl, p2h, p2l, bp2, out, nullptr, nullptr,
                 TOK, HID, HID, 0, 0);                      // fp32 out

    // ---- new_mask appended after the [B,S,HID] output ----
    mask_kernel<<<BB, 1024>>>(msb, out + (size_t)TOK * HID);
}

// round 8
// speedup vs baseline: 1.2123x; 1.0424x over previous
#include <cuda_runtime.h>
#include <cuda_fp16.h>
#include <cstdint>
#include <math.h>

// ---------------------------------------------------------------------------
// Problem constants
// ---------------------------------------------------------------------------
#define BB 4
#define SS 1024
#define DD 1024
#define HH 16
#define HDIM 64
#define FF 2048
#define HID 4096
#define TOK (BB*SS)          // 4096 tokens
#define QKVN 3072
#define WSCALE (1.0f/64.0f)  // weights pre-scaled by 64 (fp16 subnormal guard)

// ---------------------------------------------------------------------------
// Scratch (__device__ globals; no allocation allowed)
// ---------------------------------------------------------------------------
__device__ float g_o   [TOK*DD];
__device__ float g_h   [TOK*DD];
__device__ float g_feat[TOK*DD];
__device__ float g_feat2[TOK*DD];
__device__ float g_s   [TOK];
__device__ float g_sv  [TOK];
__device__ int   g_seg [TOK];
__device__ float g_maxseg[BB];
__device__ float g_bqkv[QKVN];

// fp16 split activations
__device__ __half g_qkvh[TOK*QKVN], g_qkvl[TOK*QKVN];
__device__ __half g_xh[TOK*DD],    g_xl[TOK*DD];
__device__ __half g_fh[TOK*DD],    g_fl[TOK*DD];     // feat / feat2 split
__device__ __half g_ath[TOK*DD],   g_atl[TOK*DD];    // attention out split
__device__ __half g_hh[TOK*DD],    g_hl[TOK*DD];     // h split
__device__ __half g_ffh[TOK*FF],   g_ffl[TOK*FF];    // ffn mid split
__device__ __half g_plh[TOK*DD],   g_pll[TOK*DD];    // pooled split
__device__ __half g_phh[TOK*HID],  g_phl[TOK*HID];   // projector mid split

// fp16 split weights [N,K] K-contiguous, pre-scaled x64
__device__ __half g_wqkvh[QKVN*DD], g_wqkvl[QKVN*DD];
__device__ __half g_woh[DD*DD],     g_wol[DD*DD];
__device__ __half g_w1h[FF*DD],     g_w1l[FF*DD];
__device__ __half g_w2h[DD*FF],     g_w2l[DD*FF];
__device__ __half g_p1h[HID*DD],    g_p1l[HID*DD];
__device__ __half g_p2h[HID*HID],   g_p2l[HID*HID];

// ---------------------------------------------------------------------------
// Helpers
// ---------------------------------------------------------------------------
__device__ __forceinline__ float gelu_f(float x) {
    return 0.5f * x * (1.0f + erff(x * 0.70710678118654752440f));
}

__device__ __forceinline__ void cp16(uint32_t dst, const void* src) {
    asm volatile("cp.async.cg.shared.global [%0], [%1], 16;\n"
                 :: "r"(dst), "l"(src));
}

__device__ __forceinline__ uint32_t smem_u32(const void* p) {
    uint32_t a;
    asm("{ .reg .u64 t; cvta.to.shared.u64 t, %1; cvt.u32.u64 %0, t; }"
        : "=r"(a) : "l"(p));
    return a;
}

// mma.sync m16n8k16 f16 with f32 accumulate
__device__ __forceinline__ void mma_f16(float* c,
                                        uint32_t a0, uint32_t a1,
                                        uint32_t a2, uint32_t a3,
                                        uint32_t b0, uint32_t b1) {
    asm volatile(
        "mma.sync.aligned.m16n8k16.row.col.f32.f16.f16.f32 "
        "{%0,%1,%2,%3}, {%4,%5,%6,%7}, {%8,%9}, {%0,%1,%2,%3};\n"
        : "+f"(c[0]), "+f"(c[1]), "+f"(c[2]), "+f"(c[3])
        : "r"(a0), "r"(a1), "r"(a2), "r"(a3), "r"(b0), "r"(b1));
}

__device__ __forceinline__ void hsplit(float v, __half& h, __half& l) {
    h = __float2half(v);
    l = __float2half(v - __half2float(h));
}

__device__ __forceinline__ uint32_t hpack(__half a, __half b) {
    __half2 t = __halves2half2(a, b);
    return *reinterpret_cast<uint32_t*>(&t);
}

// ---------------------------------------------------------------------------
// fp16 2-split 3-combo GEMM (fp32-grade accuracy)
// C[M,N] = act((A @ Bt^T) * WSCALE + bias[N]),  A = Ah+Al, Bt = Bh+Bl
// out_split=1: write split fp16 (Ch, Cl) instead of fp32 C.
// ---------------------------------------------------------------------------
#define HS 40
#define H_STAGE_HALVES 20480          // 4 arrays * 128*40
#define H_SMEM_BYTES  (2 * H_STAGE_HALVES * 2)

__global__ __launch_bounds__(256)
void hgemm_kernel(const __half* __restrict__ Ah, const __half* __restrict__ Al,
                  const __half* __restrict__ Bh, const __half* __restrict__ Bl,
                  const float* __restrict__ bias, float* __restrict__ C,
                  __half* __restrict__ Ch, __half* __restrict__ Cl,
                  int M, int N, int K, int act, int out_split)
{
    extern __shared__ __half hsm[];
    const int tid  = threadIdx.x;
    const int wid  = tid >> 5;
    const int lane = tid & 31;
    const int gr   = lane >> 2;
    const int gc   = lane & 3;
    const int row0 = blockIdx.y * 128;
    const int col0 = blockIdx.x * 128;
    const int warp_m = (wid & 3) * 32;
    const int warp_n = (wid >> 2) * 64;
    const uint32_t sbase = smem_u32(hsm);

    float acc[2][8][4];
#pragma unroll
    for (int i = 0; i < 2; i++)
#pragma unroll
        for (int j = 0; j < 8; j++)
#pragma unroll
            for (int r = 0; r < 4; r++) acc[i][j][r] = 0.0f;

    const int nk = K >> 5;
    const int c0i = tid * 2, c1i = tid * 2 + 1;
    const int m0 = c0i >> 2, kc0 = (c0i & 3) * 8;
    const int m1 = c1i >> 2, kc1 = (c1i & 3) * 8;

#define H_LOAD_STAGE(st, k0)                                                     \
    do {                                                                         \
        uint32_t b = sbase + (uint32_t)(st) * H_STAGE_HALVES * 2u;               \
        cp16(b + (uint32_t)(m0 * HS + kc0) * 2u,                                 \
             Ah + (size_t)(row0 + m0) * K + (k0) + kc0);                         \
        cp16(b + (uint32_t)(m1 * HS + kc1) * 2u,                                 \
             Ah + (size_t)(row0 + m1) * K + (k0) + kc1);                         \
        cp16(b + (uint32_t)(5120 + m0 * HS + kc0) * 2u,                          \
             Al + (size_t)(row0 + m0) * K + (k0) + kc0);                         \
        cp16(b + (uint32_t)(5120 + m1 * HS + kc1) * 2u,                          \
             Al + (size_t)(row0 + m1) * K + (k0) + kc1);                         \
        cp16(b + (uint32_t)(10240 + m0 * HS + kc0) * 2u,                         \
             Bh + (size_t)(col0 + m0) * K + (k0) + kc0);                         \
        cp16(b + (uint32_t)(10240 + m1 * HS + kc1) * 2u,                         \
             Bh + (size_t)(col0 + m1) * K + (k0) + kc1);                         \
        cp16(b + (uint32_t)(15360 + m0 * HS + kc0) * 2u,                         \
             Bl + (size_t)(col0 + m0) * K + (k0) + kc0);                         \
        cp16(b + (uint32_t)(15360 + m1 * HS + kc1) * 2u,                         \
             Bl + (size_t)(col0 + m1) * K + (k0) + kc1);                         \
        asm volatile("cp.async.commit_group;\n");                                \
    } while (0)

    H_LOAD_STAGE(0, 0);

    for (int t = 0; t < nk; t++) {
        const int st = t & 1;
        if (t + 1 < nk) {
            H_LOAD_STAGE((t + 1) & 1, (t + 1) << 5);
            asm volatile("cp.async.wait_group 1;\n");
        } else {
            asm volatile("cp.async.wait_group 0;\n");
        }
        __syncthreads();

        const __half* s = hsm + st * H_STAGE_HALVES;

#pragma unroll
        for (int ks = 0; ks < 2; ks++) {
            const int kh = ks * 16;
            uint32_t ahf[2][4], alf[2][4];
#pragma unroll
            for (int mt = 0; mt < 2; mt++) {
                int r = warp_m + mt * 16 + gr;
                ahf[mt][0] = *(const uint32_t*)(s + r * HS + kh + 2 * gc);
                ahf[mt][1] = *(const uint32_t*)(s + (r + 8) * HS + kh + 2 * gc);
                ahf[mt][2] = *(const uint32_t*)(s + r * HS + kh + 8 + 2 * gc);
                ahf[mt][3] = *(const uint32_t*)(s + (r + 8) * HS + kh + 8 + 2 * gc);
                alf[mt][0] = *(const uint32_t*)(s + 5120 + r * HS + kh + 2 * gc);
                alf[mt][1] = *(const uint32_t*)(s + 5120 + (r + 8) * HS + kh + 2 * gc);
                alf[mt][2] = *(const uint32_t*)(s + 5120 + r * HS + kh + 8 + 2 * gc);
                alf[mt][3] = *(const uint32_t*)(s + 5120 + (r + 8) * HS + kh + 8 + 2 * gc);
            }
#pragma unroll
            for (int nt = 0; nt < 8; nt++) {
                int r = warp_n + nt * 8 + gr;
                uint32_t bh0 = *(const uint32_t*)(s + 10240 + r * HS + kh + 2 * gc);
                uint32_t bh1 = *(const uint32_t*)(s + 10240 + r * HS + kh + 8 + 2 * gc);
                uint32_t bl0 = *(const uint32_t*)(s + 15360 + r * HS + kh + 2 * gc);
                uint32_t bl1 = *(const uint32_t*)(s + 15360 + r * HS + kh + 8 + 2 * gc);
#pragma unroll
                for (int mt = 0; mt < 2; mt++) {
                    float* c = acc[mt][nt];
                    mma_f16(c, ahf[mt][0], ahf[mt][1], ahf[mt][2], ahf[mt][3], bh0, bh1);
                    mma_f16(c, ahf[mt][0], ahf[mt][1], ahf[mt][2], ahf[mt][3], bl0, bl1);
                    mma_f16(c, alf[mt][0], alf[mt][1], alf[mt][2], alf[mt][3], bh0, bh1);
                }
            }
        }
        __syncthreads();
    }

#pragma unroll
    for (int mt = 0; mt < 2; mt++) {
        const int r0 = row0 + warp_m + mt * 16 + gr;
#pragma unroll
        for (int nt = 0; nt < 8; nt++) {
            const int cc = col0 + warp_n + nt * 8 + 2 * gc;
            float b0v = bias[cc], b1v = bias[cc + 1];
            float v0 = acc[mt][nt][0] * WSCALE + b0v;
            float v1 = acc[mt][nt][1] * WSCALE + b1v;
            float v2 = acc[mt][nt][2] * WSCALE + b0v;
            float v3 = acc[mt][nt][3] * WSCALE + b1v;
            if (act == 1) {
                v0 = gelu_f(v0); v1 = gelu_f(v1);
                v2 = gelu_f(v2); v3 = gelu_f(v3);
            }
            if (!out_split) {
                *(float2*)(C + (size_t)r0 * N + cc)       = make_float2(v0, v1);
                *(float2*)(C + (size_t)(r0 + 8) * N + cc) = make_float2(v2, v3);
            } else {
                __half h0, l0, h1, l1;
                hsplit(v0, h0, l0); hsplit(v1, h1, l1);
                *(__half2*)(Ch + (size_t)r0 * N + cc) = __halves2half2(h0, h1);
                *(__half2*)(Cl + (size_t)r0 * N + cc) = __halves2half2(l0, l1);
                hsplit(v2, h0, l0); hsplit(v3, h1, l1);
                *(__half2*)(Ch + (size_t)(r0 + 8) * N + cc) = __halves2half2(h0, h1);
                *(__half2*)(Cl + (size_t)(r0 + 8) * N + cc) = __halves2half2(l0, l1);
            }
        }
    }
}

// ---------------------------------------------------------------------------
// Tensor-core flash attention on fp16-split operands (3-combo, m16n8k16).
// 64-q tile, 128 threads (4 warps x 16 queries). QKV input pre-split fp16.
// Row stride 72 halves: fragment loads conflict-free (4*gr+gc mod 32).
// Scores scaled by 0.125 post-MMA (exact).
// ---------------------------------------------------------------------------
#define HST 72
#define ATT_SMEM_BYTES (8 * 64 * HST * 2 + 64 * 4)

__global__ __launch_bounds__(128)
void attn_mma_kernel(const __half* __restrict__ qkvh, const __half* __restrict__ qkvl,
                     const float* __restrict__ masks,
                     int mode, __half* __restrict__ oh, __half* __restrict__ ol)
{
    extern __shared__ __half hs[];
    __half* Qh  = hs;
    __half* Ql  = Qh  + 64 * HST;
    __half* Kh  = Ql  + 64 * HST;
    __half* Kl  = Kh  + 64 * HST;
    __half* Vh  = Kl  + 64 * HST;
    __half* Vl  = Vh  + 64 * HST;
    __half* Psh = Vl  + 64 * HST;
    __half* Psl = Psh + 64 * HST;
    float*  mb  = (float*)(Psl + 64 * HST);

    const uint32_t sQh = smem_u32(Qh), sQl = smem_u32(Ql);
    const uint32_t sKh = smem_u32(Kh), sKl = smem_u32(Kl);
    const uint32_t sVh = smem_u32(Vh), sVl = smem_u32(Vl);

    const int tid  = threadIdx.x;
    const int wid  = tid >> 5;
    const int lane = tid & 31;
    const int gr   = lane >> 2;
    const int gc   = lane & 3;
    const int q0   = blockIdx.x * 64;
    const int b    = blockIdx.y >> 4;
    const int h    = blockIdx.y & 15;
    const size_t qbase = (size_t)b * SS * QKVN + (size_t)h * HDIM;
    const size_t obase = (size_t)b * SS * DD + (size_t)h * HDIM;
    const int q0w = wid * 16;

    // load Q tile (64 rows x 64 halves, h+l)
    for (int idx = tid; idx < 512; idx += 128) {
        int r = idx >> 3, c8 = (idx & 7) << 3;
        uint32_t soff = (uint32_t)(r * HST + c8) * 2u;
        cp16(sQh + soff, qkvh + qbase + (size_t)(q0 + r) * QKVN + c8);
        cp16(sQl + soff, qkvl + qbase + (size_t)(q0 + r) * QKVN + c8);
    }
    asm volatile("cp.async.commit_group;\n");

    float mrow[2] = {-1e30f, -1e30f};
    float lrow[2] = {0.0f, 0.0f};
    float Oacc[8][4];
#pragma unroll
    for (int i = 0; i < 8; i++)
#pragma unroll
        for (int j = 0; j < 4; j++) Oacc[i][j] = 0.0f;

    for (int t = 0; t < 16; t++) {
        const int k0 = t * 64;
        for (int idx = tid; idx < 512; idx += 128) {
            int r = idx >> 3, c8 = (idx & 7) << 3;
            uint32_t soff = (uint32_t)(r * HST + c8) * 2u;
            size_t kg = qbase + 1024 + (size_t)(k0 + r) * QKVN + c8;
            size_t vg = qbase + 2048 + (size_t)(k0 + r) * QKVN + c8;
            cp16(sKh + soff, qkvh + kg);
            cp16(sKl + soff, qkvl + kg);
            cp16(sVh + soff, qkvh + vg);
            cp16(sVl + soff, qkvl + vg);
        }
        asm volatile("cp.async.commit_group;\n");
        if (tid < 64) {
            float mv = masks[b * SS + k0 + tid];
            mb[tid] = (mode == 0) ? mv : (mv > 0.0f ? 0.0f : -1e9f);
        }
        asm volatile("cp.async.wait_group 0;\n");
        __syncthreads();

        // ---- scores: S(16q x 64k) = Q @ K^T (3-combo fp16)
        float S[8][4];
#pragma unroll
        for (int i = 0; i < 8; i++)
#pragma unroll
            for (int j = 0; j < 4; j++) S[i][j] = 0.0f;

#pragma unroll
        for (int kh = 0; kh < 64; kh += 16) {
            uint32_t qhf[4], qlf[4];
            {
                int base = (q0w + gr) * HST + kh + 2 * gc;
                qhf[0] = *(const uint32_t*)(Qh + base);
                qhf[1] = *(const uint32_t*)(Qh + base + 8 * HST);
                qhf[2] = *(const uint32_t*)(Qh + base + 8);
                qhf[3] = *(const uint32_t*)(Qh + base + 8 * HST + 8);
                qlf[0] = *(const uint32_t*)(Ql + base);
                qlf[1] = *(const uint32_t*)(Ql + base + 8 * HST);
                qlf[2] = *(const uint32_t*)(Ql + base + 8);
                qlf[3] = *(const uint32_t*)(Ql + base + 8 * HST + 8);
            }
#pragma unroll
            for (int nt = 0; nt < 8; nt++) {
                int bb = (nt * 8 + gr) * HST + kh + 2 * gc;
                uint32_t kh0 = *(const uint32_t*)(Kh + bb);
                uint32_t kh1 = *(const uint32_t*)(Kh + bb + 8);
                uint32_t kl0 = *(const uint32_t*)(Kl + bb);
                uint32_t kl1 = *(const uint32_t*)(Kl + bb + 8);
                mma_f16(S[nt], qhf[0], qhf[1], qhf[2], qhf[3], kh0, kh1);
                mma_f16(S[nt], qhf[0], qhf[1], qhf[2], qhf[3], kl0, kl1);
                mma_f16(S[nt], qlf[0], qlf[1], qlf[2], qlf[3], kh0, kh1);
            }
        }

        // ---- scale + bias + online softmax
        float rmax[2] = {-1e30f, -1e30f};
#pragma unroll
        for (int nt = 0; nt < 8; nt++) {
            float m0 = mb[nt * 8 + 2 * gc];
            float m1 = mb[nt * 8 + 2 * gc + 1];
            S[nt][0] = S[nt][0] * 0.125f + m0;
            S[nt][1] = S[nt][1] * 0.125f + m1;
            S[nt][2] = S[nt][2] * 0.125f + m0;
            S[nt][3] = S[nt][3] * 0.125f + m1;
            rmax[0] = fmaxf(rmax[0], fmaxf(S[nt][0], S[nt][1]));
            rmax[1] = fmaxf(rmax[1], fmaxf(S[nt][2], S[nt][3]));
        }
#pragma unroll
        for (int sh = 1; sh < 4; sh <<= 1) {
            rmax[0] = fmaxf(rmax[0], __shfl_xor_sync(0xffffffffu, rmax[0], sh));
            rmax[1] = fmaxf(rmax[1], __shfl_xor_sync(0xffffffffu, rmax[1], sh));
        }
        float mnew0 = fmaxf(mrow[0], rmax[0]);
        float mnew1 = fmaxf(mrow[1], rmax[1]);
        float scl0 = __expf(mrow[0] - mnew0);
        float scl1 = __expf(mrow[1] - mnew1);
        float rsum[2] = {0.0f, 0.0f};
#pragma unroll
        for (int nt = 0; nt < 8; nt++) {
            S[nt][0] = __expf(S[nt][0] - mnew0);
            S[nt][1] = __expf(S[nt][1] - mnew0);
            S[nt][2] = __expf(S[nt][2] - mnew1);
            S[nt][3] = __expf(S[nt][3] - mnew1);
            rsum[0] += S[nt][0] + S[nt][1];
            rsum[1] += S[nt][2] + S[nt][3];
        }
#pragma unroll
        for (int sh = 1; sh < 4; sh <<= 1) {
            rsum[0] += __shfl_xor_sync(0xffffffffu, rsum[0], sh);
            rsum[1] += __shfl_xor_sync(0xffffffffu, rsum[1], sh);
        }
        lrow[0] = lrow[0] * scl0 + rsum[0];
        lrow[1] = lrow[1] * scl1 + rsum[1];
        mrow[0] = mnew0; mrow[1] = mnew1;
#pragma unroll
        for (int dt = 0; dt < 8; dt++) {
            Oacc[dt][0] *= scl0; Oacc[dt][1] *= scl0;
            Oacc[dt][2] *= scl1; Oacc[dt][3] *= scl1;
        }

        // ---- stage P split to smem (per-warp private rows)
        __syncwarp();
#pragma unroll
        for (int nt = 0; nt < 8; nt++) {
            int c0 = nt * 8 + 2 * gc;
            __half h0, l0, h1, l1;
            hsplit(S[nt][0], h0, l0); hsplit(S[nt][1], h1, l1);
            *(__half2*)(Psh + (q0w + gr) * HST + c0) = __halves2half2(h0, h1);
            *(__half2*)(Psl + (q0w + gr) * HST + c0) = __halves2half2(l0, l1);
            hsplit(S[nt][2], h0, l0); hsplit(S[nt][3], h1, l1);
            *(__half2*)(Psh + (q0w + gr + 8) * HST + c0) = __halves2half2(h0, h1);
            *(__half2*)(Psl + (q0w + gr + 8) * HST + c0) = __halves2half2(l0, l1);
        }
        __syncwarp();

        // ---- O += P @ V (3-combo fp16; V fragments pair-assembled)
#pragma unroll
        for (int kh = 0; kh < 64; kh += 16) {
            uint32_t phf[4], plf[4];
            {
                int base = (q0w + gr) * HST + kh + 2 * gc;
                phf[0] = *(const uint32_t*)(Psh + base);
                phf[1] = *(const uint32_t*)(Psh + base + 8 * HST);
                phf[2] = *(const uint32_t*)(Psh + base + 8);
                phf[3] = *(const uint32_t*)(Psh + base + 8 * HST + 8);
                plf[0] = *(const uint32_t*)(Psl + base);
                plf[1] = *(const uint32_t*)(Psl + base + 8 * HST);
                plf[2] = *(const uint32_t*)(Psl + base + 8);
                plf[3] = *(const uint32_t*)(Psl + base + 8 * HST + 8);
            }
            const int ka = kh + 2 * gc;
#pragma unroll
            for (int dt = 0; dt < 8; dt++) {
                int d = dt * 8 + gr;
                uint32_t vh0 = hpack(Vh[ka * HST + d],       Vh[(ka + 1) * HST + d]);
                uint32_t vh1 = hpack(Vh[(ka + 8) * HST + d], Vh[(ka + 9) * HST + d]);
                uint32_t vl0 = hpack(Vl[ka * HST + d],       Vl[(ka + 1) * HST + d]);
                uint32_t vl1 = hpack(Vl[(ka + 8) * HST + d], Vl[(ka + 9) * HST + d]);
                mma_f16(Oacc[dt], phf[0], phf[1], phf[2], phf[3], vh0, vh1);
                mma_f16(Oacc[dt], phf[0], phf[1], phf[2], phf[3], vl0, vl1);
                mma_f16(Oacc[dt], plf[0], plf[1], plf[2], plf[3], vh0, vh1);
            }
        }
        __syncthreads();   // all warps done with K/V before next tile load
    }

    // ---- normalize + fp16-split store
    float inv0 = 1.0f / lrow[0];
    float inv1 = 1.0f / lrow[1];
    const int r0 = q0 + q0w + gr;
#pragma unroll
    for (int dt = 0; dt < 8; dt++) {
        int col = dt * 8 + 2 * gc;
        __half h0, l0, h1, l1;
        hsplit(Oacc[dt][0] * inv0, h0, l0);
        hsplit(Oacc[dt][1] * inv0, h1, l1);
        *(__half2*)(oh + obase + (size_t)r0 * DD + col) = __halves2half2(h0, h1);
        *(__half2*)(ol + obase + (size_t)r0 * DD + col) = __halves2half2(l0, l1);
        hsplit(Oacc[dt][2] * inv1, h0, l0);
        hsplit(Oacc[dt][3] * inv1, h1, l1);
        *(__half2*)(oh + obase + (size_t)(r0 + 8) * DD + col) = __halves2half2(h0, h1);
        *(__half2*)(ol + obase + (size_t)(r0 + 8) * DD + col) = __halves2half2(l0, l1);
    }
}

// ---------------------------------------------------------------------------
// Transpose + scale x64 + fp16 split: Wh/Wl[n,k] = split(64 * W[k,n])
// ---------------------------------------------------------------------------
__global__ __launch_bounds__(256)
void trans_split_h_kernel(const float* __restrict__ W,
                          __half* __restrict__ Wh, __half* __restrict__ Wl,
                          int Kd, int Nd)
{
    __shared__ float t[32][33];
    const int n0 = blockIdx.x * 32, k0 = blockIdx.y * 32;
    const int tx = threadIdx.x & 31, ty = threadIdx.x >> 5;
#pragma unroll
    for (int r = ty; r < 32; r += 8)
        t[r][tx] = W[(size_t)(k0 + r) * Nd + n0 + tx];
    __syncthreads();
#pragma unroll
    for (int r = ty; r < 32; r += 8) {
        float v = t[tx][r] * 64.0f;
        __half h, l;
        hsplit(v, h, l);
        Wh[(size_t)(n0 + r) * Kd + k0 + tx] = h;
        Wl[(size_t)(n0 + r) * Kd + k0 + tx] = l;
    }
}

// ---------------------------------------------------------------------------
// Elementwise fp16 split of an fp32 array
// ---------------------------------------------------------------------------
__global__ __launch_bounds__(256)
void split_h_kernel(const float* __restrict__ a, __half* __restrict__ ah,
                    __half* __restrict__ al, int n)
{
    int i = blockIdx.x * 256 + threadIdx.x;
    if (i < n) {
        __half h, l;
        hsplit(a[i], h, l);
        ah[i] = h; al[i] = l;
    }
}

// ---------------------------------------------------------------------------
// concat bias [bq|bk|bv] -> bqkv
// ---------------------------------------------------------------------------
__global__ __launch_bounds__(256)
void concat_bias_kernel(const float* __restrict__ bq, const float* __restrict__ bk,
                        const float* __restrict__ bv, float* __restrict__ bqkv)
{
    int i = blockIdx.x * 256 + threadIdx.x;
    if (i < QKVN) {
        float v = (i < 1024) ? bq[i] : ((i < 2048) ? bk[i - 1024] : bv[i - 2048]);
        bqkv[i] = v;
    }
}

// ---------------------------------------------------------------------------
// out = LayerNorm(a + b) * g + beta ; also writes fp16 split of out
// ---------------------------------------------------------------------------
__global__ __launch_bounds__(256)
void add_ln_kernel(const float* __restrict__ a, const float* __restrict__ b2,
                   const float* __restrict__ g, const float* __restrict__ beta,
                   float* __restrict__ out,
                   __half* __restrict__ outh, __half* __restrict__ outl)
{
    const int row = blockIdx.x;
    const size_t off = (size_t)row * DD;
    const int t = threadIdx.x;
    __shared__ float r1[256], r2[256];

    float vloc[4];
    float s = 0.0f, s2 = 0.0f;
#pragma unroll
    for (int i = 0; i < 4; i++) {
        int d = t + i * 256;
        float vv = a[off + d] + b2[off + d];
        vloc[i] = vv;
        s += vv; s2 += vv * vv;
    }
    r1[t] = s; r2[t] = s2;
    __syncthreads();
    for (int o2 = 128; o2 > 0; o2 >>= 1) {
        if (t < o2) { r1[t] += r1[t + o2]; r2[t] += r2[t + o2]; }
        __syncthreads();
    }
    float mean = r1[0] * (1.0f / DD);
    float var  = r2[0] * (1.0f / DD) - mean * mean;
    float inv  = rsqrtf(var + 1e-5f);
#pragma unroll
    for (int i = 0; i < 4; i++) {
        int d = t + i * 256;
        float vv = (vloc[i] - mean) * inv * g[d] + beta[d];
        out[off + d] = vv;
        __half h, l;
        hsplit(vv, h, l);
        outh[off + d] = h;
        outl[off + d] = l;
    }
}

// ---------------------------------------------------------------------------
// s = sigmoid(feat @ Ws + bs); one warp per token
// ---------------------------------------------------------------------------
__global__ __launch_bounds__(256)
void score_kernel(const float* __restrict__ feat, const float* __restrict__ Ws,
                  const float* __restrict__ bs, float* __restrict__ sbuf)
{
    int token = blockIdx.x * 8 + (threadIdx.x >> 5);
    int lane  = threadIdx.x & 31;
    const float* f = feat + (size_t)token * DD;
    float acc = 0.0f;
    for (int i = lane; i < DD; i += 32) acc += f[i] * Ws[i];
#pragma unroll
    for (int m = 16; m; m >>= 1) acc += __shfl_xor_sync(0xffffffffu, acc, m);
    if (lane == 0) sbuf[token] = 1.0f / (1.0f + expf(-(acc + bs[0])));
}

// ---------------------------------------------------------------------------
// Per-batch inclusive scan of sv, floor -> segment ids, max over valid
// ---------------------------------------------------------------------------
__global__ __launch_bounds__(1024)
void scan_kernel(const float* __restrict__ sbuf, const float* __restrict__ masks,
                 float* __restrict__ svbuf, int* __restrict__ segbuf,
                 float* __restrict__ maxseg)
{
    const int b = blockIdx.x;
    const int t = threadIdx.x;
    __shared__ float sc[SS];
    __shared__ float mr[SS];

    float valid = masks[b * SS + t];
    float sv = (valid > 0.0f) ? sbuf[b * SS + t] : 0.0f;
    svbuf[b * SS + t] = sv;
    sc[t] = sv;
    __syncthreads();
    for (int off = 1; off < SS; off <<= 1) {
        float vprev = (t >= off) ? sc[t - off] : 0.0f;
        __syncthreads();
        sc[t] += vprev;
        __syncthreads();
    }
    float c = floorf(sc[t]);
    int seg = (int)c;
    seg = seg < 0 ? 0 : (seg > SS - 1 ? SS - 1 : seg);
    segbuf[b * SS + t] = seg;

    mr[t] = (valid > 0.0f) ? c : -1.0f;
    __syncthreads();
    for (int off = 512; off > 0; off >>= 1) {
        if (t < off) mr[t] = fmaxf(mr[t], mr[t + off]);
        __syncthreads();
    }
    if (t == 0) maxseg[b] = mr[0];
}

// ---------------------------------------------------------------------------
// pooled[b,g,:] = sum_{s: seg[b,s]==g} x[b,s,:]*sv[b,s] -> split fp16 output
// ---------------------------------------------------------------------------
__global__ __launch_bounds__(256)
void pool_kernel(const float* __restrict__ x, const float* __restrict__ svbuf,
                 const int* __restrict__ segbuf,
                 __half* __restrict__ ph, __half* __restrict__ pl)
{
    const int g = blockIdx.x;
    const int b = blockIdx.y;
    const int* seg = segbuf + b * SS;

    int lo = 0, hi = SS;
    while (lo < hi) { int mid = (lo + hi) >> 1; if (seg[mid] < g) lo = mid + 1; else hi = mid; }
    int beg = lo;
    lo = beg; hi = SS;
    while (lo < hi) { int mid = (lo + hi) >> 1; if (seg[mid] < g + 1) lo = mid + 1; else hi = mid; }
    int end = lo;

    const int t = threadIdx.x;
    float acc[4] = {0.0f, 0.0f, 0.0f, 0.0f};
    for (int s = beg; s < end; s++) {
        float w = svbuf[b * SS + s];
        const float* xr = x + ((size_t)b * SS + s) * DD;
#pragma unroll
        for (int i = 0; i < 4; i++) acc[i] += xr[t + i * 256] * w;
    }
    size_t rbase = ((size_t)b * SS + g) * DD;
#pragma unroll
    for (int i = 0; i < 4; i++) {
        __half h, l;
        hsplit(acc[i], h, l);
        ph[rbase + t + i * 256] = h;
        pl[rbase + t + i * 256] = l;
    }
}

// ---------------------------------------------------------------------------
// new_mask[b,s] = (s <= max_seg[b]) ? 1 : 0
// ---------------------------------------------------------------------------
__global__ __launch_bounds__(1024)
void mask_kernel(const float* __restrict__ maxseg, float* __restrict__ outmask)
{
    const int b = blockIdx.x;
    const int t = threadIdx.x;
    outmask[b * SS + t] = ((float)t <= maxseg[b]) ? 1.0f : 0.0f;
}

// ---------------------------------------------------------------------------
// Host side
// ---------------------------------------------------------------------------
static void* sym_addr(const void* sym) {
    void* p = nullptr;
    cudaGetSymbolAddress(&p, sym);
    return p;
}

static void launch_hgemm(const __half* Ah, const __half* Al,
                         const __half* Bh, const __half* Bl,
                         const float* bias, float* C,
                         __half* Ch, __half* Cl,
                         int M, int N, int K, int act, int out_split) {
    dim3 grid(N / 128, M / 128);
    hgemm_kernel<<<grid, 256, H_SMEM_BYTES>>>(Ah, Al, Bh, Bl, bias, C,
                                              Ch, Cl, M, N, K, act, out_split);
}

extern "C" void kernel_launch(void* const* d_in, const int* in_sizes, int n_in,
                              void* d_out, int out_size)
{
    (void)in_sizes; (void)n_in;
    const float* x     = (const float*)d_in[0];
    const float* masks = (const float*)d_in[1];
    const float* Wq  = (const float*)d_in[2];
    const float* bq  = (const float*)d_in[3];
    const float* Wk  = (const float*)d_in[4];
    const float* bk  = (const float*)d_in[5];
    const float* Wv  = (const float*)d_in[6];
    const float* bv  = (const float*)d_in[7];
    const float* Wo  = (const float*)d_in[8];
    const float* bo  = (const float*)d_in[9];
    const float* g1  = (const float*)d_in[10];
    const float* be1 = (const float*)d_in[11];
    const float* g2  = (const float*)d_in[12];
    const float* be2 = (const float*)d_in[13];
    const float* W1  = (const float*)d_in[14];
    const float* bf1 = (const float*)d_in[15];
    const float* W2  = (const float*)d_in[16];
    const float* bf2 = (const float*)d_in[17];
    const float* Ws  = (const float*)d_in[18];
    const float* bs  = (const float*)d_in[19];
    const float* P1  = (const float*)d_in[20];
    const float* bp1 = (const float*)d_in[21];
    const float* P2  = (const float*)d_in[22];
    const float* bp2 = (const float*)d_in[23];

    float* out = (float*)d_out;
    (void)out_size;

    cudaFuncSetAttribute(attn_mma_kernel,
                         cudaFuncAttributeMaxDynamicSharedMemorySize,
                         ATT_SMEM_BYTES);
    cudaFuncSetAttribute(hgemm_kernel,
                         cudaFuncAttributeMaxDynamicSharedMemorySize,
                         H_SMEM_BYTES);

    float* ob    = (float*)sym_addr(g_o);
    float* hb    = (float*)sym_addr(g_h);
    float* featb = (float*)sym_addr(g_feat);
    float* feat2b= (float*)sym_addr(g_feat2);
    float* sb    = (float*)sym_addr(g_s);
    float* svb   = (float*)sym_addr(g_sv);
    int*   segb  = (int*)sym_addr(g_seg);
    float* msb   = (float*)sym_addr(g_maxseg);
    float* bqkvb = (float*)sym_addr(g_bqkv);

    __half* qkvh = (__half*)sym_addr(g_qkvh);
    __half* qkvl = (__half*)sym_addr(g_qkvl);
    __half* xh  = (__half*)sym_addr(g_xh);
    __half* xl  = (__half*)sym_addr(g_xl);
    __half* fh  = (__half*)sym_addr(g_fh);
    __half* fl  = (__half*)sym_addr(g_fl);
    __half* ath = (__half*)sym_addr(g_ath);
    __half* atl = (__half*)sym_addr(g_atl);
    __half* hh  = (__half*)sym_addr(g_hh);
    __half* hl  = (__half*)sym_addr(g_hl);
    __half* ffh = (__half*)sym_addr(g_ffh);
    __half* ffl = (__half*)sym_addr(g_ffl);
    __half* plh = (__half*)sym_addr(g_plh);
    __half* pll = (__half*)sym_addr(g_pll);
    __half* phh = (__half*)sym_addr(g_phh);
    __half* phl = (__half*)sym_addr(g_phl);

    __half* wqkvh = (__half*)sym_addr(g_wqkvh);
    __half* wqkvl = (__half*)sym_addr(g_wqkvl);
    __half* woh = (__half*)sym_addr(g_woh);
    __half* wol = (__half*)sym_addr(g_wol);
    __half* w1h = (__half*)sym_addr(g_w1h);
    __half* w1l = (__half*)sym_addr(g_w1l);
    __half* w2h = (__half*)sym_addr(g_w2h);
    __half* w2l = (__half*)sym_addr(g_w2l);
    __half* p1h = (__half*)sym_addr(g_p1h);
    __half* p1l = (__half*)sym_addr(g_p1l);
    __half* p2h = (__half*)sym_addr(g_p2h);
    __half* p2l = (__half*)sym_addr(g_p2l);

    // ---- weight prep: transpose + x64 + fp16 split ----
    trans_split_h_kernel<<<dim3(DD / 32, DD / 32), 256>>>(Wq, wqkvh, wqkvl, DD, DD);
    trans_split_h_kernel<<<dim3(DD / 32, DD / 32), 256>>>(Wk, wqkvh + DD * DD,
                                                          wqkvl + DD * DD, DD, DD);
    trans_split_h_kernel<<<dim3(DD / 32, DD / 32), 256>>>(Wv, wqkvh + 2 * DD * DD,
                                                          wqkvl + 2 * DD * DD, DD, DD);
    trans_split_h_kernel<<<dim3(DD / 32, DD / 32), 256>>>(Wo, woh, wol, DD, DD);
    trans_split_h_kernel<<<dim3(FF / 32, DD / 32), 256>>>(W1, w1h, w1l, DD, FF);
    trans_split_h_kernel<<<dim3(DD / 32, FF / 32), 256>>>(W2, w2h, w2l, FF, DD);
    trans_split_h_kernel<<<dim3(HID / 32, DD / 32), 256>>>(P1, p1h, p1l, DD, HID);
    trans_split_h_kernel<<<dim3(HID / 32, HID / 32), 256>>>(P2, p2h, p2l, HID, HID);
    concat_bias_kernel<<<(QKVN + 255) / 256, 256>>>(bq, bk, bv, bqkvb);
    split_h_kernel<<<(TOK * DD + 255) / 256, 256>>>(x, xh, xl, TOK * DD);

    // ---- encoder layer, applied twice (fp16 2-split exact path) ----
    const __half* inh = xh;
    const __half* inl = xl;
    const float* enc_in = x;
    float* enc_out = featb;
    for (int pass = 0; pass < 2; pass++) {
        int mode = pass;
        launch_hgemm(inh, inl, wqkvh, wqkvl, bqkvb, nullptr, qkvh, qkvl,
                     TOK, QKVN, DD, 0, 1);                  // split fp16 out
        attn_mma_kernel<<<dim3(SS / 64, BB * HH), 128, ATT_SMEM_BYTES>>>(
            qkvh, qkvl, masks, mode, ath, atl);
        launch_hgemm(ath, atl, woh, wol, bo, ob, nullptr, nullptr,
                     TOK, DD, DD, 0, 0);
        add_ln_kernel<<<TOK, 256>>>(enc_in, ob, g1, be1, hb, hh, hl);
        launch_hgemm(hh, hl, w1h, w1l, bf1, nullptr, ffh, ffl,
                     TOK, FF, DD, 1, 1);                    // GELU, split out
        launch_hgemm(ffh, ffl, w2h, w2l, bf2, ob, nullptr, nullptr,
                     TOK, DD, FF, 0, 0);
        add_ln_kernel<<<TOK, 256>>>(hb, ob, g2, be2, enc_out, fh, fl);
        enc_in = featb;
        enc_out = feat2b;
        inh = fh; inl = fl;
    }

    // ---- importance scores, cumsum segmentation ----
    score_kernel<<<TOK / 8, 256>>>(feat2b, Ws, bs, sb);
    scan_kernel<<<BB, 1024>>>(sb, masks, svb, segb, msb);

    // ---- weighted segment-sum pooling of original x (split fp16 output) ----
    pool_kernel<<<dim3(SS, BB), 256>>>(x, svb, segb, plh, pll);

    // ---- projector on fp16-split tensor cores ----
    launch_hgemm(plh, pll, p1h, p1l, bp1, nullptr, phh, phl,
                 TOK, HID, DD, 1, 1);                       // GELU, split out
    launch_hgemm(phh, phl, p2h, p2l, bp2, out, nullptr, nullptr,
                 TOK, HID, HID, 0, 0);                      // fp32 out

    // ---- new_mask appended after the [B,S,HID] output ----
    mask_kernel<<<BB, 1024>>>(msb, out + (size_t)TOK * HID);
}

// round 9
// speedup vs baseline: 1.2487x; 1.0300x over previous
#include <cuda_runtime.h>
#include <cuda_fp16.h>
#include <cstdint>
#include <math.h>

// ---------------------------------------------------------------------------
// Problem constants
// ---------------------------------------------------------------------------
#define BB 4
#define SS 1024
#define DD 1024
#define HH 16
#define HDIM 64
#define FF 2048
#define HID 4096
#define TOK (BB*SS)          // 4096 tokens
#define QKVN 3072
#define WSCALE (1.0f/64.0f)  // weights pre-scaled by 64 (fp16 subnormal guard)

// ---------------------------------------------------------------------------
// Scratch (__device__ globals; no allocation allowed)
// ---------------------------------------------------------------------------
__device__ float g_o   [TOK*DD];
__device__ float g_h   [TOK*DD];
__device__ float g_feat[TOK*DD];
__device__ float g_feat2[TOK*DD];
__device__ float g_s   [TOK];
__device__ float g_sv  [TOK];
__device__ int   g_seg [TOK];
__device__ float g_maxseg[BB];
__device__ float g_bqkv[QKVN];

// fp16 split activations
__device__ __half g_qkvh[TOK*QKVN], g_qkvl[TOK*QKVN];
__device__ __half g_xh[TOK*DD],    g_xl[TOK*DD];
__device__ __half g_fh[TOK*DD],    g_fl[TOK*DD];     // feat / feat2 split
__device__ __half g_ath[TOK*DD],   g_atl[TOK*DD];    // attention out split
__device__ __half g_hh[TOK*DD],    g_hl[TOK*DD];     // h split
__device__ __half g_ffh[TOK*FF],   g_ffl[TOK*FF];    // ffn mid split
__device__ __half g_plh[TOK*DD],   g_pll[TOK*DD];    // pooled split
__device__ __half g_phh[TOK*HID],  g_phl[TOK*HID];   // projector mid split

// fp16 split weights [N,K] K-contiguous, pre-scaled x64
__device__ __half g_wqkvh[QKVN*DD], g_wqkvl[QKVN*DD];
__device__ __half g_woh[DD*DD],     g_wol[DD*DD];
__device__ __half g_w1h[FF*DD],     g_w1l[FF*DD];
__device__ __half g_w2h[DD*FF],     g_w2l[DD*FF];
__device__ __half g_p1h[HID*DD],    g_p1l[HID*DD];
__device__ __half g_p2h[HID*HID],   g_p2l[HID*HID];

// ---------------------------------------------------------------------------
// Helpers
// ---------------------------------------------------------------------------
__device__ __forceinline__ float gelu_f(float x) {
    return 0.5f * x * (1.0f + erff(x * 0.70710678118654752440f));
}

__device__ __forceinline__ void cp16(uint32_t dst, const void* src) {
    asm volatile("cp.async.cg.shared.global [%0], [%1], 16;\n"
                 :: "r"(dst), "l"(src));
}

__device__ __forceinline__ uint32_t smem_u32(const void* p) {
    uint32_t a;
    asm("{ .reg .u64 t; cvta.to.shared.u64 t, %1; cvt.u32.u64 %0, t; }"
        : "=r"(a) : "l"(p));
    return a;
}

// mma.sync m16n8k16 f16 with f32 accumulate
__device__ __forceinline__ void mma_f16(float* c,
                                        uint32_t a0, uint32_t a1,
                                        uint32_t a2, uint32_t a3,
                                        uint32_t b0, uint32_t b1) {
    asm volatile(
        "mma.sync.aligned.m16n8k16.row.col.f32.f16.f16.f32 "
        "{%0,%1,%2,%3}, {%4,%5,%6,%7}, {%8,%9}, {%0,%1,%2,%3};\n"
        : "+f"(c[0]), "+f"(c[1]), "+f"(c[2]), "+f"(c[3])
        : "r"(a0), "r"(a1), "r"(a2), "r"(a3), "r"(b0), "r"(b1));
}

// ldmatrix x4: four 8x8 b16 tiles, one per lane-octet address
__device__ __forceinline__ void ldsm_x4(uint32_t* r, uint32_t addr) {
    asm volatile(
        "ldmatrix.sync.aligned.m8n8.x4.shared.b16 {%0,%1,%2,%3}, [%4];\n"
        : "=r"(r[0]), "=r"(r[1]), "=r"(r[2]), "=r"(r[3]) : "r"(addr));
}

__device__ __forceinline__ void hsplit(float v, __half& h, __half& l) {
    h = __float2half(v);
    l = __float2half(v - __half2float(h));
}

__device__ __forceinline__ uint32_t hpack(__half a, __half b) {
    __half2 t = __halves2half2(a, b);
    return *reinterpret_cast<uint32_t*>(&t);
}

// ---------------------------------------------------------------------------
// fp16 2-split 3-combo GEMM (fp32-grade accuracy), ldmatrix fragment loads
// C[M,N] = act((A @ Bt^T) * WSCALE + bias[N]),  A = Ah+Al, Bt = Bh+Bl
// out_split=1: write split fp16 (Ch, Cl) instead of fp32 C.
// ---------------------------------------------------------------------------
#define HS 40
#define H_STAGE_HALVES 20480          // 4 arrays * 128*40
#define H_SMEM_BYTES  (2 * H_STAGE_HALVES * 2)

__global__ __launch_bounds__(256)
void hgemm_kernel(const __half* __restrict__ Ah, const __half* __restrict__ Al,
                  const __half* __restrict__ Bh, const __half* __restrict__ Bl,
                  const float* __restrict__ bias, float* __restrict__ C,
                  __half* __restrict__ Ch, __half* __restrict__ Cl,
                  int M, int N, int K, int act, int out_split)
{
    extern __shared__ __half hsm[];
    const int tid  = threadIdx.x;
    const int wid  = tid >> 5;
    const int lane = tid & 31;
    const int gr   = lane >> 2;
    const int gc   = lane & 3;
    const int lg   = lane >> 3;     // lane octet 0..3
    const int lr   = lane & 7;
    const int row0 = blockIdx.y * 128;
    const int col0 = blockIdx.x * 128;
    const int warp_m = (wid & 3) * 32;
    const int warp_n = (wid >> 2) * 64;
    const uint32_t sbase = smem_u32(hsm);

    // ldmatrix lane-address components (in halves, relative to array start)
    // A x4 tile order: (rows, k), (rows+8, k), (rows, k+8), (rows+8, k+8)
    const int a_rowoff = (lg & 1) * 8 + lr;        // + warp_m + mt*16
    const int a_koff   = (lg >> 1) * 8;
    // B x4 tile order: (nt=2p rows, k), (2p rows, k+8), (2p+1 rows, k), (2p+1, k+8)
    const int b_rowoff = (lg >> 1) * 8 + lr;       // + warp_n + p*16
    const int b_koff   = (lg & 1) * 8;

    float acc[2][8][4];
#pragma unroll
    for (int i = 0; i < 2; i++)
#pragma unroll
        for (int j = 0; j < 8; j++)
#pragma unroll
            for (int r = 0; r < 4; r++) acc[i][j][r] = 0.0f;

    const int nk = K >> 5;
    const int c0i = tid * 2, c1i = tid * 2 + 1;
    const int m0 = c0i >> 2, kc0 = (c0i & 3) * 8;
    const int m1 = c1i >> 2, kc1 = (c1i & 3) * 8;

#define H_LOAD_STAGE(st, k0)                                                     \
    do {                                                                         \
        uint32_t b = sbase + (uint32_t)(st) * H_STAGE_HALVES * 2u;               \
        cp16(b + (uint32_t)(m0 * HS + kc0) * 2u,                                 \
             Ah + (size_t)(row0 + m0) * K + (k0) + kc0);                         \
        cp16(b + (uint32_t)(m1 * HS + kc1) * 2u,                                 \
             Ah + (size_t)(row0 + m1) * K + (k0) + kc1);                         \
        cp16(b + (uint32_t)(5120 + m0 * HS + kc0) * 2u,                          \
             Al + (size_t)(row0 + m0) * K + (k0) + kc0);                         \
        cp16(b + (uint32_t)(5120 + m1 * HS + kc1) * 2u,                          \
             Al + (size_t)(row0 + m1) * K + (k0) + kc1);                         \
        cp16(b + (uint32_t)(10240 + m0 * HS + kc0) * 2u,                         \
             Bh + (size_t)(col0 + m0) * K + (k0) + kc0);                         \
        cp16(b + (uint32_t)(10240 + m1 * HS + kc1) * 2u,                         \
             Bh + (size_t)(col0 + m1) * K + (k0) + kc1);                         \
        cp16(b + (uint32_t)(15360 + m0 * HS + kc0) * 2u,                         \
             Bl + (size_t)(col0 + m0) * K + (k0) + kc0);                         \
        cp16(b + (uint32_t)(15360 + m1 * HS + kc1) * 2u,                         \
             Bl + (size_t)(col0 + m1) * K + (k0) + kc1);                         \
        asm volatile("cp.async.commit_group;\n");                                \
    } while (0)

    H_LOAD_STAGE(0, 0);

    for (int t = 0; t < nk; t++) {
        const int st = t & 1;
        if (t + 1 < nk) {
            H_LOAD_STAGE((t + 1) & 1, (t + 1) << 5);
            asm volatile("cp.async.wait_group 1;\n");
        } else {
            asm volatile("cp.async.wait_group 0;\n");
        }
        __syncthreads();

        const uint32_t sg = sbase + (uint32_t)st * H_STAGE_HALVES * 2u;

#pragma unroll
        for (int ks = 0; ks < 2; ks++) {
            const int kh = ks * 16;
            uint32_t ahf[2][4], alf[2][4];
#pragma unroll
            for (int mt = 0; mt < 2; mt++) {
                uint32_t aaddr = sg + (uint32_t)(
                    (warp_m + mt * 16 + a_rowoff) * HS + kh + a_koff) * 2u;
                ldsm_x4(ahf[mt], aaddr);
                ldsm_x4(alf[mt], aaddr + 5120u * 2u);
            }
#pragma unroll
            for (int p = 0; p < 4; p++) {
                uint32_t baddr = sg + (uint32_t)(
                    (warp_n + p * 16 + b_rowoff) * HS + kh + b_koff) * 2u
                    + 10240u * 2u;
                uint32_t bhf[4], blf[4];
                ldsm_x4(bhf, baddr);
                ldsm_x4(blf, baddr + 5120u * 2u);
#pragma unroll
                for (int q = 0; q < 2; q++) {
                    const int nt = p * 2 + q;
                    uint32_t bh0 = bhf[q * 2], bh1 = bhf[q * 2 + 1];
                    uint32_t bl0 = blf[q * 2], bl1 = blf[q * 2 + 1];
#pragma unroll
                    for (int mt = 0; mt < 2; mt++) {
                        float* c = acc[mt][nt];
                        mma_f16(c, ahf[mt][0], ahf[mt][1], ahf[mt][2], ahf[mt][3], bh0, bh1);
                        mma_f16(c, ahf[mt][0], ahf[mt][1], ahf[mt][2], ahf[mt][3], bl0, bl1);
                        mma_f16(c, alf[mt][0], alf[mt][1], alf[mt][2], alf[mt][3], bh0, bh1);
                    }
                }
            }
        }
        __syncthreads();
    }

#pragma unroll
    for (int mt = 0; mt < 2; mt++) {
        const int r0 = row0 + warp_m + mt * 16 + gr;
#pragma unroll
        for (int nt = 0; nt < 8; nt++) {
            const int cc = col0 + warp_n + nt * 8 + 2 * gc;
            float b0v = bias[cc], b1v = bias[cc + 1];
            float v0 = acc[mt][nt][0] * WSCALE + b0v;
            float v1 = acc[mt][nt][1] * WSCALE + b1v;
            float v2 = acc[mt][nt][2] * WSCALE + b0v;
            float v3 = acc[mt][nt][3] * WSCALE + b1v;
            if (act == 1) {
                v0 = gelu_f(v0); v1 = gelu_f(v1);
                v2 = gelu_f(v2); v3 = gelu_f(v3);
            }
            if (!out_split) {
                *(float2*)(C + (size_t)r0 * N + cc)       = make_float2(v0, v1);
                *(float2*)(C + (size_t)(r0 + 8) * N + cc) = make_float2(v2, v3);
            } else {
                __half h0, l0, h1, l1;
                hsplit(v0, h0, l0); hsplit(v1, h1, l1);
                *(__half2*)(Ch + (size_t)r0 * N + cc) = __halves2half2(h0, h1);
                *(__half2*)(Cl + (size_t)r0 * N + cc) = __halves2half2(l0, l1);
                hsplit(v2, h0, l0); hsplit(v3, h1, l1);
                *(__half2*)(Ch + (size_t)(r0 + 8) * N + cc) = __halves2half2(h0, h1);
                *(__half2*)(Cl + (size_t)(r0 + 8) * N + cc) = __halves2half2(l0, l1);
            }
        }
    }
}

// ---------------------------------------------------------------------------
// Tensor-core flash attention on fp16-split operands (3-combo, m16n8k16).
// 64-q tile, 128 threads (4 warps x 16 queries). QKV input pre-split fp16.
// ---------------------------------------------------------------------------
#define HST 72
#define ATT_SMEM_BYTES (8 * 64 * HST * 2 + 64 * 4)

__global__ __launch_bounds__(128)
void attn_mma_kernel(const __half* __restrict__ qkvh, const __half* __restrict__ qkvl,
                     const float* __restrict__ masks,
                     int mode, __half* __restrict__ oh, __half* __restrict__ ol)
{
    extern __shared__ __half hs[];
    __half* Qh  = hs;
    __half* Ql  = Qh  + 64 * HST;
    __half* Kh  = Ql  + 64 * HST;
    __half* Kl  = Kh  + 64 * HST;
    __half* Vh  = Kl  + 64 * HST;
    __half* Vl  = Vh  + 64 * HST;
    __half* Psh = Vl  + 64 * HST;
    __half* Psl = Psh + 64 * HST;
    float*  mb  = (float*)(Psl + 64 * HST);

    const uint32_t sQh = smem_u32(Qh), sQl = smem_u32(Ql);
    const uint32_t sKh = smem_u32(Kh), sKl = smem_u32(Kl);
    const uint32_t sVh = smem_u32(Vh), sVl = smem_u32(Vl);

    const int tid  = threadIdx.x;
    const int wid  = tid >> 5;
    const int lane = tid & 31;
    const int gr   = lane >> 2;
    const int gc   = lane & 3;
    const int q0   = blockIdx.x * 64;
    const int b    = blockIdx.y >> 4;
    const int h    = blockIdx.y & 15;
    const size_t qbase = (size_t)b * SS * QKVN + (size_t)h * HDIM;
    const size_t obase = (size_t)b * SS * DD + (size_t)h * HDIM;
    const int q0w = wid * 16;

    for (int idx = tid; idx < 512; idx += 128) {
        int r = idx >> 3, c8 = (idx & 7) << 3;
        uint32_t soff = (uint32_t)(r * HST + c8) * 2u;
        cp16(sQh + soff, qkvh + qbase + (size_t)(q0 + r) * QKVN + c8);
        cp16(sQl + soff, qkvl + qbase + (size_t)(q0 + r) * QKVN + c8);
    }
    asm volatile("cp.async.commit_group;\n");

    float mrow[2] = {-1e30f, -1e30f};
    float lrow[2] = {0.0f, 0.0f};
    float Oacc[8][4];
#pragma unroll
    for (int i = 0; i < 8; i++)
#pragma unroll
        for (int j = 0; j < 4; j++) Oacc[i][j] = 0.0f;

    for (int t = 0; t < 16; t++) {
        const int k0 = t * 64;
        for (int idx = tid; idx < 512; idx += 128) {
            int r = idx >> 3, c8 = (idx & 7) << 3;
            uint32_t soff = (uint32_t)(r * HST + c8) * 2u;
            size_t kg = qbase + 1024 + (size_t)(k0 + r) * QKVN + c8;
            size_t vg = qbase + 2048 + (size_t)(k0 + r) * QKVN + c8;
            cp16(sKh + soff, qkvh + kg);
            cp16(sKl + soff, qkvl + kg);
            cp16(sVh + soff, qkvh + vg);
            cp16(sVl + soff, qkvl + vg);
        }
        asm volatile("cp.async.commit_group;\n");
        if (tid < 64) {
            float mv = masks[b * SS + k0 + tid];
            mb[tid] = (mode == 0) ? mv : (mv > 0.0f ? 0.0f : -1e9f);
        }
        asm volatile("cp.async.wait_group 0;\n");
        __syncthreads();

        float S[8][4];
#pragma unroll
        for (int i = 0; i < 8; i++)
#pragma unroll
            for (int j = 0; j < 4; j++) S[i][j] = 0.0f;

#pragma unroll
        for (int kh = 0; kh < 64; kh += 16) {
            uint32_t qhf[4], qlf[4];
            {
                int base = (q0w + gr) * HST + kh + 2 * gc;
                qhf[0] = *(const uint32_t*)(Qh + base);
                qhf[1] = *(const uint32_t*)(Qh + base + 8 * HST);
                qhf[2] = *(const uint32_t*)(Qh + base + 8);
                qhf[3] = *(const uint32_t*)(Qh + base + 8 * HST + 8);
                qlf[0] = *(const uint32_t*)(Ql + base);
                qlf[1] = *(const uint32_t*)(Ql + base + 8 * HST);
                qlf[2] = *(const uint32_t*)(Ql + base + 8);
                qlf[3] = *(const uint32_t*)(Ql + base + 8 * HST + 8);
            }
#pragma unroll
            for (int nt = 0; nt < 8; nt++) {
                int bb = (nt * 8 + gr) * HST + kh + 2 * gc;
                uint32_t kh0 = *(const uint32_t*)(Kh + bb);
                uint32_t kh1 = *(const uint32_t*)(Kh + bb + 8);
                uint32_t kl0 = *(const uint32_t*)(Kl + bb);
                uint32_t kl1 = *(const uint32_t*)(Kl + bb + 8);
                mma_f16(S[nt], qhf[0], qhf[1], qhf[2], qhf[3], kh0, kh1);
                mma_f16(S[nt], qhf[0], qhf[1], qhf[2], qhf[3], kl0, kl1);
                mma_f16(S[nt], qlf[0], qlf[1], qlf[2], qlf[3], kh0, kh1);
            }
        }

        float rmax[2] = {-1e30f, -1e30f};
#pragma unroll
        for (int nt = 0; nt < 8; nt++) {
            float m0 = mb[nt * 8 + 2 * gc];
            float m1 = mb[nt * 8 + 2 * gc + 1];
            S[nt][0] = S[nt][0] * 0.125f + m0;
            S[nt][1] = S[nt][1] * 0.125f + m1;
            S[nt][2] = S[nt][2] * 0.125f + m0;
            S[nt][3] = S[nt][3] * 0.125f + m1;
            rmax[0] = fmaxf(rmax[0], fmaxf(S[nt][0], S[nt][1]));
            rmax[1] = fmaxf(rmax[1], fmaxf(S[nt][2], S[nt][3]));
        }
#pragma unroll
        for (int sh = 1; sh < 4; sh <<= 1) {
            rmax[0] = fmaxf(rmax[0], __shfl_xor_sync(0xffffffffu, rmax[0], sh));
            rmax[1] = fmaxf(rmax[1], __shfl_xor_sync(0xffffffffu, rmax[1], sh));
        }
        float mnew0 = fmaxf(mrow[0], rmax[0]);
        float mnew1 = fmaxf(mrow[1], rmax[1]);
        float scl0 = __expf(mrow[0] - mnew0);
        float scl1 = __expf(mrow[1] - mnew1);
        float rsum[2] = {0.0f, 0.0f};
#pragma unroll
        for (int nt = 0; nt < 8; nt++) {
            S[nt][0] = __expf(S[nt][0] - mnew0);
            S[nt][1] = __expf(S[nt][1] - mnew0);
            S[nt][2] = __expf(S[nt][2] - mnew1);
            S[nt][3] = __expf(S[nt][3] - mnew1);
            rsum[0] += S[nt][0] + S[nt][1];
            rsum[1] += S[nt][2] + S[nt][3];
        }
#pragma unroll
        for (int sh = 1; sh < 4; sh <<= 1) {
            rsum[0] += __shfl_xor_sync(0xffffffffu, rsum[0], sh);
            rsum[1] += __shfl_xor_sync(0xffffffffu, rsum[1], sh);
        }
        lrow[0] = lrow[0] * scl0 + rsum[0];
        lrow[1] = lrow[1] * scl1 + rsum[1];
        mrow[0] = mnew0; mrow[1] = mnew1;
#pragma unroll
        for (int dt = 0; dt < 8; dt++) {
            Oacc[dt][0] *= scl0; Oacc[dt][1] *= scl0;
            Oacc[dt][2] *= scl1; Oacc[dt][3] *= scl1;
        }

        __syncwarp();
#pragma unroll
        for (int nt = 0; nt < 8; nt++) {
            int c0 = nt * 8 + 2 * gc;
            __half h0, l0, h1, l1;
            hsplit(S[nt][0], h0, l0); hsplit(S[nt][1], h1, l1);
            *(__half2*)(Psh + (q0w + gr) * HST + c0) = __halves2half2(h0, h1);
            *(__half2*)(Psl + (q0w + gr) * HST + c0) = __halves2half2(l0, l1);
            hsplit(S[nt][2], h0, l0); hsplit(S[nt][3], h1, l1);
            *(__half2*)(Psh + (q0w + gr + 8) * HST + c0) = __halves2half2(h0, h1);
            *(__half2*)(Psl + (q0w + gr + 8) * HST + c0) = __halves2half2(l0, l1);
        }
        __syncwarp();

#pragma unroll
        for (int kh = 0; kh < 64; kh += 16) {
            uint32_t phf[4], plf[4];
            {
                int base = (q0w + gr) * HST + kh + 2 * gc;
                phf[0] = *(const uint32_t*)(Psh + base);
                phf[1] = *(const uint32_t*)(Psh + base + 8 * HST);
                phf[2] = *(const uint32_t*)(Psh + base + 8);
                phf[3] = *(const uint32_t*)(Psh + base + 8 * HST + 8);
                plf[0] = *(const uint32_t*)(Psl + base);
                plf[1] = *(const uint32_t*)(Psl + base + 8 * HST);
                plf[2] = *(const uint32_t*)(Psl + base + 8);
                plf[3] = *(const uint32_t*)(Psl + base + 8 * HST + 8);
            }
            const int ka = kh + 2 * gc;
#pragma unroll
            for (int dt = 0; dt < 8; dt++) {
                int d = dt * 8 + gr;
                uint32_t vh0 = hpack(Vh[ka * HST + d],       Vh[(ka + 1) * HST + d]);
                uint32_t vh1 = hpack(Vh[(ka + 8) * HST + d], Vh[(ka + 9) * HST + d]);
                uint32_t vl0 = hpack(Vl[ka * HST + d],       Vl[(ka + 1) * HST + d]);
                uint32_t vl1 = hpack(Vl[(ka + 8) * HST + d], Vl[(ka + 9) * HST + d]);
                mma_f16(Oacc[dt], phf[0], phf[1], phf[2], phf[3], vh0, vh1);
                mma_f16(Oacc[dt], phf[0], phf[1], phf[2], phf[3], vl0, vl1);
                mma_f16(Oacc[dt], plf[0], plf[1], plf[2], plf[3], vh0, vh1);
            }
        }
        __syncthreads();
    }

    float inv0 = 1.0f / lrow[0];
    float inv1 = 1.0f / lrow[1];
    const int r0 = q0 + q0w + gr;
#pragma unroll
    for (int dt = 0; dt < 8; dt++) {
        int col = dt * 8 + 2 * gc;
        __half h0, l0, h1, l1;
        hsplit(Oacc[dt][0] * inv0, h0, l0);
        hsplit(Oacc[dt][1] * inv0, h1, l1);
        *(__half2*)(oh + obase + (size_t)r0 * DD + col) = __halves2half2(h0, h1);
        *(__half2*)(ol + obase + (size_t)r0 * DD + col) = __halves2half2(l0, l1);
        hsplit(Oacc[dt][2] * inv1, h0, l0);
        hsplit(Oacc[dt][3] * inv1, h1, l1);
        *(__half2*)(oh + obase + (size_t)(r0 + 8) * DD + col) = __halves2half2(h0, h1);
        *(__half2*)(ol + obase + (size_t)(r0 + 8) * DD + col) = __halves2half2(l0, l1);
    }
}

// ---------------------------------------------------------------------------
// Transpose + scale x64 + fp16 split: Wh/Wl[n,k] = split(64 * W[k,n])
// ---------------------------------------------------------------------------
__global__ __launch_bounds__(256)
void trans_split_h_kernel(const float* __restrict__ W,
                          __half* __restrict__ Wh, __half* __restrict__ Wl,
                          int Kd, int Nd)
{
    __shared__ float t[32][33];
    const int n0 = blockIdx.x * 32, k0 = blockIdx.y * 32;
    const int tx = threadIdx.x & 31, ty = threadIdx.x >> 5;
#pragma unroll
    for (int r = ty; r < 32; r += 8)
        t[r][tx] = W[(size_t)(k0 + r) * Nd + n0 + tx];
    __syncthreads();
#pragma unroll
    for (int r = ty; r < 32; r += 8) {
        float v = t[tx][r] * 64.0f;
        __half h, l;
        hsplit(v, h, l);
        Wh[(size_t)(n0 + r) * Kd + k0 + tx] = h;
        Wl[(size_t)(n0 + r) * Kd + k0 + tx] = l;
    }
}

// ---------------------------------------------------------------------------
// Elementwise fp16 split of an fp32 array
// ---------------------------------------------------------------------------
__global__ __launch_bounds__(256)
void split_h_kernel(const float* __restrict__ a, __half* __restrict__ ah,
                    __half* __restrict__ al, int n)
{
    int i = blockIdx.x * 256 + threadIdx.x;
    if (i < n) {
        __half h, l;
        hsplit(a[i], h, l);
        ah[i] = h; al[i] = l;
    }
}

// ---------------------------------------------------------------------------
// concat bias [bq|bk|bv] -> bqkv
// ---------------------------------------------------------------------------
__global__ __launch_bounds__(256)
void concat_bias_kernel(const float* __restrict__ bq, const float* __restrict__ bk,
                        const float* __restrict__ bv, float* __restrict__ bqkv)
{
    int i = blockIdx.x * 256 + threadIdx.x;
    if (i < QKVN) {
        float v = (i < 1024) ? bq[i] : ((i < 2048) ? bk[i - 1024] : bv[i - 2048]);
        bqkv[i] = v;
    }
}

// ---------------------------------------------------------------------------
// out = LayerNorm(a + b) * g + beta ; also writes fp16 split of out
// ---------------------------------------------------------------------------
__global__ __launch_bounds__(256)
void add_ln_kernel(const float* __restrict__ a, const float* __restrict__ b2,
                   const float* __restrict__ g, const float* __restrict__ beta,
                   float* __restrict__ out,
                   __half* __restrict__ outh, __half* __restrict__ outl)
{
    const int row = blockIdx.x;
    const size_t off = (size_t)row * DD;
    const int t = threadIdx.x;
    __shared__ float r1[256], r2[256];

    float vloc[4];
    float s = 0.0f, s2 = 0.0f;
#pragma unroll
    for (int i = 0; i < 4; i++) {
        int d = t + i * 256;
        float vv = a[off + d] + b2[off + d];
        vloc[i] = vv;
        s += vv; s2 += vv * vv;
    }
    r1[t] = s; r2[t] = s2;
    __syncthreads();
    for (int o2 = 128; o2 > 0; o2 >>= 1) {
        if (t < o2) { r1[t] += r1[t + o2]; r2[t] += r2[t + o2]; }
        __syncthreads();
    }
    float mean = r1[0] * (1.0f / DD);
    float var  = r2[0] * (1.0f / DD) - mean * mean;
    float inv  = rsqrtf(var + 1e-5f);
#pragma unroll
    for (int i = 0; i < 4; i++) {
        int d = t + i * 256;
        float vv = (vloc[i] - mean) * inv * g[d] + beta[d];
        out[off + d] = vv;
        __half h, l;
        hsplit(vv, h, l);
        outh[off + d] = h;
        outl[off + d] = l;
    }
}

// ---------------------------------------------------------------------------
// s = sigmoid(feat @ Ws + bs); one warp per token
// ---------------------------------------------------------------------------
__global__ __launch_bounds__(256)
void score_kernel(const float* __restrict__ feat, const float* __restrict__ Ws,
                  const float* __restrict__ bs, float* __restrict__ sbuf)
{
    int token = blockIdx.x * 8 + (threadIdx.x >> 5);
    int lane  = threadIdx.x & 31;
    const float* f = feat + (size_t)token * DD;
    float acc = 0.0f;
    for (int i = lane; i < DD; i += 32) acc += f[i] * Ws[i];
#pragma unroll
    for (int m = 16; m; m >>= 1) acc += __shfl_xor_sync(0xffffffffu, acc, m);
    if (lane == 0) sbuf[token] = 1.0f / (1.0f + expf(-(acc + bs[0])));
}

// ---------------------------------------------------------------------------
// Per-batch inclusive scan of sv, floor -> segment ids, max over valid
// ---------------------------------------------------------------------------
__global__ __launch_bounds__(1024)
void scan_kernel(const float* __restrict__ sbuf, const float* __restrict__ masks,
                 float* __restrict__ svbuf, int* __restrict__ segbuf,
                 float* __restrict__ maxseg)
{
    const int b = blockIdx.x;
    const int t = threadIdx.x;
    __shared__ float sc[SS];
    __shared__ float mr[SS];

    float valid = masks[b * SS + t];
    float sv = (valid > 0.0f) ? sbuf[b * SS + t] : 0.0f;
    svbuf[b * SS + t] = sv;
    sc[t] = sv;
    __syncthreads();
    for (int off = 1; off < SS; off <<= 1) {
        float vprev = (t >= off) ? sc[t - off] : 0.0f;
        __syncthreads();
        sc[t] += vprev;
        __syncthreads();
    }
    float c = floorf(sc[t]);
    int seg = (int)c;
    seg = seg < 0 ? 0 : (seg > SS - 1 ? SS - 1 : seg);
    segbuf[b * SS + t] = seg;

    mr[t] = (valid > 0.0f) ? c : -1.0f;
    __syncthreads();
    for (int off = 512; off > 0; off >>= 1) {
        if (t < off) mr[t] = fmaxf(mr[t], mr[t + off]);
        __syncthreads();
    }
    if (t == 0) maxseg[b] = mr[0];
}

// ---------------------------------------------------------------------------
// pooled[b,g,:] = sum_{s: seg[b,s]==g} x[b,s,:]*sv[b,s] -> split fp16 output
// ---------------------------------------------------------------------------
__global__ __launch_bounds__(256)
void pool_kernel(const float* __restrict__ x, const float* __restrict__ svbuf,
                 const int* __restrict__ segbuf,
                 __half* __restrict__ ph, __half* __restrict__ pl)
{
    const int g = blockIdx.x;
    const int b = blockIdx.y;
    const int* seg = segbuf + b * SS;

    int lo = 0, hi = SS;
    while (lo < hi) { int mid = (lo + hi) >> 1; if (seg[mid] < g) lo = mid + 1; else hi = mid; }
    int beg = lo;
    lo = beg; hi = SS;
    while (lo < hi) { int mid = (lo + hi) >> 1; if (seg[mid] < g + 1) lo = mid + 1; else hi = mid; }
    int end = lo;

    const int t = threadIdx.x;
    float acc[4] = {0.0f, 0.0f, 0.0f, 0.0f};
    for (int s = beg; s < end; s++) {
        float w = svbuf[b * SS + s];
        const float* xr = x + ((size_t)b * SS + s) * DD;
#pragma unroll
        for (int i = 0; i < 4; i++) acc[i] += xr[t + i * 256] * w;
    }
    size_t rbase = ((size_t)b * SS + g) * DD;
#pragma unroll
    for (int i = 0; i < 4; i++) {
        __half h, l;
        hsplit(acc[i], h, l);
        ph[rbase + t + i * 256] = h;
        pl[rbase + t + i * 256] = l;
    }
}

// ---------------------------------------------------------------------------
// new_mask[b,s] = (s <= max_seg[b]) ? 1 : 0
// ---------------------------------------------------------------------------
__global__ __launch_bounds__(1024)
void mask_kernel(const float* __restrict__ maxseg, float* __restrict__ outmask)
{
    const int b = blockIdx.x;
    const int t = threadIdx.x;
    outmask[b * SS + t] = ((float)t <= maxseg[b]) ? 1.0f : 0.0f;
}

// ---------------------------------------------------------------------------
// Host side
// ---------------------------------------------------------------------------
static void* sym_addr(const void* sym) {
    void* p = nullptr;
    cudaGetSymbolAddress(&p, sym);
    return p;
}

static void launch_hgemm(const __half* Ah, const __half* Al,
                         const __half* Bh, const __half* Bl,
                         const float* bias, float* C,
                         __half* Ch, __half* Cl,
                         int M, int N, int K, int act, int out_split) {
    dim3 grid(N / 128, M / 128);
    hgemm_kernel<<<grid, 256, H_SMEM_BYTES>>>(Ah, Al, Bh, Bl, bias, C,
                                              Ch, Cl, M, N, K, act, out_split);
}

extern "C" void kernel_launch(void* const* d_in, const int* in_sizes, int n_in,
                              void* d_out, int out_size)
{
    (void)in_sizes; (void)n_in;
    const float* x     = (const float*)d_in[0];
    const float* masks = (const float*)d_in[1];
    const float* Wq  = (const float*)d_in[2];
    const float* bq  = (const float*)d_in[3];
    const float* Wk  = (const float*)d_in[4];
    const float* bk  = (const float*)d_in[5];
    const float* Wv  = (const float*)d_in[6];
    const float* bv  = (const float*)d_in[7];
    const float* Wo  = (const float*)d_in[8];
    const float* bo  = (const float*)d_in[9];
    const float* g1  = (const float*)d_in[10];
    const float* be1 = (const float*)d_in[11];
    const float* g2  = (const float*)d_in[12];
    const float* be2 = (const float*)d_in[13];
    const float* W1  = (const float*)d_in[14];
    const float* bf1 = (const float*)d_in[15];
    const float* W2  = (const float*)d_in[16];
    const float* bf2 = (const float*)d_in[17];
    const float* Ws  = (const float*)d_in[18];
    const float* bs  = (const float*)d_in[19];
    const float* P1  = (const float*)d_in[20];
    const float* bp1 = (const float*)d_in[21];
    const float* P2  = (const float*)d_in[22];
    const float* bp2 = (const float*)d_in[23];

    float* out = (float*)d_out;
    (void)out_size;

    cudaFuncSetAttribute(attn_mma_kernel,
                         cudaFuncAttributeMaxDynamicSharedMemorySize,
                         ATT_SMEM_BYTES);
    cudaFuncSetAttribute(hgemm_kernel,
                         cudaFuncAttributeMaxDynamicSharedMemorySize,
                         H_SMEM_BYTES);

    float* ob    = (float*)sym_addr(g_o);
    float* hb    = (float*)sym_addr(g_h);
    float* featb = (float*)sym_addr(g_feat);
    float* feat2b= (float*)sym_addr(g_feat2);
    float* sb    = (float*)sym_addr(g_s);
    float* svb   = (float*)sym_addr(g_sv);
    int*   segb  = (int*)sym_addr(g_seg);
    float* msb   = (float*)sym_addr(g_maxseg);
    float* bqkvb = (float*)sym_addr(g_bqkv);

    __half* qkvh = (__half*)sym_addr(g_qkvh);
    __half* qkvl = (__half*)sym_addr(g_qkvl);
    __half* xh  = (__half*)sym_addr(g_xh);
    __half* xl  = (__half*)sym_addr(g_xl);
    __half* fh  = (__half*)sym_addr(g_fh);
    __half* fl  = (__half*)sym_addr(g_fl);
    __half* ath = (__half*)sym_addr(g_ath);
    __half* atl = (__half*)sym_addr(g_atl);
    __half* hh  = (__half*)sym_addr(g_hh);
    __half* hl  = (__half*)sym_addr(g_hl);
    __half* ffh = (__half*)sym_addr(g_ffh);
    __half* ffl = (__half*)sym_addr(g_ffl);
    __half* plh = (__half*)sym_addr(g_plh);
    __half* pll = (__half*)sym_addr(g_pll);
    __half* phh = (__half*)sym_addr(g_phh);
    __half* phl = (__half*)sym_addr(g_phl);

    __half* wqkvh = (__half*)sym_addr(g_wqkvh);
    __half* wqkvl = (__half*)sym_addr(g_wqkvl);
    __half* woh = (__half*)sym_addr(g_woh);
    __half* wol = (__half*)sym_addr(g_wol);
    __half* w1h = (__half*)sym_addr(g_w1h);
    __half* w1l = (__half*)sym_addr(g_w1l);
    __half* w2h = (__half*)sym_addr(g_w2h);
    __half* w2l = (__half*)sym_addr(g_w2l);
    __half* p1h = (__half*)sym_addr(g_p1h);
    __half* p1l = (__half*)sym_addr(g_p1l);
    __half* p2h = (__half*)sym_addr(g_p2h);
    __half* p2l = (__half*)sym_addr(g_p2l);

    // ---- weight prep: transpose + x64 + fp16 split ----
    trans_split_h_kernel<<<dim3(DD / 32, DD / 32), 256>>>(Wq, wqkvh, wqkvl, DD, DD);
    trans_split_h_kernel<<<dim3(DD / 32, DD / 32), 256>>>(Wk, wqkvh + DD * DD,
                                                          wqkvl + DD * DD, DD, DD);
    trans_split_h_kernel<<<dim3(DD / 32, DD / 32), 256>>>(Wv, wqkvh + 2 * DD * DD,
                                                          wqkvl + 2 * DD * DD, DD, DD);
    trans_split_h_kernel<<<dim3(DD / 32, DD / 32), 256>>>(Wo, woh, wol, DD, DD);
    trans_split_h_kernel<<<dim3(FF / 32, DD / 32), 256>>>(W1, w1h, w1l, DD, FF);
    trans_split_h_kernel<<<dim3(DD / 32, FF / 32), 256>>>(W2, w2h, w2l, FF, DD);
    trans_split_h_kernel<<<dim3(HID / 32, DD / 32), 256>>>(P1, p1h, p1l, DD, HID);
    trans_split_h_kernel<<<dim3(HID / 32, HID / 32), 256>>>(P2, p2h, p2l, HID, HID);
    concat_bias_kernel<<<(QKVN + 255) / 256, 256>>>(bq, bk, bv, bqkvb);
    split_h_kernel<<<(TOK * DD + 255) / 256, 256>>>(x, xh, xl, TOK * DD);

    // ---- encoder layer, applied twice (fp16 2-split exact path) ----
    const __half* inh = xh;
    const __half* inl = xl;
    const float* enc_in = x;
    float* enc_out = featb;
    for (int pass = 0; pass < 2; pass++) {
        int mode = pass;
        launch_hgemm(inh, inl, wqkvh, wqkvl, bqkvb, nullptr, qkvh, qkvl,
                     TOK, QKVN, DD, 0, 1);                  // split fp16 out
        attn_mma_kernel<<<dim3(SS / 64, BB * HH), 128, ATT_SMEM_BYTES>>>(
            qkvh, qkvl, masks, mode, ath, atl);
        launch_hgemm(ath, atl, woh, wol, bo, ob, nullptr, nullptr,
                     TOK, DD, DD, 0, 0);
        add_ln_kernel<<<TOK, 256>>>(enc_in, ob, g1, be1, hb, hh, hl);
        launch_hgemm(hh, hl, w1h, w1l, bf1, nullptr, ffh, ffl,
                     TOK, FF, DD, 1, 1);                    // GELU, split out
        launch_hgemm(ffh, ffl, w2h, w2l, bf2, ob, nullptr, nullptr,
                     TOK, DD, FF, 0, 0);
        add_ln_kernel<<<TOK, 256>>>(hb, ob, g2, be2, enc_out, fh, fl);
        enc_in = featb;
        enc_out = feat2b;
        inh = fh; inl = fl;
    }

    // ---- importance scores, cumsum segmentation ----
    score_kernel<<<TOK / 8, 256>>>(feat2b, Ws, bs, sb);
    scan_kernel<<<BB, 1024>>>(sb, masks, svb, segb, msb);

    // ---- weighted segment-sum pooling of original x (split fp16 output) ----
    pool_kernel<<<dim3(SS, BB), 256>>>(x, svb, segb, plh, pll);

    // ---- projector on fp16-split tensor cores ----
    launch_hgemm(plh, pll, p1h, p1l, bp1, nullptr, phh, phl,
                 TOK, HID, DD, 1, 1);                       // GELU, split out
    launch_hgemm(phh, phl, p2h, p2l, bp2, out, nullptr, nullptr,
                 TOK, HID, HID, 0, 0);                      // fp32 out

    // ---- new_mask appended after the [B,S,HID] output ----
    mask_kernel<<<BB, 1024>>>(msb, out + (size_t)TOK * HID);
}

// round 10
// speedup vs baseline: 1.2697x; 1.0168x over previous
#include <cuda_runtime.h>
#include <cuda_fp16.h>
#include <cstdint>
#include <math.h>

// ---------------------------------------------------------------------------
// Problem constants
// ---------------------------------------------------------------------------
#define BB 4
#define SS 1024
#define DD 1024
#define HH 16
#define HDIM 64
#define FF 2048
#define HID 4096
#define TOK (BB*SS)          // 4096 tokens
#define QKVN 3072
#define WSCALE (1.0f/64.0f)  // weights pre-scaled by 64 (fp16 subnormal guard)

// ---------------------------------------------------------------------------
// Scratch (__device__ globals; no allocation allowed)
// ---------------------------------------------------------------------------
__device__ float g_o   [TOK*DD];
__device__ float g_h   [TOK*DD];
__device__ float g_feat[TOK*DD];
__device__ float g_feat2[TOK*DD];
__device__ float g_s   [TOK];
__device__ float g_sv  [TOK];
__device__ int   g_seg [TOK];
__device__ float g_maxseg[BB];
__device__ float g_bqkv[QKVN];

// fp16 split activations
__device__ __half g_qkvh[TOK*QKVN], g_qkvl[TOK*QKVN];
__device__ __half g_xh[TOK*DD],    g_xl[TOK*DD];
__device__ __half g_fh[TOK*DD],    g_fl[TOK*DD];     // feat / feat2 split
__device__ __half g_ath[TOK*DD],   g_atl[TOK*DD];    // attention out split
__device__ __half g_hh[TOK*DD],    g_hl[TOK*DD];     // h split
__device__ __half g_ffh[TOK*FF],   g_ffl[TOK*FF];    // ffn mid split
__device__ __half g_plh[TOK*DD],   g_pll[TOK*DD];    // pooled split
__device__ __half g_phh[TOK*HID],  g_phl[TOK*HID];   // projector mid split

// fp16 split weights [N,K] K-contiguous, pre-scaled x64
__device__ __half g_wqkvh[QKVN*DD], g_wqkvl[QKVN*DD];
__device__ __half g_woh[DD*DD],     g_wol[DD*DD];
__device__ __half g_w1h[FF*DD],     g_w1l[FF*DD];
__device__ __half g_w2h[DD*FF],     g_w2l[DD*FF];
__device__ __half g_p1h[HID*DD],    g_p1l[HID*DD];
__device__ __half g_p2h[HID*HID],   g_p2l[HID*HID];

// ---------------------------------------------------------------------------
// Helpers
// ---------------------------------------------------------------------------
__device__ __forceinline__ float gelu_f(float x) {
    return 0.5f * x * (1.0f + erff(x * 0.70710678118654752440f));
}

__device__ __forceinline__ void cp16(uint32_t dst, const void* src) {
    asm volatile("cp.async.cg.shared.global [%0], [%1], 16;\n"
                 :: "r"(dst), "l"(src));
}

__device__ __forceinline__ uint32_t smem_u32(const void* p) {
    uint32_t a;
    asm("{ .reg .u64 t; cvta.to.shared.u64 t, %1; cvt.u32.u64 %0, t; }"
        : "=r"(a) : "l"(p));
    return a;
}

// mma.sync m16n8k16 f16 with f32 accumulate
__device__ __forceinline__ void mma_f16(float* c,
                                        uint32_t a0, uint32_t a1,
                                        uint32_t a2, uint32_t a3,
                                        uint32_t b0, uint32_t b1) {
    asm volatile(
        "mma.sync.aligned.m16n8k16.row.col.f32.f16.f16.f32 "
        "{%0,%1,%2,%3}, {%4,%5,%6,%7}, {%8,%9}, {%0,%1,%2,%3};\n"
        : "+f"(c[0]), "+f"(c[1]), "+f"(c[2]), "+f"(c[3])
        : "r"(a0), "r"(a1), "r"(a2), "r"(a3), "r"(b0), "r"(b1));
}

// ldmatrix x4: four 8x8 b16 tiles, one per lane-octet address
__device__ __forceinline__ void ldsm_x4(uint32_t* r, uint32_t addr) {
    asm volatile(
        "ldmatrix.sync.aligned.m8n8.x4.shared.b16 {%0,%1,%2,%3}, [%4];\n"
        : "=r"(r[0]), "=r"(r[1]), "=r"(r[2]), "=r"(r[3]) : "r"(addr));
}

// ldmatrix x4 transposed (for col-major B fragments from row-major [k][n] smem)
__device__ __forceinline__ void ldsm_x4_t(uint32_t* r, uint32_t addr) {
    asm volatile(
        "ldmatrix.sync.aligned.m8n8.x4.trans.shared.b16 {%0,%1,%2,%3}, [%4];\n"
        : "=r"(r[0]), "=r"(r[1]), "=r"(r[2]), "=r"(r[3]) : "r"(addr));
}

__device__ __forceinline__ void hsplit(float v, __half& h, __half& l) {
    h = __float2half(v);
    l = __float2half(v - __half2float(h));
}

// ---------------------------------------------------------------------------
// fp16 2-split 3-combo GEMM (fp32-grade accuracy), ldmatrix fragment loads
// C[M,N] = act((A @ Bt^T) * WSCALE + bias[N]),  A = Ah+Al, Bt = Bh+Bl
// out_split=1: write split fp16 (Ch, Cl) instead of fp32 C.
// ---------------------------------------------------------------------------
#define HS 40
#define H_STAGE_HALVES 20480          // 4 arrays * 128*40
#define H_SMEM_BYTES  (2 * H_STAGE_HALVES * 2)

__global__ __launch_bounds__(256)
void hgemm_kernel(const __half* __restrict__ Ah, const __half* __restrict__ Al,
                  const __half* __restrict__ Bh, const __half* __restrict__ Bl,
                  const float* __restrict__ bias, float* __restrict__ C,
                  __half* __restrict__ Ch, __half* __restrict__ Cl,
                  int M, int N, int K, int act, int out_split)
{
    extern __shared__ __half hsm[];
    const int tid  = threadIdx.x;
    const int wid  = tid >> 5;
    const int lane = tid & 31;
    const int gr   = lane >> 2;
    const int gc   = lane & 3;
    const int lg   = lane >> 3;     // lane octet 0..3
    const int lr   = lane & 7;
    const int row0 = blockIdx.y * 128;
    const int col0 = blockIdx.x * 128;
    const int warp_m = (wid & 3) * 32;
    const int warp_n = (wid >> 2) * 64;
    const uint32_t sbase = smem_u32(hsm);

    const int a_rowoff = (lg & 1) * 8 + lr;
    const int a_koff   = (lg >> 1) * 8;
    const int b_rowoff = (lg >> 1) * 8 + lr;
    const int b_koff   = (lg & 1) * 8;

    float acc[2][8][4];
#pragma unroll
    for (int i = 0; i < 2; i++)
#pragma unroll
        for (int j = 0; j < 8; j++)
#pragma unroll
            for (int r = 0; r < 4; r++) acc[i][j][r] = 0.0f;

    const int nk = K >> 5;
    const int c0i = tid * 2, c1i = tid * 2 + 1;
    const int m0 = c0i >> 2, kc0 = (c0i & 3) * 8;
    const int m1 = c1i >> 2, kc1 = (c1i & 3) * 8;

#define H_LOAD_STAGE(st, k0)                                                     \
    do {                                                                         \
        uint32_t b = sbase + (uint32_t)(st) * H_STAGE_HALVES * 2u;               \
        cp16(b + (uint32_t)(m0 * HS + kc0) * 2u,                                 \
             Ah + (size_t)(row0 + m0) * K + (k0) + kc0);                         \
        cp16(b + (uint32_t)(m1 * HS + kc1) * 2u,                                 \
             Ah + (size_t)(row0 + m1) * K + (k0) + kc1);                         \
        cp16(b + (uint32_t)(5120 + m0 * HS + kc0) * 2u,                          \
             Al + (size_t)(row0 + m0) * K + (k0) + kc0);                         \
        cp16(b + (uint32_t)(5120 + m1 * HS + kc1) * 2u,                          \
             Al + (size_t)(row0 + m1) * K + (k0) + kc1);                         \
        cp16(b + (uint32_t)(10240 + m0 * HS + kc0) * 2u,                         \
             Bh + (size_t)(col0 + m0) * K + (k0) + kc0);                         \
        cp16(b + (uint32_t)(10240 + m1 * HS + kc1) * 2u,                         \
             Bh + (size_t)(col0 + m1) * K + (k0) + kc1);                         \
        cp16(b + (uint32_t)(15360 + m0 * HS + kc0) * 2u,                         \
             Bl + (size_t)(col0 + m0) * K + (k0) + kc0);                         \
        cp16(b + (uint32_t)(15360 + m1 * HS + kc1) * 2u,                         \
             Bl + (size_t)(col0 + m1) * K + (k0) + kc1);                         \
        asm volatile("cp.async.commit_group;\n");                                \
    } while (0)

    H_LOAD_STAGE(0, 0);

    for (int t = 0; t < nk; t++) {
        const int st = t & 1;
        if (t + 1 < nk) {
            H_LOAD_STAGE((t + 1) & 1, (t + 1) << 5);
            asm volatile("cp.async.wait_group 1;\n");
        } else {
            asm volatile("cp.async.wait_group 0;\n");
        }
        __syncthreads();

        const uint32_t sg = sbase + (uint32_t)st * H_STAGE_HALVES * 2u;

#pragma unroll
        for (int ks = 0; ks < 2; ks++) {
            const int kh = ks * 16;
            uint32_t ahf[2][4], alf[2][4];
#pragma unroll
            for (int mt = 0; mt < 2; mt++) {
                uint32_t aaddr = sg + (uint32_t)(
                    (warp_m + mt * 16 + a_rowoff) * HS + kh + a_koff) * 2u;
                ldsm_x4(ahf[mt], aaddr);
                ldsm_x4(alf[mt], aaddr + 5120u * 2u);
            }
#pragma unroll
            for (int p = 0; p < 4; p++) {
                uint32_t baddr = sg + (uint32_t)(
                    (warp_n + p * 16 + b_rowoff) * HS + kh + b_koff) * 2u
                    + 10240u * 2u;
                uint32_t bhf[4], blf[4];
                ldsm_x4(bhf, baddr);
                ldsm_x4(blf, baddr + 5120u * 2u);
#pragma unroll
                for (int q = 0; q < 2; q++) {
                    const int nt = p * 2 + q;
                    uint32_t bh0 = bhf[q * 2], bh1 = bhf[q * 2 + 1];
                    uint32_t bl0 = blf[q * 2], bl1 = blf[q * 2 + 1];
#pragma unroll
                    for (int mt = 0; mt < 2; mt++) {
                        float* c = acc[mt][nt];
                        mma_f16(c, ahf[mt][0], ahf[mt][1], ahf[mt][2], ahf[mt][3], bh0, bh1);
                        mma_f16(c, ahf[mt][0], ahf[mt][1], ahf[mt][2], ahf[mt][3], bl0, bl1);
                        mma_f16(c, alf[mt][0], alf[mt][1], alf[mt][2], alf[mt][3], bh0, bh1);
                    }
                }
            }
        }
        __syncthreads();
    }

#pragma unroll
    for (int mt = 0; mt < 2; mt++) {
        const int r0 = row0 + warp_m + mt * 16 + gr;
#pragma unroll
        for (int nt = 0; nt < 8; nt++) {
            const int cc = col0 + warp_n + nt * 8 + 2 * gc;
            float b0v = bias[cc], b1v = bias[cc + 1];
            float v0 = acc[mt][nt][0] * WSCALE + b0v;
            float v1 = acc[mt][nt][1] * WSCALE + b1v;
            float v2 = acc[mt][nt][2] * WSCALE + b0v;
            float v3 = acc[mt][nt][3] * WSCALE + b1v;
            if (act == 1) {
                v0 = gelu_f(v0); v1 = gelu_f(v1);
                v2 = gelu_f(v2); v3 = gelu_f(v3);
            }
            if (!out_split) {
                *(float2*)(C + (size_t)r0 * N + cc)       = make_float2(v0, v1);
                *(float2*)(C + (size_t)(r0 + 8) * N + cc) = make_float2(v2, v3);
            } else {
                __half h0, l0, h1, l1;
                hsplit(v0, h0, l0); hsplit(v1, h1, l1);
                *(__half2*)(Ch + (size_t)r0 * N + cc) = __halves2half2(h0, h1);
                *(__half2*)(Cl + (size_t)r0 * N + cc) = __halves2half2(l0, l1);
                hsplit(v2, h0, l0); hsplit(v3, h1, l1);
                *(__half2*)(Ch + (size_t)(r0 + 8) * N + cc) = __halves2half2(h0, h1);
                *(__half2*)(Cl + (size_t)(r0 + 8) * N + cc) = __halves2half2(l0, l1);
            }
        }
    }
}

// ---------------------------------------------------------------------------
// Tensor-core flash attention on fp16-split operands (3-combo, m16n8k16),
// ldmatrix fragment loads everywhere (trans for V).
// 64-q tile, 128 threads (4 warps x 16 queries). QKV input pre-split fp16.
// ---------------------------------------------------------------------------
#define HST 72
#define ATT_SMEM_BYTES (8 * 64 * HST * 2 + 64 * 4)

__global__ __launch_bounds__(128)
void attn_mma_kernel(const __half* __restrict__ qkvh, const __half* __restrict__ qkvl,
                     const float* __restrict__ masks,
                     int mode, __half* __restrict__ oh, __half* __restrict__ ol)
{
    extern __shared__ __half hs[];
    __half* Qh  = hs;
    __half* Ql  = Qh  + 64 * HST;
    __half* Kh  = Ql  + 64 * HST;
    __half* Kl  = Kh  + 64 * HST;
    __half* Vh  = Kl  + 64 * HST;
    __half* Vl  = Vh  + 64 * HST;
    __half* Psh = Vl  + 64 * HST;
    __half* Psl = Psh + 64 * HST;
    float*  mb  = (float*)(Psl + 64 * HST);

    const uint32_t sQh = smem_u32(Qh), sQl = smem_u32(Ql);
    const uint32_t sKh = smem_u32(Kh), sKl = smem_u32(Kl);
    const uint32_t sVh = smem_u32(Vh), sVl = smem_u32(Vl);
    const uint32_t sPh = smem_u32(Psh), sPl = smem_u32(Psl);

    const int tid  = threadIdx.x;
    const int wid  = tid >> 5;
    const int lane = tid & 31;
    const int gr   = lane >> 2;
    const int gc   = lane & 3;
    const int lg   = lane >> 3;
    const int lr   = lane & 7;
    const int q0   = blockIdx.x * 64;
    const int b    = blockIdx.y >> 4;
    const int h    = blockIdx.y & 15;
    const size_t qbase = (size_t)b * SS * QKVN + (size_t)h * HDIM;
    const size_t obase = (size_t)b * SS * DD + (size_t)h * HDIM;
    const int q0w = wid * 16;

    // ldmatrix lane-address components
    const int a_ro = (lg & 1) * 8 + lr;     // A-style (Q, P)
    const int a_ko = (lg >> 1) * 8;
    const int b_ro = (lg >> 1) * 8 + lr;    // B-style (K)
    const int b_ko = (lg & 1) * 8;
    const int v_ko = (lg & 1) * 8 + lr;     // trans (V): k-row within tile
    const int v_do = (lg >> 1) * 8;         // d offset

    for (int idx = tid; idx < 512; idx += 128) {
        int r = idx >> 3, c8 = (idx & 7) << 3;
        uint32_t soff = (uint32_t)(r * HST + c8) * 2u;
        cp16(sQh + soff, qkvh + qbase + (size_t)(q0 + r) * QKVN + c8);
        cp16(sQl + soff, qkvl + qbase + (size_t)(q0 + r) * QKVN + c8);
    }
    asm volatile("cp.async.commit_group;\n");

    float mrow[2] = {-1e30f, -1e30f};
    float lrow[2] = {0.0f, 0.0f};
    float Oacc[8][4];
#pragma unroll
    for (int i = 0; i < 8; i++)
#pragma unroll
        for (int j = 0; j < 4; j++) Oacc[i][j] = 0.0f;

    for (int t = 0; t < 16; t++) {
        const int k0 = t * 64;
        for (int idx = tid; idx < 512; idx += 128) {
            int r = idx >> 3, c8 = (idx & 7) << 3;
            uint32_t soff = (uint32_t)(r * HST + c8) * 2u;
            size_t kg = qbase + 1024 + (size_t)(k0 + r) * QKVN + c8;
            size_t vg = qbase + 2048 + (size_t)(k0 + r) * QKVN + c8;
            cp16(sKh + soff, qkvh + kg);
            cp16(sKl + soff, qkvl + kg);
            cp16(sVh + soff, qkvh + vg);
            cp16(sVl + soff, qkvl + vg);
        }
        asm volatile("cp.async.commit_group;\n");
        if (tid < 64) {
            float mv = masks[b * SS + k0 + tid];
            mb[tid] = (mode == 0) ? mv : (mv > 0.0f ? 0.0f : -1e9f);
        }
        asm volatile("cp.async.wait_group 0;\n");
        __syncthreads();

        // ---- scores: S(16q x 64k) = Q @ K^T (3-combo fp16, ldmatrix)
        float S[8][4];
#pragma unroll
        for (int i = 0; i < 8; i++)
#pragma unroll
            for (int j = 0; j < 4; j++) S[i][j] = 0.0f;

#pragma unroll
        for (int kh = 0; kh < 64; kh += 16) {
            uint32_t qhf[4], qlf[4];
            {
                uint32_t qaddr = (uint32_t)((q0w + a_ro) * HST + kh + a_ko) * 2u;
                ldsm_x4(qhf, sQh + qaddr);
                ldsm_x4(qlf, sQl + qaddr);
            }
#pragma unroll
            for (int p = 0; p < 4; p++) {
                uint32_t kaddr = (uint32_t)((p * 16 + b_ro) * HST + kh + b_ko) * 2u;
                uint32_t khf[4], klf[4];
                ldsm_x4(khf, sKh + kaddr);
                ldsm_x4(klf, sKl + kaddr);
#pragma unroll
                for (int q = 0; q < 2; q++) {
                    const int nt = p * 2 + q;
                    uint32_t kh0 = khf[q * 2], kh1 = khf[q * 2 + 1];
                    uint32_t kl0 = klf[q * 2], kl1 = klf[q * 2 + 1];
                    mma_f16(S[nt], qhf[0], qhf[1], qhf[2], qhf[3], kh0, kh1);
                    mma_f16(S[nt], qhf[0], qhf[1], qhf[2], qhf[3], kl0, kl1);
                    mma_f16(S[nt], qlf[0], qlf[1], qlf[2], qlf[3], kh0, kh1);
                }
            }
        }

        // ---- scale + bias + online softmax
        float rmax[2] = {-1e30f, -1e30f};
#pragma unroll
        for (int nt = 0; nt < 8; nt++) {
            float m0 = mb[nt * 8 + 2 * gc];
            float m1 = mb[nt * 8 + 2 * gc + 1];
            S[nt][0] = S[nt][0] * 0.125f + m0;
            S[nt][1] = S[nt][1] * 0.125f + m1;
            S[nt][2] = S[nt][2] * 0.125f + m0;
            S[nt][3] = S[nt][3] * 0.125f + m1;
            rmax[0] = fmaxf(rmax[0], fmaxf(S[nt][0], S[nt][1]));
            rmax[1] = fmaxf(rmax[1], fmaxf(S[nt][2], S[nt][3]));
        }
#pragma unroll
        for (int sh = 1; sh < 4; sh <<= 1) {
            rmax[0] = fmaxf(rmax[0], __shfl_xor_sync(0xffffffffu, rmax[0], sh));
            rmax[1] = fmaxf(rmax[1], __shfl_xor_sync(0xffffffffu, rmax[1], sh));
        }
        float mnew0 = fmaxf(mrow[0], rmax[0]);
        float mnew1 = fmaxf(mrow[1], rmax[1]);
        float scl0 = __expf(mrow[0] - mnew0);
        float scl1 = __expf(mrow[1] - mnew1);
        float rsum[2] = {0.0f, 0.0f};
#pragma unroll
        for (int nt = 0; nt < 8; nt++) {
            S[nt][0] = __expf(S[nt][0] - mnew0);
            S[nt][1] = __expf(S[nt][1] - mnew0);
            S[nt][2] = __expf(S[nt][2] - mnew1);
            S[nt][3] = __expf(S[nt][3] - mnew1);
            rsum[0] += S[nt][0] + S[nt][1];
            rsum[1] += S[nt][2] + S[nt][3];
        }
#pragma unroll
        for (int sh = 1; sh < 4; sh <<= 1) {
            rsum[0] += __shfl_xor_sync(0xffffffffu, rsum[0], sh);
            rsum[1] += __shfl_xor_sync(0xffffffffu, rsum[1], sh);
        }
        lrow[0] = lrow[0] * scl0 + rsum[0];
        lrow[1] = lrow[1] * scl1 + rsum[1];
        mrow[0] = mnew0; mrow[1] = mnew1;
#pragma unroll
        for (int dt = 0; dt < 8; dt++) {
            Oacc[dt][0] *= scl0; Oacc[dt][1] *= scl0;
            Oacc[dt][2] *= scl1; Oacc[dt][3] *= scl1;
        }

        // ---- stage P split to smem (per-warp private rows)
        __syncwarp();
#pragma unroll
        for (int nt = 0; nt < 8; nt++) {
            int c0 = nt * 8 + 2 * gc;
            __half h0, l0, h1, l1;
            hsplit(S[nt][0], h0, l0); hsplit(S[nt][1], h1, l1);
            *(__half2*)(Psh + (q0w + gr) * HST + c0) = __halves2half2(h0, h1);
            *(__half2*)(Psl + (q0w + gr) * HST + c0) = __halves2half2(l0, l1);
            hsplit(S[nt][2], h0, l0); hsplit(S[nt][3], h1, l1);
            *(__half2*)(Psh + (q0w + gr + 8) * HST + c0) = __halves2half2(h0, h1);
            *(__half2*)(Psl + (q0w + gr + 8) * HST + c0) = __halves2half2(l0, l1);
        }
        __syncwarp();

        // ---- O += P @ V (3-combo fp16; V via ldmatrix.trans)
#pragma unroll
        for (int kh = 0; kh < 64; kh += 16) {
            uint32_t phf[4], plf[4];
            {
                uint32_t paddr = (uint32_t)((q0w + a_ro) * HST + kh + a_ko) * 2u;
                ldsm_x4(phf, sPh + paddr);
                ldsm_x4(plf, sPl + paddr);
            }
#pragma unroll
            for (int p = 0; p < 4; p++) {
                const int d0 = p * 16;
                uint32_t vaddr = (uint32_t)((kh + v_ko) * HST + d0 + v_do) * 2u;
                uint32_t vhf[4], vlf[4];
                ldsm_x4_t(vhf, sVh + vaddr);
                ldsm_x4_t(vlf, sVl + vaddr);
#pragma unroll
                for (int q = 0; q < 2; q++) {
                    const int dt = p * 2 + q;
                    uint32_t vh0 = vhf[q * 2], vh1 = vhf[q * 2 + 1];
                    uint32_t vl0 = vlf[q * 2], vl1 = vlf[q * 2 + 1];
                    mma_f16(Oacc[dt], phf[0], phf[1], phf[2], phf[3], vh0, vh1);
                    mma_f16(Oacc[dt], phf[0], phf[1], phf[2], phf[3], vl0, vl1);
                    mma_f16(Oacc[dt], plf[0], plf[1], plf[2], plf[3], vh0, vh1);
                }
            }
        }
        __syncthreads();   // all warps done with K/V before next tile load
    }

    // ---- normalize + fp16-split store
    float inv0 = 1.0f / lrow[0];
    float inv1 = 1.0f / lrow[1];
    const int r0 = q0 + q0w + gr;
#pragma unroll
    for (int dt = 0; dt < 8; dt++) {
        int col = dt * 8 + 2 * gc;
        __half h0, l0, h1, l1;
        hsplit(Oacc[dt][0] * inv0, h0, l0);
        hsplit(Oacc[dt][1] * inv0, h1, l1);
        *(__half2*)(oh + obase + (size_t)r0 * DD + col) = __halves2half2(h0, h1);
        *(__half2*)(ol + obase + (size_t)r0 * DD + col) = __halves2half2(l0, l1);
        hsplit(Oacc[dt][2] * inv1, h0, l0);
        hsplit(Oacc[dt][3] * inv1, h1, l1);
        *(__half2*)(oh + obase + (size_t)(r0 + 8) * DD + col) = __halves2half2(h0, h1);
        *(__half2*)(ol + obase + (size_t)(r0 + 8) * DD + col) = __halves2half2(l0, l1);
    }
}

// ---------------------------------------------------------------------------
// Transpose + scale x64 + fp16 split: Wh/Wl[n,k] = split(64 * W[k,n])
// ---------------------------------------------------------------------------
__global__ __launch_bounds__(256)
void trans_split_h_kernel(const float* __restrict__ W,
                          __half* __restrict__ Wh, __half* __restrict__ Wl,
                          int Kd, int Nd)
{
    __shared__ float t[32][33];
    const int n0 = blockIdx.x * 32, k0 = blockIdx.y * 32;
    const int tx = threadIdx.x & 31, ty = threadIdx.x >> 5;
#pragma unroll
    for (int r = ty; r < 32; r += 8)
        t[r][tx] = W[(size_t)(k0 + r) * Nd + n0 + tx];
    __syncthreads();
#pragma unroll
    for (int r = ty; r < 32; r += 8) {
        float v = t[tx][r] * 64.0f;
        __half h, l;
        hsplit(v, h, l);
        Wh[(size_t)(n0 + r) * Kd + k0 + tx] = h;
        Wl[(size_t)(n0 + r) * Kd + k0 + tx] = l;
    }
}

// ---------------------------------------------------------------------------
// Elementwise fp16 split of an fp32 array
// ---------------------------------------------------------------------------
__global__ __launch_bounds__(256)
void split_h_kernel(const float* __restrict__ a, __half* __restrict__ ah,
                    __half* __restrict__ al, int n)
{
    int i = blockIdx.x * 256 + threadIdx.x;
    if (i < n) {
        __half h, l;
        hsplit(a[i], h, l);
        ah[i] = h; al[i] = l;
    }
}

// ---------------------------------------------------------------------------
// concat bias [bq|bk|bv] -> bqkv
// ---------------------------------------------------------------------------
__global__ __launch_bounds__(256)
void concat_bias_kernel(const float* __restrict__ bq, const float* __restrict__ bk,
                        const float* __restrict__ bv, float* __restrict__ bqkv)
{
    int i = blockIdx.x * 256 + threadIdx.x;
    if (i < QKVN) {
        float v = (i < 1024) ? bq[i] : ((i < 2048) ? bk[i - 1024] : bv[i - 2048]);
        bqkv[i] = v;
    }
}

// ---------------------------------------------------------------------------
// out = LayerNorm(a + b) * g + beta ; also writes fp16 split of out
// ---------------------------------------------------------------------------
__global__ __launch_bounds__(256)
void add_ln_kernel(const float* __restrict__ a, const float* __restrict__ b2,
                   const float* __restrict__ g, const float* __restrict__ beta,
                   float* __restrict__ out,
                   __half* __restrict__ outh, __half* __restrict__ outl)
{
    const int row = blockIdx.x;
    const size_t off = (size_t)row * DD;
    const int t = threadIdx.x;
    __shared__ float r1[256], r2[256];

    float vloc[4];
    float s = 0.0f, s2 = 0.0f;
#pragma unroll
    for (int i = 0; i < 4; i++) {
        int d = t + i * 256;
        float vv = a[off + d] + b2[off + d];
        vloc[i] = vv;
        s += vv; s2 += vv * vv;
    }
    r1[t] = s; r2[t] = s2;
    __syncthreads();
    for (int o2 = 128; o2 > 0; o2 >>= 1) {
        if (t < o2) { r1[t] += r1[t + o2]; r2[t] += r2[t + o2]; }
        __syncthreads();
    }
    float mean = r1[0] * (1.0f / DD);
    float var  = r2[0] * (1.0f / DD) - mean * mean;
    float inv  = rsqrtf(var + 1e-5f);
#pragma unroll
    for (int i = 0; i < 4; i++) {
        int d = t + i * 256;
        float vv = (vloc[i] - mean) * inv * g[d] + beta[d];
        out[off + d] = vv;
        __half h, l;
        hsplit(vv, h, l);
        outh[off + d] = h;
        outl[off + d] = l;
    }
}

// ---------------------------------------------------------------------------
// s = sigmoid(feat @ Ws + bs); one warp per token
// ---------------------------------------------------------------------------
__global__ __launch_bounds__(256)
void score_kernel(const float* __restrict__ feat, const float* __restrict__ Ws,
                  const float* __restrict__ bs, float* __restrict__ sbuf)
{
    int token = blockIdx.x * 8 + (threadIdx.x >> 5);
    int lane  = threadIdx.x & 31;
    const float* f = feat + (size_t)token * DD;
    float acc = 0.0f;
    for (int i = lane; i < DD; i += 32) acc += f[i] * Ws[i];
#pragma unroll
    for (int m = 16; m; m >>= 1) acc += __shfl_xor_sync(0xffffffffu, acc, m);
    if (lane == 0) sbuf[token] = 1.0f / (1.0f + expf(-(acc + bs[0])));
}

// ---------------------------------------------------------------------------
// Per-batch inclusive scan of sv, floor -> segment ids, max over valid
// ---------------------------------------------------------------------------
__global__ __launch_bounds__(1024)
void scan_kernel(const float* __restrict__ sbuf, const float* __restrict__ masks,
                 float* __restrict__ svbuf, int* __restrict__ segbuf,
                 float* __restrict__ maxseg)
{
    const int b = blockIdx.x;
    const int t = threadIdx.x;
    __shared__ float sc[SS];
    __shared__ float mr[SS];

    float valid = masks[b * SS + t];
    float sv = (valid > 0.0f) ? sbuf[b * SS + t] : 0.0f;
    svbuf[b * SS + t] = sv;
    sc[t] = sv;
    __syncthreads();
    for (int off = 1; off < SS; off <<= 1) {
        float vprev = (t >= off) ? sc[t - off] : 0.0f;
        __syncthreads();
        sc[t] += vprev;
        __syncthreads();
    }
    float c = floorf(sc[t]);
    int seg = (int)c;
    seg = seg < 0 ? 0 : (seg > SS - 1 ? SS - 1 : seg);
    segbuf[b * SS + t] = seg;

    mr[t] = (valid > 0.0f) ? c : -1.0f;
    __syncthreads();
    for (int off = 512; off > 0; off >>= 1) {
        if (t < off) mr[t] = fmaxf(mr[t], mr[t + off]);
        __syncthreads();
    }
    if (t == 0) maxseg[b] = mr[0];
}

// ---------------------------------------------------------------------------
// pooled[b,g,:] = sum_{s: seg[b,s]==g} x[b,s,:]*sv[b,s] -> split fp16 output
// ---------------------------------------------------------------------------
__global__ __launch_bounds__(256)
void pool_kernel(const float* __restrict__ x, const float* __restrict__ svbuf,
                 const int* __restrict__ segbuf,
                 __half* __restrict__ ph, __half* __restrict__ pl)
{
    const int g = blockIdx.x;
    const int b = blockIdx.y;
    const int* seg = segbuf + b * SS;

    int lo = 0, hi = SS;
    while (lo < hi) { int mid = (lo + hi) >> 1; if (seg[mid] < g) lo = mid + 1; else hi = mid; }
    int beg = lo;
    lo = beg; hi = SS;
    while (lo < hi) { int mid = (lo + hi) >> 1; if (seg[mid] < g + 1) lo = mid + 1; else hi = mid; }
    int end = lo;

    const int t = threadIdx.x;
    float acc[4] = {0.0f, 0.0f, 0.0f, 0.0f};
    for (int s = beg; s < end; s++) {
        float w = svbuf[b * SS + s];
        const float* xr = x + ((size_t)b * SS + s) * DD;
#pragma unroll
        for (int i = 0; i < 4; i++) acc[i] += xr[t + i * 256] * w;
    }
    size_t rbase = ((size_t)b * SS + g) * DD;
#pragma unroll
    for (int i = 0; i < 4; i++) {
        __half h, l;
        hsplit(acc[i], h, l);
        ph[rbase + t + i * 256] = h;
        pl[rbase + t + i * 256] = l;
    }
}

// ---------------------------------------------------------------------------
// new_mask[b,s] = (s <= max_seg[b]) ? 1 : 0
// ---------------------------------------------------------------------------
__global__ __launch_bounds__(1024)
void mask_kernel(const float* __restrict__ maxseg, float* __restrict__ outmask)
{
    const int b = blockIdx.x;
    const int t = threadIdx.x;
    outmask[b * SS + t] = ((float)t <= maxseg[b]) ? 1.0f : 0.0f;
}

// ---------------------------------------------------------------------------
// Host side
// ---------------------------------------------------------------------------
static void* sym_addr(const void* sym) {
    void* p = nullptr;
    cudaGetSymbolAddress(&p, sym);
    return p;
}

static void launch_hgemm(const __half* Ah, const __half* Al,
                         const __half* Bh, const __half* Bl,
                         const float* bias, float* C,
                         __half* Ch, __half* Cl,
                         int M, int N, int K, int act, int out_split) {
    dim3 grid(N / 128, M / 128);
    hgemm_kernel<<<grid, 256, H_SMEM_BYTES>>>(Ah, Al, Bh, Bl, bias, C,
                                              Ch, Cl, M, N, K, act, out_split);
}

extern "C" void kernel_launch(void* const* d_in, const int* in_sizes, int n_in,
                              void* d_out, int out_size)
{
    (void)in_sizes; (void)n_in;
    const float* x     = (const float*)d_in[0];
    const float* masks = (const float*)d_in[1];
    const float* Wq  = (const float*)d_in[2];
    const float* bq  = (const float*)d_in[3];
    const float* Wk  = (const float*)d_in[4];
    const float* bk  = (const float*)d_in[5];
    const float* Wv  = (const float*)d_in[6];
    const float* bv  = (const float*)d_in[7];
    const float* Wo  = (const float*)d_in[8];
    const float* bo  = (const float*)d_in[9];
    const float* g1  = (const float*)d_in[10];
    const float* be1 = (const float*)d_in[11];
    const float* g2  = (const float*)d_in[12];
    const float* be2 = (const float*)d_in[13];
    const float* W1  = (const float*)d_in[14];
    const float* bf1 = (const float*)d_in[15];
    const float* W2  = (const float*)d_in[16];
    const float* bf2 = (const float*)d_in[17];
    const float* Ws  = (const float*)d_in[18];
    const float* bs  = (const float*)d_in[19];
    const float* P1  = (const float*)d_in[20];
    const float* bp1 = (const float*)d_in[21];
    const float* P2  = (const float*)d_in[22];
    const float* bp2 = (const float*)d_in[23];

    float* out = (float*)d_out;
    (void)out_size;

    cudaFuncSetAttribute(attn_mma_kernel,
                         cudaFuncAttributeMaxDynamicSharedMemorySize,
                         ATT_SMEM_BYTES);
    cudaFuncSetAttribute(hgemm_kernel,
                         cudaFuncAttributeMaxDynamicSharedMemorySize,
                         H_SMEM_BYTES);

    float* ob    = (float*)sym_addr(g_o);
    float* hb    = (float*)sym_addr(g_h);
    float* featb = (float*)sym_addr(g_feat);
    float* feat2b= (float*)sym_addr(g_feat2);
    float* sb    = (float*)sym_addr(g_s);
    float* svb   = (float*)sym_addr(g_sv);
    int*   segb  = (int*)sym_addr(g_seg);
    float* msb   = (float*)sym_addr(g_maxseg);
    float* bqkvb = (float*)sym_addr(g_bqkv);

    __half* qkvh = (__half*)sym_addr(g_qkvh);
    __half* qkvl = (__half*)sym_addr(g_qkvl);
    __half* xh  = (__half*)sym_addr(g_xh);
    __half* xl  = (__half*)sym_addr(g_xl);
    __half* fh  = (__half*)sym_addr(g_fh);
    __half* fl  = (__half*)sym_addr(g_fl);
    __half* ath = (__half*)sym_addr(g_ath);
    __half* atl = (__half*)sym_addr(g_atl);
    __half* hh  = (__half*)sym_addr(g_hh);
    __half* hl  = (__half*)sym_addr(g_hl);
    __half* ffh = (__half*)sym_addr(g_ffh);
    __half* ffl = (__half*)sym_addr(g_ffl);
    __half* plh = (__half*)sym_addr(g_plh);
    __half* pll = (__half*)sym_addr(g_pll);
    __half* phh = (__half*)sym_addr(g_phh);
    __half* phl = (__half*)sym_addr(g_phl);

    __half* wqkvh = (__half*)sym_addr(g_wqkvh);
    __half* wqkvl = (__half*)sym_addr(g_wqkvl);
    __half* woh = (__half*)sym_addr(g_woh);
    __half* wol = (__half*)sym_addr(g_wol);
    __half* w1h = (__half*)sym_addr(g_w1h);
    __half* w1l = (__half*)sym_addr(g_w1l);
    __half* w2h = (__half*)sym_addr(g_w2h);
    __half* w2l = (__half*)sym_addr(g_w2l);
    __half* p1h = (__half*)sym_addr(g_p1h);
    __half* p1l = (__half*)sym_addr(g_p1l);
    __half* p2h = (__half*)sym_addr(g_p2h);
    __half* p2l = (__half*)sym_addr(g_p2l);

    // ---- weight prep: transpose + x64 + fp16 split ----
    trans_split_h_kernel<<<dim3(DD / 32, DD / 32), 256>>>(Wq, wqkvh, wqkvl, DD, DD);
    trans_split_h_kernel<<<dim3(DD / 32, DD / 32), 256>>>(Wk, wqkvh + DD * DD,
                                                          wqkvl + DD * DD, DD, DD);
    trans_split_h_kernel<<<dim3(DD / 32, DD / 32), 256>>>(Wv, wqkvh + 2 * DD * DD,
                                                          wqkvl + 2 * DD * DD, DD, DD);
    trans_split_h_kernel<<<dim3(DD / 32, DD / 32), 256>>>(Wo, woh, wol, DD, DD);
    trans_split_h_kernel<<<dim3(FF / 32, DD / 32), 256>>>(W1, w1h, w1l, DD, FF);
    trans_split_h_kernel<<<dim3(DD / 32, FF / 32), 256>>>(W2, w2h, w2l, FF, DD);
    trans_split_h_kernel<<<dim3(HID / 32, DD / 32), 256>>>(P1, p1h, p1l, DD, HID);
    trans_split_h_kernel<<<dim3(HID / 32, HID / 32), 256>>>(P2, p2h, p2l, HID, HID);
    concat_bias_kernel<<<(QKVN + 255) / 256, 256>>>(bq, bk, bv, bqkvb);
    split_h_kernel<<<(TOK * DD + 255) / 256, 256>>>(x, xh, xl, TOK * DD);

    // ---- encoder layer, applied twice (fp16 2-split exact path) ----
    const __half* inh = xh;
    const __half* inl = xl;
    const float* enc_in = x;
    float* enc_out = featb;
    for (int pass = 0; pass < 2; pass++) {
        int mode = pass;
        launch_hgemm(inh, inl, wqkvh, wqkvl, bqkvb, nullptr, qkvh, qkvl,
                     TOK, QKVN, DD, 0, 1);                  // split fp16 out
        attn_mma_kernel<<<dim3(SS / 64, BB * HH), 128, ATT_SMEM_BYTES>>>(
            qkvh, qkvl, masks, mode, ath, atl);
        launch_hgemm(ath, atl, woh, wol, bo, ob, nullptr, nullptr,
                     TOK, DD, DD, 0, 0);
        add_ln_kernel<<<TOK, 256>>>(enc_in, ob, g1, be1, hb, hh, hl);
        launch_hgemm(hh, hl, w1h, w1l, bf1, nullptr, ffh, ffl,
                     TOK, FF, DD, 1, 1);                    // GELU, split out
        launch_hgemm(ffh, ffl, w2h, w2l, bf2, ob, nullptr, nullptr,
                     TOK, DD, FF, 0, 0);
        add_ln_kernel<<<TOK, 256>>>(hb, ob, g2, be2, enc_out, fh, fl);
        enc_in = featb;
        enc_out = feat2b;
        inh = fh; inl = fl;
    }

    // ---- importance scores, cumsum segmentation ----
    score_kernel<<<TOK / 8, 256>>>(feat2b, Ws, bs, sb);
    scan_kernel<<<BB, 1024>>>(sb, masks, svb, segb, msb);

    // ---- weighted segment-sum pooling of original x (split fp16 output) ----
    pool_kernel<<<dim3(SS, BB), 256>>>(x, svb, segb, plh, pll);

    // ---- projector on fp16-split tensor cores ----
    launch_hgemm(plh, pll, p1h, p1l, bp1, nullptr, phh, phl,
                 TOK, HID, DD, 1, 1);                       // GELU, split out
    launch_hgemm(phh, phl, p2h, p2l, bp2, out, nullptr, nullptr,
                 TOK, HID, HID, 0, 0);                      // fp32 out

    // ---- new_mask appended after the [B,S,HID] output ----
    mask_kernel<<<BB, 1024>>>(msb, out + (size_t)TOK * HID);
}